// round 5
// baseline (speedup 1.0000x reference)
#include <cuda_runtime.h>
#include <cstdint>

// ----- problem constants -----
#define BNODES 8192
#define EE     262144
#define DD     512
#define NRBF   128
#define NLAYER 4

// ----- distance->ef lookup table -----
#define NP    4096
#define DMAXF 10.4f
#define HSTEP (DMAXF / (float)(NP - 1))
#define INVH  ((float)(NP - 1) / DMAXF)

// ----- device scratch -----
__device__ float g_x[BNODES * DD];
__device__ float g_dist[EE];
__device__ float g_th[NP * DD];
__device__ float g_tab[NP * DD];
__device__ float g_agg[BNODES * DD];
__device__ float g_t[BNODES * DD];

typedef unsigned long long ull;

__device__ __forceinline__ float silu_f(float v) { return v / (1.0f + __expf(-v)); }

__device__ __forceinline__ void cp16(void* dst, const void* src) {
    uint32_t d = (uint32_t)__cvta_generic_to_shared(dst);
    asm volatile("cp.async.cg.shared.global [%0], [%1], 16;" :: "r"(d), "l"(src));
}
__device__ __forceinline__ void cp_commit() { asm volatile("cp.async.commit_group;"); }
__device__ __forceinline__ void cp_wait0() { asm volatile("cp.async.wait_group 0;" ::: "memory"); }

// ---- packed f32x2 helpers ----
__device__ __forceinline__ ull dup_f32x2(float a) {
    ull r;
    asm("mov.b64 %0, {%1, %1};" : "=l"(r) : "f"(a));
    return r;
}
__device__ __forceinline__ void fma_f32x2(ull& d, ull a, ull b) {
    asm("fma.rn.f32x2 %0, %1, %2, %3;" : "=l"(d) : "l"(a), "l"(b), "l"(d));
}
__device__ __forceinline__ float2 unpack_f32x2(ull v) {
    float lo, hi;
    asm("mov.b64 {%0, %1}, %2;" : "=f"(lo), "=f"(hi) : "l"(v));
    return make_float2(lo, hi);
}

// ============================================================
__global__ void k_gather(const int* __restrict__ tok, const float* __restrict__ emb) {
    int i = blockIdx.x;
    int t = tok[i];
    ((float4*)(g_x + (size_t)i * DD))[threadIdx.x] =
        ((const float4*)(emb + (size_t)t * DD))[threadIdx.x];
}

__global__ void k_dist(const int* __restrict__ ei, const float* __restrict__ coords) {
    int e = blockIdx.x * 256 + threadIdx.x;
    int r = ei[e], c = ei[EE + e];
    float dx = coords[r * 3 + 0] - coords[c * 3 + 0];
    float dy = coords[r * 3 + 1] - coords[c * 3 + 1];
    float dz = coords[r * 3 + 2] - coords[c * 3 + 2];
    g_dist[e] = sqrtf(dx * dx + dy * dy + dz * dz);
}

// ============================================================
// GEMM microkernel: 128x128 tile, BK=16, 256 thr, 8x8 microtile,
// accumulators packed as f32x2 (acc2[i][p] = cols 2p,2p+1).
// ============================================================
__device__ __forceinline__ void mma_tile2(const float (*As)[132], const float (*Bs)[128],
                                          int tx, int ty, ull acc2[8][4]) {
#pragma unroll
    for (int k = 0; k < 16; k++) {
        float4 a0 = *(const float4*)&As[k][ty * 8];
        float4 a1 = *(const float4*)&As[k][ty * 8 + 4];
        // B pairs: float4 loads give consecutive regs -> valid f32x2 pairs
        ull b[4];
        b[0] = ((const ull*)&Bs[k][tx * 8])[0];
        b[1] = ((const ull*)&Bs[k][tx * 8])[1];
        b[2] = ((const ull*)&Bs[k][tx * 8])[2];
        b[3] = ((const ull*)&Bs[k][tx * 8])[3];
        float av[8] = {a0.x, a0.y, a0.z, a0.w, a1.x, a1.y, a1.z, a1.w};
#pragma unroll
        for (int i = 0; i < 8; i++) {
            ull aa = dup_f32x2(av[i]);
#pragma unroll
            for (int p = 0; p < 4; p++) fma_f32x2(acc2[i][p], aa, b[p]);
        }
    }
}

__device__ __forceinline__ void ldA_regs(const float* __restrict__ A, int m0, int kc,
                                         int tid, float4* v) {
#pragma unroll
    for (int i = 0; i < 2; i++) {
        int q = i * 256 + tid;
        int r = q >> 2, c4 = q & 3;
        v[i] = *(const float4*)&A[(size_t)(m0 + r) * DD + kc * 16 + c4 * 4];
    }
}
__device__ __forceinline__ void stsA(float (*As)[132], int tid, const float4* v) {
#pragma unroll
    for (int i = 0; i < 2; i++) {
        int q = i * 256 + tid;
        int r = q >> 2, c4 = q & 3;
        As[c4 * 4 + 0][r] = v[i].x;
        As[c4 * 4 + 1][r] = v[i].y;
        As[c4 * 4 + 2][r] = v[i].z;
        As[c4 * 4 + 3][r] = v[i].w;
    }
}
__device__ __forceinline__ void cpB(float (*Bs)[128], const float* __restrict__ W,
                                    int n0, int kc, int tid) {
#pragma unroll
    for (int i = 0; i < 2; i++) {
        int q = i * 256 + tid;
        int r = q >> 5, c4 = q & 31;
        cp16(&Bs[r][c4 * 4], &W[(size_t)(kc * 16 + r) * DD + n0 + c4 * 4]);
    }
}

// unpack 8x4 packed acc into 8 floats for one row
__device__ __forceinline__ void row_unpack(const ull* accr, float* o) {
#pragma unroll
    for (int p = 0; p < 4; p++) {
        float2 u = unpack_f32x2(accr[p]);
        o[2 * p] = u.x;
        o[2 * p + 1] = u.y;
    }
}

// ============================================================
// Table pass 1: g_th = silu(rbf(grid) @ W1 + b1)   grid (NP/128, 4)
// ============================================================
__global__ void __launch_bounds__(256, 2) k_tab1(const float* __restrict__ W,
                                                 const float* __restrict__ b) {
    __shared__ float As[16][132];
    __shared__ float Bs[2][16][128];
    int tid = threadIdx.x, tx = tid & 15, ty = tid >> 4;
    int m0 = blockIdx.x * 128, n0 = blockIdx.y * 128;
    const float step = 6.0f / 127.0f;

    cpB(Bs[0], W, n0, 0, tid);
    cp_commit();

    ull acc2[8][4] = {};
#pragma unroll 1
    for (int kc = 0; kc < NRBF / 16; kc++) {
        int buf = kc & 1;
#pragma unroll
        for (int i = 0; i < 8; i++) {
            int idx = i * 256 + tid;
            int m = idx & 127, k = idx >> 7;
            float d = (float)(m0 + m) * HSTEP;
            float c = (float)(kc * 16 + k) * step;
            float dd = d - c;
            As[k][m] = __expf(-10.0f * dd * dd);
        }
        if (kc + 1 < NRBF / 16) { cpB(Bs[buf ^ 1], W, n0, kc + 1, tid); cp_commit(); }
        cp_wait0();
        __syncthreads();
        mma_tile2(As, Bs[buf], tx, ty, acc2);
        __syncthreads();
    }

    float bb[8];
#pragma unroll
    for (int j = 0; j < 8; j++) bb[j] = b[n0 + tx * 8 + j];
#pragma unroll
    for (int i = 0; i < 8; i++) {
        float o[8];
        row_unpack(acc2[i], o);
#pragma unroll
        for (int j = 0; j < 8; j++) o[j] = silu_f(o[j] + bb[j]);
        float* dst = g_th + (size_t)(m0 + ty * 8 + i) * DD + n0 + tx * 8;
        *(float4*)dst = make_float4(o[0], o[1], o[2], o[3]);
        *(float4*)(dst + 4) = make_float4(o[4], o[5], o[6], o[7]);
    }
}

// ============================================================
// Generic GEMM. EPI 0: g_t = silu(g_agg@W+b); 1: g_x += g_t@W+b; 2: g_tab = g_th@W+b
// ============================================================
template <int EPI>
__global__ void __launch_bounds__(256, 2) k_gemm(const float* __restrict__ W,
                                                 const float* __restrict__ b) {
    __shared__ float As[2][16][132];
    __shared__ float Bs[2][16][128];
    int tid = threadIdx.x, tx = tid & 15, ty = tid >> 4;
    int m0 = blockIdx.x * 128, n0 = blockIdx.y * 128;
    const float* A = (EPI == 0) ? g_agg : (EPI == 1) ? g_t : g_th;

    float4 av[2];
    ldA_regs(A, m0, 0, tid, av);
    cpB(Bs[0], W, n0, 0, tid);
    cp_commit();
    stsA(As[0], tid, av);
    cp_wait0();
    __syncthreads();

    ull acc2[8][4] = {};
    const int NCH = DD / 16;
#pragma unroll 1
    for (int kc = 0; kc < NCH; kc++) {
        int buf = kc & 1;
        if (kc + 1 < NCH) {
            cpB(Bs[buf ^ 1], W, n0, kc + 1, tid);
            cp_commit();
            ldA_regs(A, m0, kc + 1, tid, av);
        }
        mma_tile2(As[buf], Bs[buf], tx, ty, acc2);
        if (kc + 1 < NCH) stsA(As[buf ^ 1], tid, av);
        cp_wait0();
        __syncthreads();
    }

    float bb[8];
#pragma unroll
    for (int j = 0; j < 8; j++) bb[j] = b[n0 + tx * 8 + j];
#pragma unroll
    for (int i = 0; i < 8; i++) {
        size_t off = (size_t)(m0 + ty * 8 + i) * DD + n0 + tx * 8;
        float o[8];
        row_unpack(acc2[i], o);
        if (EPI == 0) {
#pragma unroll
            for (int j = 0; j < 8; j++) o[j] = silu_f(o[j] + bb[j]);
            *(float4*)(g_t + off) = make_float4(o[0], o[1], o[2], o[3]);
            *(float4*)(g_t + off + 4) = make_float4(o[4], o[5], o[6], o[7]);
        } else if (EPI == 1) {
            float4 x0 = *(float4*)(g_x + off);
            float4 x1 = *(float4*)(g_x + off + 4);
            x0.x += o[0] + bb[0];  x0.y += o[1] + bb[1];
            x0.z += o[2] + bb[2];  x0.w += o[3] + bb[3];
            x1.x += o[4] + bb[4];  x1.y += o[5] + bb[5];
            x1.z += o[6] + bb[6];  x1.w += o[7] + bb[7];
            *(float4*)(g_x + off) = x0;
            *(float4*)(g_x + off + 4) = x1;
        } else {
#pragma unroll
            for (int j = 0; j < 8; j++) o[j] = o[j] + bb[j];
            *(float4*)(g_tab + off) = make_float4(o[0], o[1], o[2], o[3]);
            *(float4*)(g_tab + off + 4) = make_float4(o[4], o[5], o[6], o[7]);
        }
    }
}

// ============================================================
// Edge pass: agg[node] = sum_{32 edges} lerp(tab, d_e) * x[col_e]
// 128 threads, float4 per thread.
// ============================================================
__global__ void __launch_bounds__(128) k_agg(const int* __restrict__ col) {
    __shared__ int   scol[32];
    __shared__ int   sidx[32];
    __shared__ float sw[32];
    int node = blockIdx.x, tid = threadIdx.x;
    if (tid < 32) {
        int e = node * 32 + tid;
        scol[tid] = col[e];
        float f = g_dist[e] * INVH;
        int i = (int)f;
        if (i > NP - 2) i = NP - 2;
        sidx[tid] = i;
        sw[tid] = f - (float)i;
    }
    __syncthreads();

    int dim = tid * 4;
    float4 a = make_float4(0.f, 0.f, 0.f, 0.f);
#pragma unroll 8
    for (int e = 0; e < 32; e++) {
        size_t tbase = (size_t)sidx[e] * DD + dim;
        float4 t0 = *(const float4*)&g_tab[tbase];
        float4 t1 = *(const float4*)&g_tab[tbase + DD];
        float4 xv = *(const float4*)&g_x[(size_t)scol[e] * DD + dim];
        float w = sw[e];
        a.x = fmaf(fmaf(w, t1.x - t0.x, t0.x), xv.x, a.x);
        a.y = fmaf(fmaf(w, t1.y - t0.y, t0.y), xv.y, a.y);
        a.z = fmaf(fmaf(w, t1.z - t0.z, t0.z), xv.z, a.z);
        a.w = fmaf(fmaf(w, t1.w - t0.w, t0.w), xv.w, a.w);
    }
    *(float4*)&g_agg[(size_t)node * DD + dim] = a;
}

// ============================================================
__global__ void k_copy_out(float* __restrict__ out) {
    size_t i = (size_t)blockIdx.x * 256 + threadIdx.x;
    ((float4*)out)[i] = ((const float4*)g_x)[i];
}
__global__ void k_mask(float* __restrict__ out, const int* __restrict__ tok, int n) {
    int i = blockIdx.x * 256 + threadIdx.x;
    if (i < n) out[i] = (i < BNODES && tok[i] == 0) ? 1.0f : 0.0f;
}

// ============================================================
extern "C" void kernel_launch(void* const* d_in, const int* in_sizes, int n_in,
                              void* d_out, int out_size) {
    const int*   tok    = (const int*)d_in[0];
    const float* coords = (const float*)d_in[1];
    const int*   ei     = (const int*)d_in[2];
    const float* emb    = (const float*)d_in[3];
    const float* ew1    = (const float*)d_in[4];
    const float* eb1    = (const float*)d_in[5];
    const float* ew2    = (const float*)d_in[6];
    const float* eb2    = (const float*)d_in[7];
    const float* nw1    = (const float*)d_in[8];
    const float* nb1    = (const float*)d_in[9];
    const float* nw2    = (const float*)d_in[10];
    const float* nb2    = (const float*)d_in[11];

    k_gather<<<BNODES, 128>>>(tok, emb);
    k_dist<<<EE / 256, 256>>>(ei, coords);

    const int* col = ei + EE;
    for (int l = 0; l < NLAYER; l++) {
        k_tab1<<<dim3(NP / 128, 4), 256>>>(ew1 + (size_t)l * NRBF * DD, eb1 + l * DD);
        k_gemm<2><<<dim3(NP / 128, 4), 256>>>(ew2 + (size_t)l * DD * DD, eb2 + l * DD);
        k_agg<<<BNODES, 128>>>(col);
        k_gemm<0><<<dim3(BNODES / 128, 4), 256>>>(nw1 + (size_t)l * DD * DD, nb1 + l * DD);
        k_gemm<1><<<dim3(BNODES / 128, 4), 256>>>(nw2 + (size_t)l * DD * DD, nb2 + l * DD);
    }

    k_copy_out<<<(BNODES * DD) / (256 * 4), 256>>>((float*)d_out);
    int extra = out_size - BNODES * DD;
    if (extra > 0)
        k_mask<<<(extra + 255) / 256, 256>>>((float*)d_out + BNODES * DD, tok, extra);
}

// round 7
// speedup vs baseline: 1.1970x; 1.1970x over previous
#include <cuda_runtime.h>
#include <cstdint>

// ----- problem constants -----
#define BNODES 8192
#define EE     262144
#define DD     512
#define NRBF   128
#define NLAYER 4

// ----- distance->ef lookup table -----
#define NP    2048
#define DMAXF 10.4f
#define HSTEP (DMAXF / (float)(NP - 1))
#define INVH  ((float)(NP - 1) / DMAXF)

// ----- device scratch -----
__device__ float g_x[BNODES * DD];
__device__ float g_dist[EE];
__device__ float g_th[NLAYER * NP * DD];    // hidden tables, all layers
__device__ float g_tab[NLAYER * NP * DD];   // ef tables, all layers
__device__ float g_agg[BNODES * DD];
__device__ float g_t[BNODES * DD];

__device__ __forceinline__ float silu_f(float v) { return v / (1.0f + __expf(-v)); }

__device__ __forceinline__ void cp16(void* dst, const void* src) {
    uint32_t d = (uint32_t)__cvta_generic_to_shared(dst);
    asm volatile("cp.async.cg.shared.global [%0], [%1], 16;" :: "r"(d), "l"(src));
}
__device__ __forceinline__ void cp_commit() { asm volatile("cp.async.commit_group;"); }
__device__ __forceinline__ void cp_wait0() { asm volatile("cp.async.wait_group 0;" ::: "memory"); }

// ============================================================
__global__ void k_gather(const int* __restrict__ tok, const float* __restrict__ emb) {
    int i = blockIdx.x;
    int t = tok[i];
    ((float4*)(g_x + (size_t)i * DD))[threadIdx.x] =
        ((const float4*)(emb + (size_t)t * DD))[threadIdx.x];
}

__global__ void k_dist(const int* __restrict__ ei, const float* __restrict__ coords) {
    int e = blockIdx.x * 256 + threadIdx.x;
    int r = ei[e], c = ei[EE + e];
    float dx = coords[r * 3 + 0] - coords[c * 3 + 0];
    float dy = coords[r * 3 + 1] - coords[c * 3 + 1];
    float dz = coords[r * 3 + 2] - coords[c * 3 + 2];
    g_dist[e] = sqrtf(dx * dx + dy * dy + dz * dz);
}

// ============================================================
// scalar GEMM microkernel: 128x128 tile, BK=16, 256 thr, 8x8 microtile
// ============================================================
__device__ __forceinline__ void mma_tile(const float (*As)[132], const float (*Bs)[128],
                                         int tx, int ty, float acc[8][8]) {
#pragma unroll
    for (int k = 0; k < 16; k++) {
        float4 a0 = *(const float4*)&As[k][ty * 8];
        float4 a1 = *(const float4*)&As[k][ty * 8 + 4];
        float4 b0 = *(const float4*)&Bs[k][tx * 8];
        float4 b1 = *(const float4*)&Bs[k][tx * 8 + 4];
        float av[8] = {a0.x, a0.y, a0.z, a0.w, a1.x, a1.y, a1.z, a1.w};
        float bv[8] = {b0.x, b0.y, b0.z, b0.w, b1.x, b1.y, b1.z, b1.w};
#pragma unroll
        for (int i = 0; i < 8; i++)
#pragma unroll
            for (int j = 0; j < 8; j++)
                acc[i][j] = fmaf(av[i], bv[j], acc[i][j]);
    }
}

__device__ __forceinline__ void ldA_regs(const float* __restrict__ A, int m0, int kc,
                                         int tid, float4* v) {
#pragma unroll
    for (int i = 0; i < 2; i++) {
        int q = i * 256 + tid;
        int r = q >> 2, c4 = q & 3;
        v[i] = *(const float4*)&A[(size_t)(m0 + r) * DD + kc * 16 + c4 * 4];
    }
}
__device__ __forceinline__ void stsA(float (*As)[132], int tid, const float4* v) {
#pragma unroll
    for (int i = 0; i < 2; i++) {
        int q = i * 256 + tid;
        int r = q >> 2, c4 = q & 3;
        As[c4 * 4 + 0][r] = v[i].x;
        As[c4 * 4 + 1][r] = v[i].y;
        As[c4 * 4 + 2][r] = v[i].z;
        As[c4 * 4 + 3][r] = v[i].w;
    }
}
__device__ __forceinline__ void cpB(float (*Bs)[128], const float* __restrict__ W,
                                    int n0, int kc, int tid) {
#pragma unroll
    for (int i = 0; i < 2; i++) {
        int q = i * 256 + tid;
        int r = q >> 5, c4 = q & 31;
        cp16(&Bs[r][c4 * 4], &W[(size_t)(kc * 16 + r) * DD + n0 + c4 * 4]);
    }
}

// ============================================================
// Table pass 1, ALL LAYERS batched: g_th[z] = silu(rbf(grid) @ W1[z] + b1[z])
// grid (NP/128, 4, NLAYER)
// ============================================================
__global__ void __launch_bounds__(256, 2) k_tab1(const float* __restrict__ Wb,
                                                 const float* __restrict__ bb_) {
    __shared__ float As[16][132];
    __shared__ float Bs[2][16][128];
    int tid = threadIdx.x, tx = tid & 15, ty = tid >> 4;
    int m0 = blockIdx.x * 128, n0 = blockIdx.y * 128, l = blockIdx.z;
    const float* W = Wb + (size_t)l * NRBF * DD;
    const float* b = bb_ + (size_t)l * DD;
    const float step = 6.0f / 127.0f;

    cpB(Bs[0], W, n0, 0, tid);
    cp_commit();

    float acc[8][8] = {};
#pragma unroll 1
    for (int kc = 0; kc < NRBF / 16; kc++) {
        int buf = kc & 1;
#pragma unroll
        for (int i = 0; i < 8; i++) {
            int idx = i * 256 + tid;
            int m = idx & 127, k = idx >> 7;
            float d = (float)(m0 + m) * HSTEP;
            float c = (float)(kc * 16 + k) * step;
            float dd = d - c;
            As[k][m] = __expf(-10.0f * dd * dd);
        }
        if (kc + 1 < NRBF / 16) { cpB(Bs[buf ^ 1], W, n0, kc + 1, tid); cp_commit(); }
        cp_wait0();
        __syncthreads();
        mma_tile(As, Bs[buf], tx, ty, acc);
        __syncthreads();
    }

    float bb[8];
#pragma unroll
    for (int j = 0; j < 8; j++) bb[j] = b[n0 + tx * 8 + j];
    float* out = g_th + (size_t)l * NP * DD;
#pragma unroll
    for (int i = 0; i < 8; i++) {
        float o[8];
#pragma unroll
        for (int j = 0; j < 8; j++) o[j] = silu_f(acc[i][j] + bb[j]);
        float* dst = out + (size_t)(m0 + ty * 8 + i) * DD + n0 + tx * 8;
        *(float4*)dst = make_float4(o[0], o[1], o[2], o[3]);
        *(float4*)(dst + 4) = make_float4(o[4], o[5], o[6], o[7]);
    }
}

// ============================================================
// Generic GEMM.
// EPI 0: g_t = silu(g_agg@W+b)           grid (BNODES/128, 4)
// EPI 1: g_x += g_t@W+b                  grid (BNODES/128, 4)
// EPI 2: g_tab[z] = g_th[z]@W[z]+b[z]    grid (NP/128, 4, NLAYER)
// ============================================================
template <int EPI>
__global__ void __launch_bounds__(256, 2) k_gemm(const float* __restrict__ Wb,
                                                 const float* __restrict__ bb_) {
    __shared__ float As[2][16][132];
    __shared__ float Bs[2][16][128];
    int tid = threadIdx.x, tx = tid & 15, ty = tid >> 4;
    int m0 = blockIdx.x * 128, n0 = blockIdx.y * 128, l = blockIdx.z;
    const float* A = (EPI == 0) ? g_agg : (EPI == 1) ? g_t : (g_th + (size_t)l * NP * DD);
    const float* W = (EPI == 2) ? Wb + (size_t)l * DD * DD : Wb;
    const float* b = (EPI == 2) ? bb_ + (size_t)l * DD : bb_;

    float4 av[2];
    ldA_regs(A, m0, 0, tid, av);
    cpB(Bs[0], W, n0, 0, tid);
    cp_commit();
    stsA(As[0], tid, av);
    cp_wait0();
    __syncthreads();

    float acc[8][8] = {};
    const int NCH = DD / 16;
#pragma unroll 1
    for (int kc = 0; kc < NCH; kc++) {
        int buf = kc & 1;
        if (kc + 1 < NCH) {
            cpB(Bs[buf ^ 1], W, n0, kc + 1, tid);
            cp_commit();
            ldA_regs(A, m0, kc + 1, tid, av);
        }
        mma_tile(As[buf], Bs[buf], tx, ty, acc);
        if (kc + 1 < NCH) stsA(As[buf ^ 1], tid, av);
        cp_wait0();
        __syncthreads();
    }

    float bb[8];
#pragma unroll
    for (int j = 0; j < 8; j++) bb[j] = b[n0 + tx * 8 + j];
#pragma unroll
    for (int i = 0; i < 8; i++) {
        size_t off = (size_t)(m0 + ty * 8 + i) * DD + n0 + tx * 8;
        if (EPI == 0) {
            float o[8];
#pragma unroll
            for (int j = 0; j < 8; j++) o[j] = silu_f(acc[i][j] + bb[j]);
            *(float4*)(g_t + off) = make_float4(o[0], o[1], o[2], o[3]);
            *(float4*)(g_t + off + 4) = make_float4(o[4], o[5], o[6], o[7]);
        } else if (EPI == 1) {
            float4 x0 = *(float4*)(g_x + off);
            float4 x1 = *(float4*)(g_x + off + 4);
            x0.x += acc[i][0] + bb[0];  x0.y += acc[i][1] + bb[1];
            x0.z += acc[i][2] + bb[2];  x0.w += acc[i][3] + bb[3];
            x1.x += acc[i][4] + bb[4];  x1.y += acc[i][5] + bb[5];
            x1.z += acc[i][6] + bb[6];  x1.w += acc[i][7] + bb[7];
            *(float4*)(g_x + off) = x0;
            *(float4*)(g_x + off + 4) = x1;
        } else {
            float o[8];
#pragma unroll
            for (int j = 0; j < 8; j++) o[j] = acc[i][j] + bb[j];
            float* out = g_tab + (size_t)l * NP * DD + off;
            *(float4*)out = make_float4(o[0], o[1], o[2], o[3]);
            *(float4*)(out + 4) = make_float4(o[4], o[5], o[6], o[7]);
        }
    }
}

// ============================================================
// Edge pass: agg[node] = sum_{32 edges} lerp(tab_l, d_e) * x[col_e]
// Layer index passed as int; table pointer computed DEVICE-side.
// ============================================================
__global__ void __launch_bounds__(128) k_agg(const int* __restrict__ col, int l) {
    __shared__ int   scol[32];
    __shared__ int   sidx[32];
    __shared__ float sw[32];
    const float* tab = g_tab + (size_t)l * NP * DD;
    int node = blockIdx.x, tid = threadIdx.x;
    if (tid < 32) {
        int e = node * 32 + tid;
        scol[tid] = col[e];
        float f = g_dist[e] * INVH;
        int i = (int)f;
        if (i > NP - 2) i = NP - 2;
        sidx[tid] = i;
        sw[tid] = f - (float)i;
    }
    __syncthreads();

    int dim = tid * 4;
    float4 a = make_float4(0.f, 0.f, 0.f, 0.f);
#pragma unroll 8
    for (int e = 0; e < 32; e++) {
        size_t tbase = (size_t)sidx[e] * DD + dim;
        float4 t0 = *(const float4*)&tab[tbase];
        float4 t1 = *(const float4*)&tab[tbase + DD];
        float4 xv = *(const float4*)&g_x[(size_t)scol[e] * DD + dim];
        float w = sw[e];
        a.x = fmaf(fmaf(w, t1.x - t0.x, t0.x), xv.x, a.x);
        a.y = fmaf(fmaf(w, t1.y - t0.y, t0.y), xv.y, a.y);
        a.z = fmaf(fmaf(w, t1.z - t0.z, t0.z), xv.z, a.z);
        a.w = fmaf(fmaf(w, t1.w - t0.w, t0.w), xv.w, a.w);
    }
    *(float4*)&g_agg[(size_t)node * DD + dim] = a;
}

// ============================================================
__global__ void k_copy_out(float* __restrict__ out) {
    size_t i = (size_t)blockIdx.x * 256 + threadIdx.x;
    ((float4*)out)[i] = ((const float4*)g_x)[i];
}
__global__ void k_mask(float* __restrict__ out, const int* __restrict__ tok, int n) {
    int i = blockIdx.x * 256 + threadIdx.x;
    if (i < n) out[i] = (i < BNODES && tok[i] == 0) ? 1.0f : 0.0f;
}

// ============================================================
extern "C" void kernel_launch(void* const* d_in, const int* in_sizes, int n_in,
                              void* d_out, int out_size) {
    const int*   tok    = (const int*)d_in[0];
    const float* coords = (const float*)d_in[1];
    const int*   ei     = (const int*)d_in[2];
    const float* emb    = (const float*)d_in[3];
    const float* ew1    = (const float*)d_in[4];
    const float* eb1    = (const float*)d_in[5];
    const float* ew2    = (const float*)d_in[6];
    const float* eb2    = (const float*)d_in[7];
    const float* nw1    = (const float*)d_in[8];
    const float* nb1    = (const float*)d_in[9];
    const float* nw2    = (const float*)d_in[10];
    const float* nb2    = (const float*)d_in[11];

    k_gather<<<BNODES, 128>>>(tok, emb);
    k_dist<<<EE / 256, 256>>>(ei, coords);

    // all layers' tables upfront (batched -> full-chip fill)
    k_tab1<<<dim3(NP / 128, 4, NLAYER), 256>>>(ew1, eb1);
    k_gemm<2><<<dim3(NP / 128, 4, NLAYER), 256>>>(ew2, eb2);

    const int* col = ei + EE;
    for (int l = 0; l < NLAYER; l++) {
        k_agg<<<BNODES, 128>>>(col, l);
        k_gemm<0><<<dim3(BNODES / 128, 4), 256>>>(nw1 + (size_t)l * DD * DD, nb1 + l * DD);
        k_gemm<1><<<dim3(BNODES / 128, 4), 256>>>(nw2 + (size_t)l * DD * DD, nb2 + l * DD);
    }

    k_copy_out<<<(BNODES * DD) / (256 * 4), 256>>>((float*)d_out);
    int extra = out_size - BNODES * DD;
    if (extra > 0)
        k_mask<<<(extra + 255) / 256, 256>>>((float*)d_out + BNODES * DD, tok, extra);
}

// round 8
// speedup vs baseline: 1.3463x; 1.1247x over previous
#include <cuda_runtime.h>
#include <cuda_bf16.h>
#include <cstdint>

// ----- problem constants -----
#define BNODES 8192
#define EE     262144
#define DD     512
#define NRBF   128
#define NLAYER 4

// ----- distance->ef lookup table -----
#define NP    2048
#define DMAXF 10.4f
#define HSTEP (DMAXF / (float)(NP - 1))
#define INVH  ((float)(NP - 1) / DMAXF)

// ----- device scratch -----
__device__ float g_x[BNODES * DD];
__device__ float g_dist[EE];
__device__ float g_th[NLAYER * NP * DD];
__device__ float g_tab[NLAYER * NP * DD];
__device__ float g_agg[BNODES * DD];
__device__ float g_t[BNODES * DD];

__device__ __forceinline__ float silu_f(float v) { return v / (1.0f + __expf(-v)); }

__device__ __forceinline__ void cp16(void* dst, const void* src) {
    uint32_t d = (uint32_t)__cvta_generic_to_shared(dst);
    asm volatile("cp.async.cg.shared.global [%0], [%1], 16;" :: "r"(d), "l"(src));
}
__device__ __forceinline__ void cp_commit() { asm volatile("cp.async.commit_group;"); }
__device__ __forceinline__ void cp_wait0() { asm volatile("cp.async.wait_group 0;" ::: "memory"); }

// bf16 hi/lo split of one float: hi = rn(x), lo = rn(x - hi)  (x-hi exact)
__device__ __forceinline__ void split_bf(float x, __nv_bfloat16& h, __nv_bfloat16& l) {
    h = __float2bfloat16_rn(x);
    l = __float2bfloat16_rn(x - __bfloat162float(h));
}
__device__ __forceinline__ uint32_t pack_bf(__nv_bfloat16 a, __nv_bfloat16 b) {
    __nv_bfloat162 p;
    p.x = a; p.y = b;
    return *(uint32_t*)&p;
}

__device__ __forceinline__ void mma_bf16(float* c, uint32_t a0, uint32_t a1, uint32_t a2,
                                         uint32_t a3, uint32_t b0, uint32_t b1) {
    asm volatile(
        "mma.sync.aligned.m16n8k16.row.col.f32.bf16.bf16.f32 "
        "{%0,%1,%2,%3}, {%4,%5,%6,%7}, {%8,%9}, {%0,%1,%2,%3};"
        : "+f"(c[0]), "+f"(c[1]), "+f"(c[2]), "+f"(c[3])
        : "r"(a0), "r"(a1), "r"(a2), "r"(a3), "r"(b0), "r"(b1));
}

// ============================================================
__global__ void k_gather(const int* __restrict__ tok, const float* __restrict__ emb) {
    int i = blockIdx.x;
    int t = tok[i];
    ((float4*)(g_x + (size_t)i * DD))[threadIdx.x] =
        ((const float4*)(emb + (size_t)t * DD))[threadIdx.x];
}

__global__ void k_dist(const int* __restrict__ ei, const float* __restrict__ coords) {
    int e = blockIdx.x * 256 + threadIdx.x;
    int r = ei[e], c = ei[EE + e];
    float dx = coords[r * 3 + 0] - coords[c * 3 + 0];
    float dy = coords[r * 3 + 1] - coords[c * 3 + 1];
    float dz = coords[r * 3 + 2] - coords[c * 3 + 2];
    g_dist[e] = sqrtf(dx * dx + dy * dy + dz * dz);
}

// ============================================================
// scalar FFMA GEMM bits (kept for k_tab1 only: K=128, rbf on the fly)
// ============================================================
__device__ __forceinline__ void mma_tile(const float (*As)[132], const float (*Bs)[128],
                                         int tx, int ty, float acc[8][8]) {
#pragma unroll
    for (int k = 0; k < 16; k++) {
        float4 a0 = *(const float4*)&As[k][ty * 8];
        float4 a1 = *(const float4*)&As[k][ty * 8 + 4];
        float4 b0 = *(const float4*)&Bs[k][tx * 8];
        float4 b1 = *(const float4*)&Bs[k][tx * 8 + 4];
        float av[8] = {a0.x, a0.y, a0.z, a0.w, a1.x, a1.y, a1.z, a1.w};
        float bv[8] = {b0.x, b0.y, b0.z, b0.w, b1.x, b1.y, b1.z, b1.w};
#pragma unroll
        for (int i = 0; i < 8; i++)
#pragma unroll
            for (int j = 0; j < 8; j++)
                acc[i][j] = fmaf(av[i], bv[j], acc[i][j]);
    }
}
__device__ __forceinline__ void cpB(float (*Bs)[128], const float* __restrict__ W,
                                    int n0, int kc, int tid) {
#pragma unroll
    for (int i = 0; i < 2; i++) {
        int q = i * 256 + tid;
        int r = q >> 5, c4 = q & 31;
        cp16(&Bs[r][c4 * 4], &W[(size_t)(kc * 16 + r) * DD + n0 + c4 * 4]);
    }
}

// ============================================================
// Table pass 1, all layers: g_th[z] = silu(rbf(grid) @ W1[z] + b1[z])
// grid (NP/128, 4, NLAYER)
// ============================================================
__global__ void __launch_bounds__(256, 2) k_tab1(const float* __restrict__ Wb,
                                                 const float* __restrict__ bb_) {
    __shared__ float As[16][132];
    __shared__ float Bs[2][16][128];
    int tid = threadIdx.x, tx = tid & 15, ty = tid >> 4;
    int m0 = blockIdx.x * 128, n0 = blockIdx.y * 128, l = blockIdx.z;
    const float* W = Wb + (size_t)l * NRBF * DD;
    const float* b = bb_ + (size_t)l * DD;
    const float step = 6.0f / 127.0f;

    cpB(Bs[0], W, n0, 0, tid);
    cp_commit();

    float acc[8][8] = {};
#pragma unroll 1
    for (int kc = 0; kc < NRBF / 16; kc++) {
        int buf = kc & 1;
#pragma unroll
        for (int i = 0; i < 8; i++) {
            int idx = i * 256 + tid;
            int m = idx & 127, k = idx >> 7;
            float d = (float)(m0 + m) * HSTEP;
            float c = (float)(kc * 16 + k) * step;
            float dd = d - c;
            As[k][m] = __expf(-10.0f * dd * dd);
        }
        if (kc + 1 < NRBF / 16) { cpB(Bs[buf ^ 1], W, n0, kc + 1, tid); cp_commit(); }
        cp_wait0();
        __syncthreads();
        mma_tile(As, Bs[buf], tx, ty, acc);
        __syncthreads();
    }

    float bb[8];
#pragma unroll
    for (int j = 0; j < 8; j++) bb[j] = b[n0 + tx * 8 + j];
    float* out = g_th + (size_t)l * NP * DD;
#pragma unroll
    for (int i = 0; i < 8; i++) {
        float o[8];
#pragma unroll
        for (int j = 0; j < 8; j++) o[j] = silu_f(acc[i][j] + bb[j]);
        float* dst = out + (size_t)(m0 + ty * 8 + i) * DD + n0 + tx * 8;
        *(float4*)dst = make_float4(o[0], o[1], o[2], o[3]);
        *(float4*)(dst + 4) = make_float4(o[4], o[5], o[6], o[7]);
    }
}

// ============================================================
// HMMA bf16x3 GEMM: C[Mx512] = A[Mx512] @ W[512x512] + b, epilogue.
// Tile 128x128, 256 thr = 8 warps (2 m x 4 n), warp tile 64x32, BK=32.
// A,B split fp32 -> bf16 hi/lo during staging; 3-term mma.
// smem (dynamic, per buffer): Ah,Al [128][17]u32, Bh,Bl [128][17]u32 (B stored [n][k]).
// EPI 0: g_t = silu(.); 1: g_x += .; 2: g_tab[z] = .
// ============================================================
#define PRW 17                        // padded row width in u32 (16 data + 1)
#define PLANE (128 * PRW)             // u32 per plane
#define BUFSZ (4 * PLANE)             // u32 per stage buffer
#define SMEM_GEMM (2 * BUFSZ * 4 + 512)

template <int EPI>
__global__ void __launch_bounds__(256) k_gemm(const float* __restrict__ Wb,
                                              const float* __restrict__ bb_) {
    extern __shared__ uint32_t smem_u[];
    float* sbias = (float*)(smem_u + 2 * BUFSZ);
    int tid = threadIdx.x, lane = tid & 31, wid = tid >> 5;
    int m0 = blockIdx.x * 128, n0 = blockIdx.y * 128, l = blockIdx.z;
    const float* A = (EPI == 0) ? g_agg : (EPI == 1) ? g_t : (g_th + (size_t)l * NP * DD);
    const float* W = (EPI == 2) ? Wb + (size_t)l * DD * DD : Wb;
    const float* b = (EPI == 2) ? bb_ + (size_t)l * DD : bb_;

    if (tid < 128) sbias[tid] = b[n0 + tid];

    // staging thread mapping
    const int ar = tid >> 1, akh = (tid & 1) * 16;      // A: row, k-half
    const int bkr = tid >> 3, bnq = (tid & 7) * 16;     // B: k-row, n-quarter

    // fragment indices
    const int g = lane >> 2, tig = lane & 3;
    const int wm = (wid >> 2) * 64, wn = (wid & 3) * 32;

    float4 va[4], vb[4];
    // ---- prologue: load + stage chunk 0 ----
#pragma unroll
    for (int i = 0; i < 4; i++)
        va[i] = *(const float4*)&A[(size_t)(m0 + ar) * DD + akh + i * 4];
#pragma unroll
    for (int i = 0; i < 4; i++)
        vb[i] = *(const float4*)&W[(size_t)bkr * DD + n0 + bnq + i * 4];

    auto stage = [&](int buf) {
        uint32_t* AH = smem_u + buf * BUFSZ;
        uint32_t* AL = AH + PLANE;
        __nv_bfloat16* BH = (__nv_bfloat16*)(AH + 2 * PLANE);
        __nv_bfloat16* BL = (__nv_bfloat16*)(AH + 3 * PLANE);
#pragma unroll
        for (int i = 0; i < 4; i++) {
            float f[4] = {va[i].x, va[i].y, va[i].z, va[i].w};
            __nv_bfloat16 h[4], lo[4];
#pragma unroll
            for (int j = 0; j < 4; j++) split_bf(f[j], h[j], lo[j]);
            int base = ar * PRW + (akh >> 1) + i * 2;
            AH[base] = pack_bf(h[0], h[1]);
            AH[base + 1] = pack_bf(h[2], h[3]);
            AL[base] = pack_bf(lo[0], lo[1]);
            AL[base + 1] = pack_bf(lo[2], lo[3]);
        }
#pragma unroll
        for (int i = 0; i < 4; i++) {
            float f[4] = {vb[i].x, vb[i].y, vb[i].z, vb[i].w};
#pragma unroll
            for (int j = 0; j < 4; j++) {
                __nv_bfloat16 h, lo;
                split_bf(f[j], h, lo);
                int n = bnq + i * 4 + j;
                BH[n * (2 * PRW) + bkr] = h;   // row stride = 34 bf16
                BL[n * (2 * PRW) + bkr] = lo;
            }
        }
    };
    stage(0);
    __syncthreads();

    float acc[4][4][4] = {};
    const int NCH = DD / 32;
#pragma unroll 1
    for (int kc = 0; kc < NCH; kc++) {
        int buf = kc & 1;
        if (kc + 1 < NCH) {
#pragma unroll
            for (int i = 0; i < 4; i++)
                va[i] = *(const float4*)&A[(size_t)(m0 + ar) * DD + (kc + 1) * 32 + akh + i * 4];
#pragma unroll
            for (int i = 0; i < 4; i++)
                vb[i] = *(const float4*)&W[(size_t)((kc + 1) * 32 + bkr) * DD + n0 + bnq + i * 4];
        }
        const uint32_t* AH = smem_u + buf * BUFSZ;
        const uint32_t* AL = AH + PLANE;
        const uint32_t* BH = AH + 2 * PLANE;
        const uint32_t* BL = AH + 3 * PLANE;
#pragma unroll
        for (int ks = 0; ks < 2; ks++) {
            int kb = ks * 8 + tig;
            uint32_t aH[4][4], aL[4][4], bH[4][2], bL[4][2];
#pragma unroll
            for (int mt = 0; mt < 4; mt++) {
                int r0 = (wm + mt * 16 + g) * PRW;
                int r8 = r0 + 8 * PRW;
                aH[mt][0] = AH[r0 + kb];     aH[mt][1] = AH[r8 + kb];
                aH[mt][2] = AH[r0 + kb + 4]; aH[mt][3] = AH[r8 + kb + 4];
                aL[mt][0] = AL[r0 + kb];     aL[mt][1] = AL[r8 + kb];
                aL[mt][2] = AL[r0 + kb + 4]; aL[mt][3] = AL[r8 + kb + 4];
            }
#pragma unroll
            for (int nt = 0; nt < 4; nt++) {
                int rn = (wn + nt * 8 + g) * PRW;
                bH[nt][0] = BH[rn + kb]; bH[nt][1] = BH[rn + kb + 4];
                bL[nt][0] = BL[rn + kb]; bL[nt][1] = BL[rn + kb + 4];
            }
#pragma unroll
            for (int mt = 0; mt < 4; mt++)
#pragma unroll
                for (int nt = 0; nt < 4; nt++) {
                    mma_bf16(acc[mt][nt], aH[mt][0], aH[mt][1], aH[mt][2], aH[mt][3],
                             bH[nt][0], bH[nt][1]);
                    mma_bf16(acc[mt][nt], aH[mt][0], aH[mt][1], aH[mt][2], aH[mt][3],
                             bL[nt][0], bL[nt][1]);
                    mma_bf16(acc[mt][nt], aL[mt][0], aL[mt][1], aL[mt][2], aL[mt][3],
                             bH[nt][0], bH[nt][1]);
                }
        }
        if (kc + 1 < NCH) stage(buf ^ 1);
        __syncthreads();
    }

    // ---- epilogue ----
#pragma unroll
    for (int mt = 0; mt < 4; mt++) {
#pragma unroll
        for (int nt = 0; nt < 4; nt++) {
            int row = m0 + wm + mt * 16 + g;
            int cl = wn + nt * 8 + tig * 2;
            float b0 = sbias[cl], b1 = sbias[cl + 1];
            float* c = acc[mt][nt];
#pragma unroll
            for (int half = 0; half < 2; half++) {
                int r = row + half * 8;
                float v0 = c[half * 2 + 0] + b0, v1 = c[half * 2 + 1] + b1;
                size_t off = (size_t)r * DD + n0 + cl;
                if (EPI == 0) {
                    *(float2*)(g_t + off) = make_float2(silu_f(v0), silu_f(v1));
                } else if (EPI == 1) {
                    float2 x = *(float2*)(g_x + off);
                    x.x += v0; x.y += v1;
                    *(float2*)(g_x + off) = x;
                } else {
                    *(float2*)(g_tab + (size_t)l * NP * DD + off) = make_float2(v0, v1);
                }
            }
        }
    }
}

// ============================================================
// Edge pass: agg[node] = sum_{32 edges} lerp(tab_l, d_e) * x[col_e]
// ============================================================
__global__ void __launch_bounds__(128) k_agg(const int* __restrict__ col, int l) {
    __shared__ int   scol[32];
    __shared__ int   sidx[32];
    __shared__ float sw[32];
    const float* tab = g_tab + (size_t)l * NP * DD;
    int node = blockIdx.x, tid = threadIdx.x;
    if (tid < 32) {
        int e = node * 32 + tid;
        scol[tid] = col[e];
        float f = g_dist[e] * INVH;
        int i = (int)f;
        if (i > NP - 2) i = NP - 2;
        sidx[tid] = i;
        sw[tid] = f - (float)i;
    }
    __syncthreads();

    int dim = tid * 4;
    float4 a = make_float4(0.f, 0.f, 0.f, 0.f);
#pragma unroll 8
    for (int e = 0; e < 32; e++) {
        size_t tbase = (size_t)sidx[e] * DD + dim;
        float4 t0 = *(const float4*)&tab[tbase];
        float4 t1 = *(const float4*)&tab[tbase + DD];
        float4 xv = *(const float4*)&g_x[(size_t)scol[e] * DD + dim];
        float w = sw[e];
        a.x = fmaf(fmaf(w, t1.x - t0.x, t0.x), xv.x, a.x);
        a.y = fmaf(fmaf(w, t1.y - t0.y, t0.y), xv.y, a.y);
        a.z = fmaf(fmaf(w, t1.z - t0.z, t0.z), xv.z, a.z);
        a.w = fmaf(fmaf(w, t1.w - t0.w, t0.w), xv.w, a.w);
    }
    *(float4*)&g_agg[(size_t)node * DD + dim] = a;
}

// ============================================================
__global__ void k_copy_out(float* __restrict__ out) {
    size_t i = (size_t)blockIdx.x * 256 + threadIdx.x;
    ((float4*)out)[i] = ((const float4*)g_x)[i];
}
__global__ void k_mask(float* __restrict__ out, const int* __restrict__ tok, int n) {
    int i = blockIdx.x * 256 + threadIdx.x;
    if (i < n) out[i] = (i < BNODES && tok[i] == 0) ? 1.0f : 0.0f;
}

// ============================================================
extern "C" void kernel_launch(void* const* d_in, const int* in_sizes, int n_in,
                              void* d_out, int out_size) {
    const int*   tok    = (const int*)d_in[0];
    const float* coords = (const float*)d_in[1];
    const int*   ei     = (const int*)d_in[2];
    const float* emb    = (const float*)d_in[3];
    const float* ew1    = (const float*)d_in[4];
    const float* eb1    = (const float*)d_in[5];
    const float* ew2    = (const float*)d_in[6];
    const float* eb2    = (const float*)d_in[7];
    const float* nw1    = (const float*)d_in[8];
    const float* nb1    = (const float*)d_in[9];
    const float* nw2    = (const float*)d_in[10];
    const float* nb2    = (const float*)d_in[11];

    cudaFuncSetAttribute(k_gemm<0>, cudaFuncAttributeMaxDynamicSharedMemorySize, SMEM_GEMM);
    cudaFuncSetAttribute(k_gemm<1>, cudaFuncAttributeMaxDynamicSharedMemorySize, SMEM_GEMM);
    cudaFuncSetAttribute(k_gemm<2>, cudaFuncAttributeMaxDynamicSharedMemorySize, SMEM_GEMM);

    k_gather<<<BNODES, 128>>>(tok, emb);
    k_dist<<<EE / 256, 256>>>(ei, coords);

    k_tab1<<<dim3(NP / 128, 4, NLAYER), 256>>>(ew1, eb1);
    k_gemm<2><<<dim3(NP / 128, 4, NLAYER), 256, SMEM_GEMM>>>(ew2, eb2);

    const int* col = ei + EE;
    for (int l = 0; l < NLAYER; l++) {
        k_agg<<<BNODES, 128>>>(col, l);
        k_gemm<0><<<dim3(BNODES / 128, 4), 256, SMEM_GEMM>>>(nw1 + (size_t)l * DD * DD,
                                                             nb1 + l * DD);
        k_gemm<1><<<dim3(BNODES / 128, 4), 256, SMEM_GEMM>>>(nw2 + (size_t)l * DD * DD,
                                                             nb2 + l * DD);
    }

    k_copy_out<<<(BNODES * DD) / (256 * 4), 256>>>((float*)d_out);
    int extra = out_size - BNODES * DD;
    if (extra > 0)
        k_mask<<<(extra + 255) / 256, 256>>>((float*)d_out + BNODES * DD, tok, extra);
}

// round 9
// speedup vs baseline: 1.3579x; 1.0086x over previous
#include <cuda_runtime.h>
#include <cuda_bf16.h>
#include <cstdint>

// ----- problem constants -----
#define BNODES 8192
#define EE     262144
#define DD     512
#define NRBF   128
#define NLAYER 4

// ----- distance->ef lookup table -----
#define NP    2048
#define DMAXF 10.4f
#define HSTEP (DMAXF / (float)(NP - 1))
#define INVH  ((float)(NP - 1) / DMAXF)

// ----- device scratch -----
__device__ float g_x[BNODES * DD];
__device__ float g_dist[EE];
__device__ float g_th[NLAYER * NP * DD];
__device__ float g_tab[NLAYER * NP * DD];
__device__ float g_agg[BNODES * DD];
__device__ float g_t[BNODES * DD];

__device__ __forceinline__ float silu_f(float v) { return v / (1.0f + __expf(-v)); }

__device__ __forceinline__ void cp16(void* dst, const void* src) {
    uint32_t d = (uint32_t)__cvta_generic_to_shared(dst);
    asm volatile("cp.async.cg.shared.global [%0], [%1], 16;" :: "r"(d), "l"(src));
}
__device__ __forceinline__ void cp_commit() { asm volatile("cp.async.commit_group;"); }
__device__ __forceinline__ void cp_wait0() { asm volatile("cp.async.wait_group 0;" ::: "memory"); }

__device__ __forceinline__ void split_bf(float x, __nv_bfloat16& h, __nv_bfloat16& l) {
    h = __float2bfloat16_rn(x);
    l = __float2bfloat16_rn(x - __bfloat162float(h));
}
__device__ __forceinline__ uint32_t pack_bf(__nv_bfloat16 a, __nv_bfloat16 b) {
    __nv_bfloat162 p;
    p.x = a; p.y = b;
    return *(uint32_t*)&p;
}
// split 8 floats into hi/lo packed uint4
__device__ __forceinline__ void split8(const float* f, uint4& H, uint4& L) {
    __nv_bfloat16 h[8], l[8];
#pragma unroll
    for (int j = 0; j < 8; j++) split_bf(f[j], h[j], l[j]);
    H = make_uint4(pack_bf(h[0], h[1]), pack_bf(h[2], h[3]),
                   pack_bf(h[4], h[5]), pack_bf(h[6], h[7]));
    L = make_uint4(pack_bf(l[0], l[1]), pack_bf(l[2], l[3]),
                   pack_bf(l[4], l[5]), pack_bf(l[6], l[7]));
}

__device__ __forceinline__ void mma_bf16(float* c, const uint32_t* a, uint32_t b0, uint32_t b1) {
    asm volatile(
        "mma.sync.aligned.m16n8k16.row.col.f32.bf16.bf16.f32 "
        "{%0,%1,%2,%3}, {%4,%5,%6,%7}, {%8,%9}, {%0,%1,%2,%3};"
        : "+f"(c[0]), "+f"(c[1]), "+f"(c[2]), "+f"(c[3])
        : "r"(a[0]), "r"(a[1]), "r"(a[2]), "r"(a[3]), "r"(b0), "r"(b1));
}
__device__ __forceinline__ void ldsm4(uint32_t* r, uint32_t addr) {
    asm volatile("ldmatrix.sync.aligned.m8n8.x4.shared.b16 {%0,%1,%2,%3}, [%4];"
                 : "=r"(r[0]), "=r"(r[1]), "=r"(r[2]), "=r"(r[3]) : "r"(addr));
}

// ============================================================
__global__ void k_gather(const int* __restrict__ tok, const float* __restrict__ emb) {
    int i = blockIdx.x;
    int t = tok[i];
    ((float4*)(g_x + (size_t)i * DD))[threadIdx.x] =
        ((const float4*)(emb + (size_t)t * DD))[threadIdx.x];
}

__global__ void k_dist(const int* __restrict__ ei, const float* __restrict__ coords) {
    int e = blockIdx.x * 256 + threadIdx.x;
    int r = ei[e], c = ei[EE + e];
    float dx = coords[r * 3 + 0] - coords[c * 3 + 0];
    float dy = coords[r * 3 + 1] - coords[c * 3 + 1];
    float dz = coords[r * 3 + 2] - coords[c * 3 + 2];
    g_dist[e] = sqrtf(dx * dx + dy * dy + dz * dz);
}

// ============================================================
// scalar FFMA GEMM bits (k_tab1 only)
// ============================================================
__device__ __forceinline__ void mma_tile(const float (*As)[132], const float (*Bs)[128],
                                         int tx, int ty, float acc[8][8]) {
#pragma unroll
    for (int k = 0; k < 16; k++) {
        float4 a0 = *(const float4*)&As[k][ty * 8];
        float4 a1 = *(const float4*)&As[k][ty * 8 + 4];
        float4 b0 = *(const float4*)&Bs[k][tx * 8];
        float4 b1 = *(const float4*)&Bs[k][tx * 8 + 4];
        float av[8] = {a0.x, a0.y, a0.z, a0.w, a1.x, a1.y, a1.z, a1.w};
        float bv[8] = {b0.x, b0.y, b0.z, b0.w, b1.x, b1.y, b1.z, b1.w};
#pragma unroll
        for (int i = 0; i < 8; i++)
#pragma unroll
            for (int j = 0; j < 8; j++)
                acc[i][j] = fmaf(av[i], bv[j], acc[i][j]);
    }
}
__device__ __forceinline__ void cpB(float (*Bs)[128], const float* __restrict__ W,
                                    int n0, int kc, int tid) {
#pragma unroll
    for (int i = 0; i < 2; i++) {
        int q = i * 256 + tid;
        int r = q >> 5, c4 = q & 31;
        cp16(&Bs[r][c4 * 4], &W[(size_t)(kc * 16 + r) * DD + n0 + c4 * 4]);
    }
}

// ============================================================
// Table pass 1: g_th[z] = silu(rbf(grid) @ W1[z] + b1[z]); grid (NP/128,4,L)
// ============================================================
__global__ void __launch_bounds__(256, 2) k_tab1(const float* __restrict__ Wb,
                                                 const float* __restrict__ bb_) {
    __shared__ float As[16][132];
    __shared__ float Bs[2][16][128];
    int tid = threadIdx.x, tx = tid & 15, ty = tid >> 4;
    int m0 = blockIdx.x * 128, n0 = blockIdx.y * 128, l = blockIdx.z;
    const float* W = Wb + (size_t)l * NRBF * DD;
    const float* b = bb_ + (size_t)l * DD;
    const float step = 6.0f / 127.0f;

    cpB(Bs[0], W, n0, 0, tid);
    cp_commit();

    float acc[8][8] = {};
#pragma unroll 1
    for (int kc = 0; kc < NRBF / 16; kc++) {
        int buf = kc & 1;
#pragma unroll
        for (int i = 0; i < 8; i++) {
            int idx = i * 256 + tid;
            int m = idx & 127, k = idx >> 7;
            float d = (float)(m0 + m) * HSTEP;
            float c = (float)(kc * 16 + k) * step;
            float dd = d - c;
            As[k][m] = __expf(-10.0f * dd * dd);
        }
        if (kc + 1 < NRBF / 16) { cpB(Bs[buf ^ 1], W, n0, kc + 1, tid); cp_commit(); }
        cp_wait0();
        __syncthreads();
        mma_tile(As, Bs[buf], tx, ty, acc);
        __syncthreads();
    }

    float bb[8];
#pragma unroll
    for (int j = 0; j < 8; j++) bb[j] = b[n0 + tx * 8 + j];
    float* out = g_th + (size_t)l * NP * DD;
#pragma unroll
    for (int i = 0; i < 8; i++) {
        float o[8];
#pragma unroll
        for (int j = 0; j < 8; j++) o[j] = silu_f(acc[i][j] + bb[j]);
        float* dst = out + (size_t)(m0 + ty * 8 + i) * DD + n0 + tx * 8;
        *(float4*)dst = make_float4(o[0], o[1], o[2], o[3]);
        *(float4*)(dst + 4) = make_float4(o[4], o[5], o[6], o[7]);
    }
}

// ============================================================
// HMMA bf16x3 GEMM with ldmatrix + swizzled 128B-row smem.
// Tile 128x128, 8 warps (2m x 4n), warp tile 64x32, BK=32.
// Plane layout (per buffer): A[128 rows][32 u32] where u32 cols 0-15 = hi
// (k0..31 packed), 16-31 = lo; 16B chunks XOR-swizzled by (row&7).
// B same with rows = n. A plane 16KB, B plane 16KB, x2 buffers = 64KB.
// ============================================================
#define A_OFF(buf) ((buf) * 32768)
#define B_OFF(buf) ((buf) * 32768 + 16384)
#define SMEM_GEMM (65536 + 512)

template <int EPI>
__global__ void __launch_bounds__(256) k_gemm(const float* __restrict__ Wb,
                                              const float* __restrict__ bb_) {
    extern __shared__ uint32_t smem_u[];
    char* smem_c = (char*)smem_u;
    float* sbias = (float*)(smem_c + 65536);
    const uint32_t sbase = (uint32_t)__cvta_generic_to_shared(smem_u);

    int tid = threadIdx.x, lane = tid & 31, wid = tid >> 5;
    int m0 = blockIdx.x * 128, n0 = blockIdx.y * 128, l = blockIdx.z;
    const float* A = (EPI == 0) ? g_agg : (EPI == 1) ? g_t : (g_th + (size_t)l * NP * DD);
    const float* W = (EPI == 2) ? Wb + (size_t)l * DD * DD : Wb;
    const float* b = (EPI == 2) ? bb_ + (size_t)l * DD : bb_;

    if (tid < 128) sbias[tid] = b[n0 + tid];

    // staging mapping
    const int ar = tid >> 1, kh = tid & 1;          // A: row, k-half (16 bf16)
    const int kp = tid >> 4, ng = (tid & 15) * 8;   // B: k-pair, n-group

    // fragment mapping
    const int g = lane >> 2, tig = lane & 3;
    const int wm = (wid >> 2) * 64, wn = (wid & 3) * 32;
    const int lq = lane >> 3, lr = lane & 7;
    const int rowA = (lq & 1) * 8 + lr, kqA = lq >> 1;
    const int rowB = (lq >> 1) * 8 + lr, kqB = lq & 1;
    const uint32_t aBase = sbase + (wm + rowA) * 128;
    const uint32_t bBase = sbase + 16384 + (wn + rowB) * 128;

    float4 va[4], vb[4];
#pragma unroll
    for (int i = 0; i < 4; i++)
        va[i] = *(const float4*)&A[(size_t)(m0 + ar) * DD + kh * 16 + i * 4];
    vb[0] = *(const float4*)&W[(size_t)(2 * kp) * DD + n0 + ng];
    vb[1] = *(const float4*)&W[(size_t)(2 * kp) * DD + n0 + ng + 4];
    vb[2] = *(const float4*)&W[(size_t)(2 * kp + 1) * DD + n0 + ng];
    vb[3] = *(const float4*)&W[(size_t)(2 * kp + 1) * DD + n0 + ng + 4];

    auto stage = [&](int buf) {
        char* Ab = smem_c + A_OFF(buf);
        char* Bb = smem_c + B_OFF(buf);
        // A: 16 k-contig floats -> 2 hi chunks + 2 lo chunks (STS.128)
        float fa[16] = {va[0].x, va[0].y, va[0].z, va[0].w, va[1].x, va[1].y, va[1].z, va[1].w,
                        va[2].x, va[2].y, va[2].z, va[2].w, va[3].x, va[3].y, va[3].z, va[3].w};
        uint4 H0, L0, H1, L1;
        split8(fa, H0, L0);
        split8(fa + 8, H1, L1);
        int ph = ar & 7, c0 = kh * 2, c1 = kh * 2 + 1;
        char* rbA = Ab + ar * 128;
        *(uint4*)(rbA + ((c0 ^ ph) << 4)) = H0;
        *(uint4*)(rbA + (((c0 ^ ph) ^ 4) << 4)) = L0;
        *(uint4*)(rbA + ((c1 ^ ph) << 4)) = H1;
        *(uint4*)(rbA + (((c1 ^ ph) ^ 4) << 4)) = L1;
        // B: 8 n x 2 k -> per n one hi u32 + one lo u32
        float fk0[8] = {vb[0].x, vb[0].y, vb[0].z, vb[0].w, vb[1].x, vb[1].y, vb[1].z, vb[1].w};
        float fk1[8] = {vb[2].x, vb[2].y, vb[2].z, vb[2].w, vb[3].x, vb[3].y, vb[3].z, vb[3].w};
        int kc4 = kp >> 2, ko = (kp & 3) * 4;
#pragma unroll
        for (int i = 0; i < 8; i++) {
            __nv_bfloat16 h0, l0, h1, l1;
            split_bf(fk0[i], h0, l0);
            split_bf(fk1[i], h1, l1);
            int n = ng + i, phn = n & 7;
            char* rbB = Bb + n * 128;
            *(uint32_t*)(rbB + ((kc4 ^ phn) << 4) + ko) = pack_bf(h0, h1);
            *(uint32_t*)(rbB + (((kc4 ^ phn) ^ 4) << 4) + ko) = pack_bf(l0, l1);
        }
    };
    stage(0);
    __syncthreads();

    float acc[4][4][4] = {};
    const int NCH = DD / 32;
#pragma unroll 1
    for (int kc = 0; kc < NCH; kc++) {
        int buf = kc & 1;
        if (kc + 1 < NCH) {
            int kb = (kc + 1) * 32;
#pragma unroll
            for (int i = 0; i < 4; i++)
                va[i] = *(const float4*)&A[(size_t)(m0 + ar) * DD + kb + kh * 16 + i * 4];
            vb[0] = *(const float4*)&W[(size_t)(kb + 2 * kp) * DD + n0 + ng];
            vb[1] = *(const float4*)&W[(size_t)(kb + 2 * kp) * DD + n0 + ng + 4];
            vb[2] = *(const float4*)&W[(size_t)(kb + 2 * kp + 1) * DD + n0 + ng];
            vb[3] = *(const float4*)&W[(size_t)(kb + 2 * kp + 1) * DD + n0 + ng + 4];
        }
#pragma unroll
        for (int ks = 0; ks < 2; ks++) {
            uint32_t aH[4][4], aL[4][4], bH[2][4], bL[2][4];
            uint32_t chA = (uint32_t)(((ks * 2 + kqA) ^ (rowA & 7)) << 4);
            uint32_t chB = (uint32_t)(((ks * 2 + kqB) ^ (rowB & 7)) << 4);
#pragma unroll
            for (int mt = 0; mt < 4; mt++) {
                uint32_t ad = aBase + (uint32_t)A_OFF(buf) + mt * 2048 + chA;
                ldsm4(aH[mt], ad);
                ldsm4(aL[mt], ad ^ 64);
            }
#pragma unroll
            for (int np = 0; np < 2; np++) {
                uint32_t bd = bBase + (uint32_t)(buf * 32768) + np * 2048 + chB;
                ldsm4(bH[np], bd);
                ldsm4(bL[np], bd ^ 64);
            }
#pragma unroll
            for (int mt = 0; mt < 4; mt++)
#pragma unroll
                for (int nt = 0; nt < 4; nt++) {
                    uint32_t bh0 = bH[nt >> 1][(nt & 1) * 2], bh1 = bH[nt >> 1][(nt & 1) * 2 + 1];
                    uint32_t bl0 = bL[nt >> 1][(nt & 1) * 2], bl1 = bL[nt >> 1][(nt & 1) * 2 + 1];
                    mma_bf16(acc[mt][nt], aH[mt], bh0, bh1);
                    mma_bf16(acc[mt][nt], aH[mt], bl0, bl1);
                    mma_bf16(acc[mt][nt], aL[mt], bh0, bh1);
                }
        }
        if (kc + 1 < NCH) stage(buf ^ 1);
        __syncthreads();
    }

    // ---- epilogue ----
#pragma unroll
    for (int mt = 0; mt < 4; mt++) {
#pragma unroll
        for (int nt = 0; nt < 4; nt++) {
            int row = m0 + wm + mt * 16 + g;
            int cl = wn + nt * 8 + tig * 2;
            float b0 = sbias[cl], b1 = sbias[cl + 1];
            float* c = acc[mt][nt];
#pragma unroll
            for (int half = 0; half < 2; half++) {
                int r = row + half * 8;
                float v0 = c[half * 2 + 0] + b0, v1 = c[half * 2 + 1] + b1;
                size_t off = (size_t)r * DD + n0 + cl;
                if (EPI == 0) {
                    *(float2*)(g_t + off) = make_float2(silu_f(v0), silu_f(v1));
                } else if (EPI == 1) {
                    float2 x = *(float2*)(g_x + off);
                    x.x += v0; x.y += v1;
                    *(float2*)(g_x + off) = x;
                } else {
                    *(float2*)(g_tab + (size_t)l * NP * DD + off) = make_float2(v0, v1);
                }
            }
        }
    }
}

// ============================================================
// Edge pass: agg[node] = sum_{32 edges} lerp(tab_l, d_e) * x[col_e]
// ============================================================
__global__ void __launch_bounds__(128) k_agg(const int* __restrict__ col, int l) {
    __shared__ int   scol[32];
    __shared__ int   sidx[32];
    __shared__ float sw[32];
    const float* tab = g_tab + (size_t)l * NP * DD;
    int node = blockIdx.x, tid = threadIdx.x;
    if (tid < 32) {
        int e = node * 32 + tid;
        scol[tid] = col[e];
        float f = g_dist[e] * INVH;
        int i = (int)f;
        if (i > NP - 2) i = NP - 2;
        sidx[tid] = i;
        sw[tid] = f - (float)i;
    }
    __syncthreads();

    int dim = tid * 4;
    float4 a = make_float4(0.f, 0.f, 0.f, 0.f);
#pragma unroll 8
    for (int e = 0; e < 32; e++) {
        size_t tbase = (size_t)sidx[e] * DD + dim;
        float4 t0 = *(const float4*)&tab[tbase];
        float4 t1 = *(const float4*)&tab[tbase + DD];
        float4 xv = *(const float4*)&g_x[(size_t)scol[e] * DD + dim];
        float w = sw[e];
        a.x = fmaf(fmaf(w, t1.x - t0.x, t0.x), xv.x, a.x);
        a.y = fmaf(fmaf(w, t1.y - t0.y, t0.y), xv.y, a.y);
        a.z = fmaf(fmaf(w, t1.z - t0.z, t0.z), xv.z, a.z);
        a.w = fmaf(fmaf(w, t1.w - t0.w, t0.w), xv.w, a.w);
    }
    *(float4*)&g_agg[(size_t)node * DD + dim] = a;
}

// ============================================================
__global__ void k_copy_out(float* __restrict__ out) {
    size_t i = (size_t)blockIdx.x * 256 + threadIdx.x;
    ((float4*)out)[i] = ((const float4*)g_x)[i];
}
__global__ void k_mask(float* __restrict__ out, const int* __restrict__ tok, int n) {
    int i = blockIdx.x * 256 + threadIdx.x;
    if (i < n) out[i] = (i < BNODES && tok[i] == 0) ? 1.0f : 0.0f;
}

// ============================================================
extern "C" void kernel_launch(void* const* d_in, const int* in_sizes, int n_in,
                              void* d_out, int out_size) {
    const int*   tok    = (const int*)d_in[0];
    const float* coords = (const float*)d_in[1];
    const int*   ei     = (const int*)d_in[2];
    const float* emb    = (const float*)d_in[3];
    const float* ew1    = (const float*)d_in[4];
    const float* eb1    = (const float*)d_in[5];
    const float* ew2    = (const float*)d_in[6];
    const float* eb2    = (const float*)d_in[7];
    const float* nw1    = (const float*)d_in[8];
    const float* nb1    = (const float*)d_in[9];
    const float* nw2    = (const float*)d_in[10];
    const float* nb2    = (const float*)d_in[11];

    cudaFuncSetAttribute(k_gemm<0>, cudaFuncAttributeMaxDynamicSharedMemorySize, SMEM_GEMM);
    cudaFuncSetAttribute(k_gemm<1>, cudaFuncAttributeMaxDynamicSharedMemorySize, SMEM_GEMM);
    cudaFuncSetAttribute(k_gemm<2>, cudaFuncAttributeMaxDynamicSharedMemorySize, SMEM_GEMM);

    k_gather<<<BNODES, 128>>>(tok, emb);
    k_dist<<<EE / 256, 256>>>(ei, coords);

    k_tab1<<<dim3(NP / 128, 4, NLAYER), 256>>>(ew1, eb1);
    k_gemm<2><<<dim3(NP / 128, 4, NLAYER), 256, SMEM_GEMM>>>(ew2, eb2);

    const int* col = ei + EE;
    for (int l = 0; l < NLAYER; l++) {
        k_agg<<<BNODES, 128>>>(col, l);
        k_gemm<0><<<dim3(BNODES / 128, 4), 256, SMEM_GEMM>>>(nw1 + (size_t)l * DD * DD,
                                                             nb1 + l * DD);
        k_gemm<1><<<dim3(BNODES / 128, 4), 256, SMEM_GEMM>>>(nw2 + (size_t)l * DD * DD,
                                                             nb2 + l * DD);
    }

    k_copy_out<<<(BNODES * DD) / (256 * 4), 256>>>((float*)d_out);
    int extra = out_size - BNODES * DD;
    if (extra > 0)
        k_mask<<<(extra + 255) / 256, 256>>>((float*)d_out + BNODES * DD, tok, extra);
}

// round 10
// speedup vs baseline: 1.6421x; 1.2093x over previous
#include <cuda_runtime.h>
#include <cuda_bf16.h>
#include <cstdint>

// ----- problem constants -----
#define BNODES 8192
#define EE     262144
#define DD     512
#define NRBF   128
#define NLAYER 4

// ----- distance->ef lookup table -----
#define NP    2048
#define DMAXF 10.4f
#define HSTEP (DMAXF / (float)(NP - 1))
#define INVH  ((float)(NP - 1) / DMAXF)

// ----- device scratch -----
// split format: per row, u32[0..255] = bf16 hi pairs (k0k1,...), u32[256..511] = lo pairs
__device__ float    g_x[BNODES * DD];
__device__ float    g_dist[EE];
__device__ float    g_tab[NLAYER * NP * DD];      // fp32 ef tables (k_agg input)
__device__ uint32_t g_thS[NLAYER * NP * DD];      // split hidden tables
__device__ uint32_t g_aggS[BNODES * DD];          // split agg
__device__ uint32_t g_tS[BNODES * DD];            // split node hidden
__device__ uint32_t g_wS[12 * DD * DD];           // split transposed weights: [mat][n][512]

__device__ __forceinline__ float silu_f(float v) { return v / (1.0f + __expf(-v)); }

__device__ __forceinline__ void cp16(void* dst, const void* src) {
    uint32_t d = (uint32_t)__cvta_generic_to_shared(dst);
    asm volatile("cp.async.cg.shared.global [%0], [%1], 16;" :: "r"(d), "l"(src));
}
__device__ __forceinline__ void cp_commit() { asm volatile("cp.async.commit_group;"); }
__device__ __forceinline__ void cp_wait0() { asm volatile("cp.async.wait_group 0;" ::: "memory"); }
__device__ __forceinline__ void cp_wait1() { asm volatile("cp.async.wait_group 1;" ::: "memory"); }

__device__ __forceinline__ void split_bf(float x, __nv_bfloat16& h, __nv_bfloat16& l) {
    h = __float2bfloat16_rn(x);
    l = __float2bfloat16_rn(x - __bfloat162float(h));
}
__device__ __forceinline__ uint32_t pack_bf(__nv_bfloat16 a, __nv_bfloat16 b) {
    __nv_bfloat162 p;
    p.x = a; p.y = b;
    return *(uint32_t*)&p;
}
__device__ __forceinline__ void split8(const float* f, uint4& H, uint4& L) {
    __nv_bfloat16 h[8], l[8];
#pragma unroll
    for (int j = 0; j < 8; j++) split_bf(f[j], h[j], l[j]);
    H = make_uint4(pack_bf(h[0], h[1]), pack_bf(h[2], h[3]),
                   pack_bf(h[4], h[5]), pack_bf(h[6], h[7]));
    L = make_uint4(pack_bf(l[0], l[1]), pack_bf(l[2], l[3]),
                   pack_bf(l[4], l[5]), pack_bf(l[6], l[7]));
}

__device__ __forceinline__ void mma_bf16(float* c, const uint32_t* a, uint32_t b0, uint32_t b1) {
    asm volatile(
        "mma.sync.aligned.m16n8k16.row.col.f32.bf16.bf16.f32 "
        "{%0,%1,%2,%3}, {%4,%5,%6,%7}, {%8,%9}, {%0,%1,%2,%3};"
        : "+f"(c[0]), "+f"(c[1]), "+f"(c[2]), "+f"(c[3])
        : "r"(a[0]), "r"(a[1]), "r"(a[2]), "r"(a[3]), "r"(b0), "r"(b1));
}
__device__ __forceinline__ void ldsm4(uint32_t* r, uint32_t addr) {
    asm volatile("ldmatrix.sync.aligned.m8n8.x4.shared.b16 {%0,%1,%2,%3}, [%4];"
                 : "=r"(r[0]), "=r"(r[1]), "=r"(r[2]), "=r"(r[3]) : "r"(addr));
}

// ============================================================
__global__ void k_gather(const int* __restrict__ tok, const float* __restrict__ emb) {
    int i = blockIdx.x;
    int t = tok[i];
    ((float4*)(g_x + (size_t)i * DD))[threadIdx.x] =
        ((const float4*)(emb + (size_t)t * DD))[threadIdx.x];
}

__global__ void k_dist(const int* __restrict__ ei, const float* __restrict__ coords) {
    int e = blockIdx.x * 256 + threadIdx.x;
    int r = ei[e], c = ei[EE + e];
    float dx = coords[r * 3 + 0] - coords[c * 3 + 0];
    float dy = coords[r * 3 + 1] - coords[c * 3 + 1];
    float dz = coords[r * 3 + 2] - coords[c * 3 + 2];
    g_dist[e] = sqrtf(dx * dx + dy * dy + dz * dz);
}

// ============================================================
// Weight prep: transpose + split. In: W[L][k=512][n=512] fp32.
// Out: g_wS[(matBase+l)][n][512]u32 (hi pairs | lo pairs along k).
// ============================================================
__global__ void k_wsplit(const float* __restrict__ Wb, int matBase) {
    __shared__ float ts[32][33];
    int k0 = blockIdx.x * 32, n0 = blockIdx.y * 32, l = blockIdx.z;
    const float* in = Wb + (size_t)l * DD * DD;
    uint32_t* out = g_wS + (size_t)(matBase + l) * DD * DD;
    int tx = threadIdx.x, ty = threadIdx.y;   // 32 x 8
#pragma unroll
    for (int i = 0; i < 4; i++)
        ts[ty + i * 8][tx] = in[(size_t)(k0 + ty + i * 8) * DD + n0 + tx];
    __syncthreads();
    int w_n = ty * 4 + (tx >> 3);
    int kp8 = tx & 7;
#pragma unroll
    for (int i = 0; i < 2; i++) {
        int kpl = kp8 * 2 + i;            // 0..15
        int kl = kpl * 2;
        __nv_bfloat16 h0, l0, h1, l1;
        split_bf(ts[kl][w_n], h0, l0);
        split_bf(ts[kl + 1][w_n], h1, l1);
        size_t base = (size_t)(n0 + w_n) * DD + (k0 >> 1) + kpl;
        out[base] = pack_bf(h0, h1);
        out[base + 256] = pack_bf(l0, l1);
    }
}

// ============================================================
// scalar FFMA GEMM bits (k_tab1 only)
// ============================================================
__device__ __forceinline__ void mma_tile(const float (*As)[132], const float (*Bs)[128],
                                         int tx, int ty, float acc[8][8]) {
#pragma unroll
    for (int k = 0; k < 16; k++) {
        float4 a0 = *(const float4*)&As[k][ty * 8];
        float4 a1 = *(const float4*)&As[k][ty * 8 + 4];
        float4 b0 = *(const float4*)&Bs[k][tx * 8];
        float4 b1 = *(const float4*)&Bs[k][tx * 8 + 4];
        float av[8] = {a0.x, a0.y, a0.z, a0.w, a1.x, a1.y, a1.z, a1.w};
        float bv[8] = {b0.x, b0.y, b0.z, b0.w, b1.x, b1.y, b1.z, b1.w};
#pragma unroll
        for (int i = 0; i < 8; i++)
#pragma unroll
            for (int j = 0; j < 8; j++)
                acc[i][j] = fmaf(av[i], bv[j], acc[i][j]);
    }
}
__device__ __forceinline__ void cpB(float (*Bs)[128], const float* __restrict__ W,
                                    int n0, int kc, int tid) {
#pragma unroll
    for (int i = 0; i < 2; i++) {
        int q = i * 256 + tid;
        int r = q >> 5, c4 = q & 31;
        cp16(&Bs[r][c4 * 4], &W[(size_t)(kc * 16 + r) * DD + n0 + c4 * 4]);
    }
}

// ============================================================
// Table pass 1: g_thS[z] = split(silu(rbf(grid) @ W1[z] + b1[z]))
// grid (NP/128, 4, NLAYER)
// ============================================================
__global__ void __launch_bounds__(256, 2) k_tab1(const float* __restrict__ Wb,
                                                 const float* __restrict__ bb_) {
    __shared__ float As[16][132];
    __shared__ float Bs[2][16][128];
    int tid = threadIdx.x, tx = tid & 15, ty = tid >> 4;
    int m0 = blockIdx.x * 128, n0 = blockIdx.y * 128, l = blockIdx.z;
    const float* W = Wb + (size_t)l * NRBF * DD;
    const float* b = bb_ + (size_t)l * DD;
    const float step = 6.0f / 127.0f;

    cpB(Bs[0], W, n0, 0, tid);
    cp_commit();

    float acc[8][8] = {};
#pragma unroll 1
    for (int kc = 0; kc < NRBF / 16; kc++) {
        int buf = kc & 1;
#pragma unroll
        for (int i = 0; i < 8; i++) {
            int idx = i * 256 + tid;
            int m = idx & 127, k = idx >> 7;
            float d = (float)(m0 + m) * HSTEP;
            float c = (float)(kc * 16 + k) * step;
            float dd = d - c;
            As[k][m] = __expf(-10.0f * dd * dd);
        }
        if (kc + 1 < NRBF / 16) { cpB(Bs[buf ^ 1], W, n0, kc + 1, tid); cp_commit(); }
        cp_wait0();
        __syncthreads();
        mma_tile(As, Bs[buf], tx, ty, acc);
        __syncthreads();
    }

    float bb[8];
#pragma unroll
    for (int j = 0; j < 8; j++) bb[j] = b[n0 + tx * 8 + j];
    uint32_t* out = g_thS + (size_t)l * NP * DD;
#pragma unroll
    for (int i = 0; i < 8; i++) {
        float o[8];
#pragma unroll
        for (int j = 0; j < 8; j++) o[j] = silu_f(acc[i][j] + bb[j]);
        uint4 H, L;
        split8(o, H, L);
        size_t rb = (size_t)(m0 + ty * 8 + i) * DD + tx * 4 + (n0 >> 1);
        *(uint4*)&out[rb] = H;
        *(uint4*)&out[rb + 256] = L;
    }
}

// ============================================================
// HMMA bf16x3 GEMM, pre-split inputs, pure cp.async staging, 3 stages.
// Tile 128x128, 8 warps (2m x 4n), warp tile 64x32, BK=32.
// smem row (128B) = 8 swizzled 16B chunks: logical 0-3 hi, 4-7 lo,
// chunk pos = (c ^ (row&7)). Stage buffer = A plane 16KB + B plane 16KB.
// EPI 0: g_tS = split(silu(.)); 1: g_x += .; 2: g_tab[z] = .
// ============================================================
#define NSTAGE 3
#define SMEM_GEMM (NSTAGE * 32768 + 512)

template <int EPI>
__global__ void __launch_bounds__(256) k_gemm(int mat, const float* __restrict__ bb_) {
    extern __shared__ uint32_t smem_u[];
    char* smem_c = (char*)smem_u;
    float* sbias = (float*)(smem_c + NSTAGE * 32768);
    const uint32_t sbase = (uint32_t)__cvta_generic_to_shared(smem_u);

    int tid = threadIdx.x, lane = tid & 31, wid = tid >> 5;
    int m0 = blockIdx.x * 128, n0 = blockIdx.y * 128, l = blockIdx.z;
    const uint32_t* Aq = (EPI == 0) ? g_aggS : (EPI == 1) ? g_tS
                                             : (g_thS + (size_t)l * NP * DD);
    const uint32_t* Wq = g_wS + (size_t)(mat + l) * DD * DD;
    const float* b = (EPI == 2) ? bb_ + (size_t)l * DD : bb_;

    if (tid < 128) sbias[tid] = b[n0 + tid];

    // staging: thread -> row tid>>1, 4 chunks (hi if tid even half, lo if odd)
    const int srow = tid >> 1, cbase = (tid & 1) * 4;
    const uint32_t* aRow = Aq + (size_t)(m0 + srow) * DD + (cbase ? 256 : 0);
    const uint32_t* bRow = Wq + (size_t)(n0 + srow) * DD + (cbase ? 256 : 0);
    uint32_t dstOff[4];
#pragma unroll
    for (int j = 0; j < 4; j++)
        dstOff[j] = srow * 128 + (((cbase + j) ^ (srow & 7)) << 4);

    auto issue = [&](int kc, int buf) {
        char* Ab = smem_c + buf * 32768;
        char* Bb = Ab + 16384;
        const uint32_t* as = aRow + kc * 16;
        const uint32_t* bs = bRow + kc * 16;
#pragma unroll
        for (int j = 0; j < 4; j++) cp16(Ab + dstOff[j], as + j * 4);
#pragma unroll
        for (int j = 0; j < 4; j++) cp16(Bb + dstOff[j], bs + j * 4);
        cp_commit();
    };

    // fragment mapping (verified round 8/9)
    const int g = lane >> 2, tig = lane & 3;
    const int wm = (wid >> 2) * 64, wn = (wid & 3) * 32;
    const int lq = lane >> 3, lr = lane & 7;
    const int rowA = (lq & 1) * 8 + lr, kqA = lq >> 1;
    const int rowB = (lq >> 1) * 8 + lr, kqB = lq & 1;
    const uint32_t aBase = sbase + (wm + rowA) * 128;
    const uint32_t bBase = sbase + 16384 + (wn + rowB) * 128;

    issue(0, 0);
    issue(1, 1);

    float acc[4][4][4] = {};
    const int NCH = DD / 32;
#pragma unroll 1
    for (int kc = 0; kc < NCH; kc++) {
        int buf = kc % NSTAGE;
        if (kc + 2 < NCH) cp_wait1(); else cp_wait0();
        __syncthreads();
#pragma unroll
        for (int ks = 0; ks < 2; ks++) {
            uint32_t aH[4][4], aL[4][4], bH[2][4], bL[2][4];
            uint32_t chA = (uint32_t)(((ks * 2 + kqA) ^ (rowA & 7)) << 4);
            uint32_t chB = (uint32_t)(((ks * 2 + kqB) ^ (rowB & 7)) << 4);
#pragma unroll
            for (int mt = 0; mt < 4; mt++) {
                uint32_t ad = aBase + buf * 32768 + mt * 2048 + chA;
                ldsm4(aH[mt], ad);
                ldsm4(aL[mt], ad ^ 64);
            }
#pragma unroll
            for (int np = 0; np < 2; np++) {
                uint32_t bd = bBase + buf * 32768 + np * 2048 + chB;
                ldsm4(bH[np], bd);
                ldsm4(bL[np], bd ^ 64);
            }
#pragma unroll
            for (int mt = 0; mt < 4; mt++)
#pragma unroll
                for (int nt = 0; nt < 4; nt++) {
                    uint32_t bh0 = bH[nt >> 1][(nt & 1) * 2], bh1 = bH[nt >> 1][(nt & 1) * 2 + 1];
                    uint32_t bl0 = bL[nt >> 1][(nt & 1) * 2], bl1 = bL[nt >> 1][(nt & 1) * 2 + 1];
                    mma_bf16(acc[mt][nt], aH[mt], bh0, bh1);
                    mma_bf16(acc[mt][nt], aH[mt], bl0, bl1);
                    mma_bf16(acc[mt][nt], aL[mt], bh0, bh1);
                }
        }
        if (kc + 2 < NCH) issue(kc + 2, (kc + 2) % NSTAGE);
    }

    // ---- epilogue ----
#pragma unroll
    for (int mt = 0; mt < 4; mt++) {
#pragma unroll
        for (int nt = 0; nt < 4; nt++) {
            int row = m0 + wm + mt * 16 + g;
            int cl = wn + nt * 8 + tig * 2;
            float b0 = sbias[cl], b1 = sbias[cl + 1];
            float* c = acc[mt][nt];
#pragma unroll
            for (int half = 0; half < 2; half++) {
                int r = row + half * 8;
                float v0 = c[half * 2 + 0] + b0, v1 = c[half * 2 + 1] + b1;
                size_t off = (size_t)r * DD + n0 + cl;
                if (EPI == 0) {
                    __nv_bfloat16 h0, l0, h1, l1;
                    float s0 = silu_f(v0), s1 = silu_f(v1);
                    split_bf(s0, h0, l0);
                    split_bf(s1, h1, l1);
                    size_t rb = (size_t)r * DD + ((n0 + cl) >> 1);
                    g_tS[rb] = pack_bf(h0, h1);
                    g_tS[rb + 256] = pack_bf(l0, l1);
                } else if (EPI == 1) {
                    float2 x = *(float2*)(g_x + off);
                    x.x += v0; x.y += v1;
                    *(float2*)(g_x + off) = x;
                } else {
                    *(float2*)(g_tab + (size_t)l * NP * DD + off) = make_float2(v0, v1);
                }
            }
        }
    }
}

// ============================================================
// Edge pass: aggS[node] = split( sum_{32} lerp(tab_l, d_e) * x[col_e] )
// ============================================================
__global__ void __launch_bounds__(128) k_agg(const int* __restrict__ col, int l) {
    __shared__ int   scol[32];
    __shared__ int   sidx[32];
    __shared__ float sw[32];
    const float* tab = g_tab + (size_t)l * NP * DD;
    int node = blockIdx.x, tid = threadIdx.x;
    if (tid < 32) {
        int e = node * 32 + tid;
        scol[tid] = col[e];
        float f = g_dist[e] * INVH;
        int i = (int)f;
        if (i > NP - 2) i = NP - 2;
        sidx[tid] = i;
        sw[tid] = f - (float)i;
    }
    __syncthreads();

    int dim = tid * 4;
    float4 a = make_float4(0.f, 0.f, 0.f, 0.f);
#pragma unroll 8
    for (int e = 0; e < 32; e++) {
        size_t tbase = (size_t)sidx[e] * DD + dim;
        float4 t0 = *(const float4*)&tab[tbase];
        float4 t1 = *(const float4*)&tab[tbase + DD];
        float4 xv = *(const float4*)&g_x[(size_t)scol[e] * DD + dim];
        float w = sw[e];
        a.x = fmaf(fmaf(w, t1.x - t0.x, t0.x), xv.x, a.x);
        a.y = fmaf(fmaf(w, t1.y - t0.y, t0.y), xv.y, a.y);
        a.z = fmaf(fmaf(w, t1.z - t0.z, t0.z), xv.z, a.z);
        a.w = fmaf(fmaf(w, t1.w - t0.w, t0.w), xv.w, a.w);
    }
    __nv_bfloat16 h0, l0, h1, l1, h2, l2, h3, l3;
    split_bf(a.x, h0, l0);
    split_bf(a.y, h1, l1);
    split_bf(a.z, h2, l2);
    split_bf(a.w, h3, l3);
    size_t rb = (size_t)node * DD + tid * 2;
    *(uint2*)&g_aggS[rb] = make_uint2(pack_bf(h0, h1), pack_bf(h2, h3));
    *(uint2*)&g_aggS[rb + 256] = make_uint2(pack_bf(l0, l1), pack_bf(l2, l3));
}

// ============================================================
__global__ void k_copy_out(float* __restrict__ out) {
    size_t i = (size_t)blockIdx.x * 256 + threadIdx.x;
    ((float4*)out)[i] = ((const float4*)g_x)[i];
}
__global__ void k_mask(float* __restrict__ out, const int* __restrict__ tok, int n) {
    int i = blockIdx.x * 256 + threadIdx.x;
    if (i < n) out[i] = (i < BNODES && tok[i] == 0) ? 1.0f : 0.0f;
}

// ============================================================
extern "C" void kernel_launch(void* const* d_in, const int* in_sizes, int n_in,
                              void* d_out, int out_size) {
    const int*   tok    = (const int*)d_in[0];
    const float* coords = (const float*)d_in[1];
    const int*   ei     = (const int*)d_in[2];
    const float* emb    = (const float*)d_in[3];
    const float* ew1    = (const float*)d_in[4];
    const float* eb1    = (const float*)d_in[5];
    const float* ew2    = (const float*)d_in[6];
    const float* eb2    = (const float*)d_in[7];
    const float* nw1    = (const float*)d_in[8];
    const float* nb1    = (const float*)d_in[9];
    const float* nw2    = (const float*)d_in[10];
    const float* nb2    = (const float*)d_in[11];

    cudaFuncSetAttribute(k_gemm<0>, cudaFuncAttributeMaxDynamicSharedMemorySize, SMEM_GEMM);
    cudaFuncSetAttribute(k_gemm<1>, cudaFuncAttributeMaxDynamicSharedMemorySize, SMEM_GEMM);
    cudaFuncSetAttribute(k_gemm<2>, cudaFuncAttributeMaxDynamicSharedMemorySize, SMEM_GEMM);

    k_gather<<<BNODES, 128>>>(tok, emb);
    k_dist<<<EE / 256, 256>>>(ei, coords);

    // weight prep: transpose + bf16 hi/lo split (once per launch)
    k_wsplit<<<dim3(16, 16, NLAYER), dim3(32, 8)>>>(ew2, 0);
    k_wsplit<<<dim3(16, 16, NLAYER), dim3(32, 8)>>>(nw1, 4);
    k_wsplit<<<dim3(16, 16, NLAYER), dim3(32, 8)>>>(nw2, 8);

    k_tab1<<<dim3(NP / 128, 4, NLAYER), 256>>>(ew1, eb1);
    k_gemm<2><<<dim3(NP / 128, 4, NLAYER), 256, SMEM_GEMM>>>(0, eb2);

    const int* col = ei + EE;
    for (int l = 0; l < NLAYER; l++) {
        k_agg<<<BNODES, 128>>>(col, l);
        k_gemm<0><<<dim3(BNODES / 128, 4), 256, SMEM_GEMM>>>(4 + l, nb1 + l * DD);
        k_gemm<1><<<dim3(BNODES / 128, 4), 256, SMEM_GEMM>>>(8 + l, nb2 + l * DD);
    }

    k_copy_out<<<(BNODES * DD) / (256 * 4), 256>>>((float*)d_out);
    int extra = out_size - BNODES * DD;
    if (extra > 0)
        k_mask<<<(extra + 255) / 256, 256>>>((float*)d_out + BNODES * DD, tok, extra);
}

// round 11
// speedup vs baseline: 1.7517x; 1.0667x over previous
#include <cuda_runtime.h>
#include <cuda_bf16.h>
#include <cstdint>

// ----- problem constants -----
#define BNODES 8192
#define EE     262144
#define DD     512
#define NRBF   128
#define NLAYER 4

// ----- distance->ef lookup table -----
#define NP    2048
#define DMAXF 10.4f
#define HSTEP (DMAXF / (float)(NP - 1))
#define INVH  ((float)(NP - 1) / DMAXF)

// ----- device scratch -----
// split format: per row, u32[0..255] = bf16 hi pairs (k0k1,...), u32[256..511] = lo pairs
__device__ float    g_x[BNODES * DD];
__device__ float    g_dist[EE];
__device__ float    g_tab[NLAYER * NP * DD];      // fp32 ef tables (k_agg input)
__device__ uint32_t g_thS[NLAYER * NP * DD];      // split hidden tables
__device__ uint32_t g_aggS[BNODES * DD];          // split agg
__device__ uint32_t g_tS[BNODES * DD];            // split node hidden
__device__ uint32_t g_wS[12 * DD * DD];           // split transposed weights: [mat][n][512]

__device__ __forceinline__ float silu_f(float v) { return v / (1.0f + __expf(-v)); }

__device__ __forceinline__ void cp16(void* dst, const void* src) {
    uint32_t d = (uint32_t)__cvta_generic_to_shared(dst);
    asm volatile("cp.async.cg.shared.global [%0], [%1], 16;" :: "r"(d), "l"(src));
}
__device__ __forceinline__ void cp_commit() { asm volatile("cp.async.commit_group;"); }
__device__ __forceinline__ void cp_wait0() { asm volatile("cp.async.wait_group 0;" ::: "memory"); }
__device__ __forceinline__ void cp_wait1() { asm volatile("cp.async.wait_group 1;" ::: "memory"); }

__device__ __forceinline__ void split_bf(float x, __nv_bfloat16& h, __nv_bfloat16& l) {
    h = __float2bfloat16_rn(x);
    l = __float2bfloat16_rn(x - __bfloat162float(h));
}
__device__ __forceinline__ uint32_t pack_bf(__nv_bfloat16 a, __nv_bfloat16 b) {
    __nv_bfloat162 p;
    p.x = a; p.y = b;
    return *(uint32_t*)&p;
}
__device__ __forceinline__ void split8(const float* f, uint4& H, uint4& L) {
    __nv_bfloat16 h[8], l[8];
#pragma unroll
    for (int j = 0; j < 8; j++) split_bf(f[j], h[j], l[j]);
    H = make_uint4(pack_bf(h[0], h[1]), pack_bf(h[2], h[3]),
                   pack_bf(h[4], h[5]), pack_bf(h[6], h[7]));
    L = make_uint4(pack_bf(l[0], l[1]), pack_bf(l[2], l[3]),
                   pack_bf(l[4], l[5]), pack_bf(l[6], l[7]));
}

__device__ __forceinline__ void mma_bf16(float* c, const uint32_t* a, uint32_t b0, uint32_t b1) {
    asm volatile(
        "mma.sync.aligned.m16n8k16.row.col.f32.bf16.bf16.f32 "
        "{%0,%1,%2,%3}, {%4,%5,%6,%7}, {%8,%9}, {%0,%1,%2,%3};"
        : "+f"(c[0]), "+f"(c[1]), "+f"(c[2]), "+f"(c[3])
        : "r"(a[0]), "r"(a[1]), "r"(a[2]), "r"(a[3]), "r"(b0), "r"(b1));
}
__device__ __forceinline__ void ldsm4(uint32_t* r, uint32_t addr) {
    asm volatile("ldmatrix.sync.aligned.m8n8.x4.shared.b16 {%0,%1,%2,%3}, [%4];"
                 : "=r"(r[0]), "=r"(r[1]), "=r"(r[2]), "=r"(r[3]) : "r"(addr));
}

// ============================================================
__global__ void k_gather(const int* __restrict__ tok, const float* __restrict__ emb) {
    int i = blockIdx.x;
    int t = tok[i];
    ((float4*)(g_x + (size_t)i * DD))[threadIdx.x] =
        ((const float4*)(emb + (size_t)t * DD))[threadIdx.x];
}

__global__ void k_dist(const int* __restrict__ ei, const float* __restrict__ coords) {
    int e = blockIdx.x * 256 + threadIdx.x;
    int r = ei[e], c = ei[EE + e];
    float dx = coords[r * 3 + 0] - coords[c * 3 + 0];
    float dy = coords[r * 3 + 1] - coords[c * 3 + 1];
    float dz = coords[r * 3 + 2] - coords[c * 3 + 2];
    g_dist[e] = sqrtf(dx * dx + dy * dy + dz * dz);
}

// ============================================================
// Weight prep: transpose + split. In: W[L][k=512][n=512] fp32.
// Out: g_wS[(matBase+l)][n][512]u32 (hi pairs | lo pairs along k).
// ============================================================
__global__ void k_wsplit(const float* __restrict__ Wb, int matBase) {
    __shared__ float ts[32][33];
    int k0 = blockIdx.x * 32, n0 = blockIdx.y * 32, l = blockIdx.z;
    const float* in = Wb + (size_t)l * DD * DD;
    uint32_t* out = g_wS + (size_t)(matBase + l) * DD * DD;
    int tx = threadIdx.x, ty = threadIdx.y;   // 32 x 8
#pragma unroll
    for (int i = 0; i < 4; i++)
        ts[ty + i * 8][tx] = in[(size_t)(k0 + ty + i * 8) * DD + n0 + tx];
    __syncthreads();
    int w_n = ty * 4 + (tx >> 3);
    int kp8 = tx & 7;
#pragma unroll
    for (int i = 0; i < 2; i++) {
        int kpl = kp8 * 2 + i;            // 0..15
        int kl = kpl * 2;
        __nv_bfloat16 h0, l0, h1, l1;
        split_bf(ts[kl][w_n], h0, l0);
        split_bf(ts[kl + 1][w_n], h1, l1);
        size_t base = (size_t)(n0 + w_n) * DD + (k0 >> 1) + kpl;
        out[base] = pack_bf(h0, h1);
        out[base + 256] = pack_bf(l0, l1);
    }
}

// ============================================================
// scalar FFMA GEMM bits (k_tab1 only)
// ============================================================
__device__ __forceinline__ void mma_tile(const float (*As)[132], const float (*Bs)[128],
                                         int tx, int ty, float acc[8][8]) {
#pragma unroll
    for (int k = 0; k < 16; k++) {
        float4 a0 = *(const float4*)&As[k][ty * 8];
        float4 a1 = *(const float4*)&As[k][ty * 8 + 4];
        float4 b0 = *(const float4*)&Bs[k][tx * 8];
        float4 b1 = *(const float4*)&Bs[k][tx * 8 + 4];
        float av[8] = {a0.x, a0.y, a0.z, a0.w, a1.x, a1.y, a1.z, a1.w};
        float bv[8] = {b0.x, b0.y, b0.z, b0.w, b1.x, b1.y, b1.z, b1.w};
#pragma unroll
        for (int i = 0; i < 8; i++)
#pragma unroll
            for (int j = 0; j < 8; j++)
                acc[i][j] = fmaf(av[i], bv[j], acc[i][j]);
    }
}
__device__ __forceinline__ void cpB(float (*Bs)[128], const float* __restrict__ W,
                                    int n0, int kc, int tid) {
#pragma unroll
    for (int i = 0; i < 2; i++) {
        int q = i * 256 + tid;
        int r = q >> 5, c4 = q & 31;
        cp16(&Bs[r][c4 * 4], &W[(size_t)(kc * 16 + r) * DD + n0 + c4 * 4]);
    }
}

// ============================================================
// Table pass 1: g_thS[z] = split(silu(rbf(grid) @ W1[z] + b1[z]))
// grid (NP/128, 4, NLAYER)
// ============================================================
__global__ void __launch_bounds__(256, 2) k_tab1(const float* __restrict__ Wb,
                                                 const float* __restrict__ bb_) {
    __shared__ float As[16][132];
    __shared__ float Bs[2][16][128];
    int tid = threadIdx.x, tx = tid & 15, ty = tid >> 4;
    int m0 = blockIdx.x * 128, n0 = blockIdx.y * 128, l = blockIdx.z;
    const float* W = Wb + (size_t)l * NRBF * DD;
    const float* b = bb_ + (size_t)l * DD;
    const float step = 6.0f / 127.0f;

    cpB(Bs[0], W, n0, 0, tid);
    cp_commit();

    float acc[8][8] = {};
#pragma unroll 1
    for (int kc = 0; kc < NRBF / 16; kc++) {
        int buf = kc & 1;
#pragma unroll
        for (int i = 0; i < 8; i++) {
            int idx = i * 256 + tid;
            int m = idx & 127, k = idx >> 7;
            float d = (float)(m0 + m) * HSTEP;
            float c = (float)(kc * 16 + k) * step;
            float dd = d - c;
            As[k][m] = __expf(-10.0f * dd * dd);
        }
        if (kc + 1 < NRBF / 16) { cpB(Bs[buf ^ 1], W, n0, kc + 1, tid); cp_commit(); }
        cp_wait0();
        __syncthreads();
        mma_tile(As, Bs[buf], tx, ty, acc);
        __syncthreads();
    }

    float bb[8];
#pragma unroll
    for (int j = 0; j < 8; j++) bb[j] = b[n0 + tx * 8 + j];
    uint32_t* out = g_thS + (size_t)l * NP * DD;
#pragma unroll
    for (int i = 0; i < 8; i++) {
        float o[8];
#pragma unroll
        for (int j = 0; j < 8; j++) o[j] = silu_f(acc[i][j] + bb[j]);
        uint4 H, L;
        split8(o, H, L);
        size_t rb = (size_t)(m0 + ty * 8 + i) * DD + tx * 4 + (n0 >> 1);
        *(uint4*)&out[rb] = H;
        *(uint4*)&out[rb + 256] = L;
    }
}

// ============================================================
// HMMA bf16x3 GEMM, pre-split inputs, cp.async staging, 3 stages.
// Tile 128x256 (ONE-WAVE grids: 128 CTAs), 8 warps (2m x 4n),
// warp tile 64x64, BK=32.
// smem row (128B) = 8 swizzled 16B chunks (pos = c ^ (row&7));
// stage buffer = A plane 16KB + B plane 32KB = 48KB.
// EPI 0: g_tS = split(silu(.)); 1: g_x += .; 2: g_tab[z] = .
// ============================================================
#define NSTAGE 3
#define STGSZ  49152
#define SMEM_GEMM (NSTAGE * STGSZ + 1024)

template <int EPI>
__global__ void __launch_bounds__(256) k_gemm(int mat, const float* __restrict__ bb_) {
    extern __shared__ uint32_t smem_u[];
    char* smem_c = (char*)smem_u;
    float* sbias = (float*)(smem_c + NSTAGE * STGSZ);
    const uint32_t sbase = (uint32_t)__cvta_generic_to_shared(smem_u);

    int tid = threadIdx.x, lane = tid & 31, wid = tid >> 5;
    int m0 = blockIdx.x * 128, n0 = blockIdx.y * 256, l = blockIdx.z;
    const uint32_t* Aq = (EPI == 0) ? g_aggS : (EPI == 1) ? g_tS
                                             : (g_thS + (size_t)l * NP * DD);
    const uint32_t* Wq = g_wS + (size_t)(mat + l) * DD * DD;
    const float* b = (EPI == 2) ? bb_ + (size_t)l * DD : bb_;

    sbias[tid] = b[n0 + tid];

    // A staging: 2 threads per row, 4 chunks each
    const int srow = tid >> 1, cbase = (tid & 1) * 4;
    const uint32_t* aRow = Aq + (size_t)(m0 + srow) * DD + (cbase ? 256 : 0);
    uint32_t dstA[4];
#pragma unroll
    for (int j = 0; j < 4; j++)
        dstA[j] = srow * 128 + (((cbase + j) ^ (srow & 7)) << 4);
    // B staging: 1 thread per row (256 rows), 8 chunks
    const int brow = tid;
    const uint32_t* bRow = Wq + (size_t)(n0 + brow) * DD;
    uint32_t dstB[8];
#pragma unroll
    for (int c = 0; c < 8; c++)
        dstB[c] = brow * 128 + ((c ^ (brow & 7)) << 4);

    auto issue = [&](int kc, int buf) {
        char* Ab = smem_c + buf * STGSZ;
        char* Bb = Ab + 16384;
        const uint32_t* as = aRow + kc * 16;
#pragma unroll
        for (int j = 0; j < 4; j++) cp16(Ab + dstA[j], as + j * 4);
#pragma unroll
        for (int c = 0; c < 8; c++)
            cp16(Bb + dstB[c], bRow + (c < 4 ? kc * 16 + c * 4 : 256 + kc * 16 + (c - 4) * 4));
        cp_commit();
    };

    // fragment mapping
    const int g = lane >> 2, tig = lane & 3;
    const int wm = (wid >> 2) * 64, wn = (wid & 3) * 64;
    const int lq = lane >> 3, lr = lane & 7;
    const int rowA = (lq & 1) * 8 + lr, kqA = lq >> 1;
    const int rowB = (lq >> 1) * 8 + lr, kqB = lq & 1;
    const uint32_t aBase = sbase + (wm + rowA) * 128;
    const uint32_t bBase = sbase + 16384 + (wn + rowB) * 128;

    issue(0, 0);
    issue(1, 1);

    float acc[4][8][4] = {};
    const int NCH = DD / 32;
#pragma unroll 1
    for (int kc = 0; kc < NCH; kc++) {
        int buf = kc % NSTAGE;
        if (kc + 2 < NCH) cp_wait1(); else cp_wait0();
        __syncthreads();
#pragma unroll
        for (int ks = 0; ks < 2; ks++) {
            uint32_t aH[4][4], aL[4][4], bH[4][4], bL[4][4];
            uint32_t chA = (uint32_t)(((ks * 2 + kqA) ^ (rowA & 7)) << 4);
            uint32_t chB = (uint32_t)(((ks * 2 + kqB) ^ (rowB & 7)) << 4);
#pragma unroll
            for (int mt = 0; mt < 4; mt++) {
                uint32_t ad = aBase + buf * STGSZ + mt * 2048 + chA;
                ldsm4(aH[mt], ad);
                ldsm4(aL[mt], ad ^ 64);
            }
#pragma unroll
            for (int np = 0; np < 4; np++) {
                uint32_t bd = bBase + buf * STGSZ + np * 2048 + chB;
                ldsm4(bH[np], bd);
                ldsm4(bL[np], bd ^ 64);
            }
#pragma unroll
            for (int mt = 0; mt < 4; mt++)
#pragma unroll
                for (int nt = 0; nt < 8; nt++) {
                    uint32_t bh0 = bH[nt >> 1][(nt & 1) * 2], bh1 = bH[nt >> 1][(nt & 1) * 2 + 1];
                    uint32_t bl0 = bL[nt >> 1][(nt & 1) * 2], bl1 = bL[nt >> 1][(nt & 1) * 2 + 1];
                    mma_bf16(acc[mt][nt], aH[mt], bh0, bh1);
                    mma_bf16(acc[mt][nt], aH[mt], bl0, bl1);
                    mma_bf16(acc[mt][nt], aL[mt], bh0, bh1);
                }
        }
        if (kc + 2 < NCH) issue(kc + 2, (kc + 2) % NSTAGE);
    }

    // ---- epilogue ----
#pragma unroll
    for (int mt = 0; mt < 4; mt++) {
#pragma unroll
        for (int nt = 0; nt < 8; nt++) {
            int row = m0 + wm + mt * 16 + g;
            int cl = wn + nt * 8 + tig * 2;
            float b0 = sbias[cl], b1 = sbias[cl + 1];
            float* c = acc[mt][nt];
#pragma unroll
            for (int half = 0; half < 2; half++) {
                int r = row + half * 8;
                float v0 = c[half * 2 + 0] + b0, v1 = c[half * 2 + 1] + b1;
                size_t off = (size_t)r * DD + n0 + cl;
                if (EPI == 0) {
                    __nv_bfloat16 h0, l0, h1, l1;
                    float s0 = silu_f(v0), s1 = silu_f(v1);
                    split_bf(s0, h0, l0);
                    split_bf(s1, h1, l1);
                    size_t rb = (size_t)r * DD + ((n0 + cl) >> 1);
                    g_tS[rb] = pack_bf(h0, h1);
                    g_tS[rb + 256] = pack_bf(l0, l1);
                } else if (EPI == 1) {
                    float2 x = *(float2*)(g_x + off);
                    x.x += v0; x.y += v1;
                    *(float2*)(g_x + off) = x;
                } else {
                    *(float2*)(g_tab + (size_t)l * NP * DD + off) = make_float2(v0, v1);
                }
            }
        }
    }
}

// ============================================================
// Edge pass: aggS[node] = split( sum_{32} lerp(tab_l, d_e) * x[col_e] )
// ============================================================
__global__ void __launch_bounds__(128) k_agg(const int* __restrict__ col, int l) {
    __shared__ int   scol[32];
    __shared__ int   sidx[32];
    __shared__ float sw[32];
    const float* tab = g_tab + (size_t)l * NP * DD;
    int node = blockIdx.x, tid = threadIdx.x;
    if (tid < 32) {
        int e = node * 32 + tid;
        scol[tid] = col[e];
        float f = g_dist[e] * INVH;
        int i = (int)f;
        if (i > NP - 2) i = NP - 2;
        sidx[tid] = i;
        sw[tid] = f - (float)i;
    }
    __syncthreads();

    int dim = tid * 4;
    float4 a = make_float4(0.f, 0.f, 0.f, 0.f);
#pragma unroll 8
    for (int e = 0; e < 32; e++) {
        size_t tbase = (size_t)sidx[e] * DD + dim;
        float4 t0 = *(const float4*)&tab[tbase];
        float4 t1 = *(const float4*)&tab[tbase + DD];
        float4 xv = *(const float4*)&g_x[(size_t)scol[e] * DD + dim];
        float w = sw[e];
        a.x = fmaf(fmaf(w, t1.x - t0.x, t0.x), xv.x, a.x);
        a.y = fmaf(fmaf(w, t1.y - t0.y, t0.y), xv.y, a.y);
        a.z = fmaf(fmaf(w, t1.z - t0.z, t0.z), xv.z, a.z);
        a.w = fmaf(fmaf(w, t1.w - t0.w, t0.w), xv.w, a.w);
    }
    __nv_bfloat16 h0, l0, h1, l1, h2, l2, h3, l3;
    split_bf(a.x, h0, l0);
    split_bf(a.y, h1, l1);
    split_bf(a.z, h2, l2);
    split_bf(a.w, h3, l3);
    size_t rb = (size_t)node * DD + tid * 2;
    *(uint2*)&g_aggS[rb] = make_uint2(pack_bf(h0, h1), pack_bf(h2, h3));
    *(uint2*)&g_aggS[rb + 256] = make_uint2(pack_bf(l0, l1), pack_bf(l2, l3));
}

// ============================================================
__global__ void k_copy_out(float* __restrict__ out) {
    size_t i = (size_t)blockIdx.x * 256 + threadIdx.x;
    ((float4*)out)[i] = ((const float4*)g_x)[i];
}
__global__ void k_mask(float* __restrict__ out, const int* __restrict__ tok, int n) {
    int i = blockIdx.x * 256 + threadIdx.x;
    if (i < n) out[i] = (i < BNODES && tok[i] == 0) ? 1.0f : 0.0f;
}

// ============================================================
extern "C" void kernel_launch(void* const* d_in, const int* in_sizes, int n_in,
                              void* d_out, int out_size) {
    const int*   tok    = (const int*)d_in[0];
    const float* coords = (const float*)d_in[1];
    const int*   ei     = (const int*)d_in[2];
    const float* emb    = (const float*)d_in[3];
    const float* ew1    = (const float*)d_in[4];
    const float* eb1    = (const float*)d_in[5];
    const float* ew2    = (const float*)d_in[6];
    const float* eb2    = (const float*)d_in[7];
    const float* nw1    = (const float*)d_in[8];
    const float* nb1    = (const float*)d_in[9];
    const float* nw2    = (const float*)d_in[10];
    const float* nb2    = (const float*)d_in[11];

    cudaFuncSetAttribute(k_gemm<0>, cudaFuncAttributeMaxDynamicSharedMemorySize, SMEM_GEMM);
    cudaFuncSetAttribute(k_gemm<1>, cudaFuncAttributeMaxDynamicSharedMemorySize, SMEM_GEMM);
    cudaFuncSetAttribute(k_gemm<2>, cudaFuncAttributeMaxDynamicSharedMemorySize, SMEM_GEMM);

    k_gather<<<BNODES, 128>>>(tok, emb);
    k_dist<<<EE / 256, 256>>>(ei, coords);

    // weight prep: transpose + bf16 hi/lo split (once per launch)
    k_wsplit<<<dim3(16, 16, NLAYER), dim3(32, 8)>>>(ew2, 0);
    k_wsplit<<<dim3(16, 16, NLAYER), dim3(32, 8)>>>(nw1, 4);
    k_wsplit<<<dim3(16, 16, NLAYER), dim3(32, 8)>>>(nw2, 8);

    k_tab1<<<dim3(NP / 128, 4, NLAYER), 256>>>(ew1, eb1);
    k_gemm<2><<<dim3(NP / 128, DD / 256, NLAYER), 256, SMEM_GEMM>>>(0, eb2);

    const int* col = ei + EE;
    for (int l = 0; l < NLAYER; l++) {
        k_agg<<<BNODES, 128>>>(col, l);
        k_gemm<0><<<dim3(BNODES / 128, DD / 256), 256, SMEM_GEMM>>>(4 + l, nb1 + l * DD);
        k_gemm<1><<<dim3(BNODES / 128, DD / 256), 256, SMEM_GEMM>>>(8 + l, nb2 + l * DD);
    }

    k_copy_out<<<(BNODES * DD) / (256 * 4), 256>>>((float*)d_out);
    int extra = out_size - BNODES * DD;
    if (extra > 0)
        k_mask<<<(extra + 255) / 256, 256>>>((float*)d_out + BNODES * DD, tok, extra);
}

// round 12
// speedup vs baseline: 1.7834x; 1.0181x over previous
#include <cuda_runtime.h>
#include <cuda_bf16.h>
#include <cuda_fp16.h>
#include <cstdint>

// ----- problem constants -----
#define BNODES 8192
#define EE     262144
#define DD     512
#define NRBF   128
#define NLAYER 4

// ----- distance->ef lookup table -----
#define NP    2048
#define DMAXF 10.4f
#define HSTEP (DMAXF / (float)(NP - 1))
#define INVH  ((float)(NP - 1) / DMAXF)

// ----- device scratch -----
// split format: per row, u32[0..255] = bf16 hi pairs, u32[256..511] = lo pairs
__device__ float    g_x[BNODES * DD];             // fp32 node features (output path)
__device__ __half   g_xh[BNODES * DD];            // fp16 shadow of x (k_agg input)
__device__ float    g_dist[EE];
__device__ __half   g_tabH[NLAYER * NP * DD];     // fp16 ef tables (k_agg input)
__device__ uint32_t g_thS[NLAYER * NP * DD];      // split hidden tables
__device__ uint32_t g_aggS[BNODES * DD];          // split agg
__device__ uint32_t g_tS[BNODES * DD];            // split node hidden
__device__ uint32_t g_wS[12 * DD * DD];           // split transposed weights

__device__ __forceinline__ float silu_f(float v) { return v / (1.0f + __expf(-v)); }

__device__ __forceinline__ void cp16(void* dst, const void* src) {
    uint32_t d = (uint32_t)__cvta_generic_to_shared(dst);
    asm volatile("cp.async.cg.shared.global [%0], [%1], 16;" :: "r"(d), "l"(src));
}
__device__ __forceinline__ void cp_commit() { asm volatile("cp.async.commit_group;"); }
__device__ __forceinline__ void cp_wait0() { asm volatile("cp.async.wait_group 0;" ::: "memory"); }
__device__ __forceinline__ void cp_wait1() { asm volatile("cp.async.wait_group 1;" ::: "memory"); }

__device__ __forceinline__ void split_bf(float x, __nv_bfloat16& h, __nv_bfloat16& l) {
    h = __float2bfloat16_rn(x);
    l = __float2bfloat16_rn(x - __bfloat162float(h));
}
__device__ __forceinline__ uint32_t pack_bf(__nv_bfloat16 a, __nv_bfloat16 b) {
    __nv_bfloat162 p;
    p.x = a; p.y = b;
    return *(uint32_t*)&p;
}
__device__ __forceinline__ void split8(const float* f, uint4& H, uint4& L) {
    __nv_bfloat16 h[8], l[8];
#pragma unroll
    for (int j = 0; j < 8; j++) split_bf(f[j], h[j], l[j]);
    H = make_uint4(pack_bf(h[0], h[1]), pack_bf(h[2], h[3]),
                   pack_bf(h[4], h[5]), pack_bf(h[6], h[7]));
    L = make_uint4(pack_bf(l[0], l[1]), pack_bf(l[2], l[3]),
                   pack_bf(l[4], l[5]), pack_bf(l[6], l[7]));
}

__device__ __forceinline__ void mma_bf16(float* c, const uint32_t* a, uint32_t b0, uint32_t b1) {
    asm volatile(
        "mma.sync.aligned.m16n8k16.row.col.f32.bf16.bf16.f32 "
        "{%0,%1,%2,%3}, {%4,%5,%6,%7}, {%8,%9}, {%0,%1,%2,%3};"
        : "+f"(c[0]), "+f"(c[1]), "+f"(c[2]), "+f"(c[3])
        : "r"(a[0]), "r"(a[1]), "r"(a[2]), "r"(a[3]), "r"(b0), "r"(b1));
}
__device__ __forceinline__ void ldsm4(uint32_t* r, uint32_t addr) {
    asm volatile("ldmatrix.sync.aligned.m8n8.x4.shared.b16 {%0,%1,%2,%3}, [%4];"
                 : "=r"(r[0]), "=r"(r[1]), "=r"(r[2]), "=r"(r[3]) : "r"(addr));
}

// ============================================================
__global__ void k_gather(const int* __restrict__ tok, const float* __restrict__ emb) {
    int i = blockIdx.x;
    int t = tok[i];
    float4 v = ((const float4*)(emb + (size_t)t * DD))[threadIdx.x];
    ((float4*)(g_x + (size_t)i * DD))[threadIdx.x] = v;
    __half2 h01 = __floats2half2_rn(v.x, v.y);
    __half2 h23 = __floats2half2_rn(v.z, v.w);
    __half2* xh = (__half2*)(g_xh + (size_t)i * DD);
    xh[threadIdx.x * 2] = h01;
    xh[threadIdx.x * 2 + 1] = h23;
}

__global__ void k_dist(const int* __restrict__ ei, const float* __restrict__ coords) {
    int e = blockIdx.x * 256 + threadIdx.x;
    int r = ei[e], c = ei[EE + e];
    float dx = coords[r * 3 + 0] - coords[c * 3 + 0];
    float dy = coords[r * 3 + 1] - coords[c * 3 + 1];
    float dz = coords[r * 3 + 2] - coords[c * 3 + 2];
    g_dist[e] = sqrtf(dx * dx + dy * dy + dz * dz);
}

// ============================================================
// Weight prep: transpose + split.
// ============================================================
__global__ void k_wsplit(const float* __restrict__ Wb, int matBase) {
    __shared__ float ts[32][33];
    int k0 = blockIdx.x * 32, n0 = blockIdx.y * 32, l = blockIdx.z;
    const float* in = Wb + (size_t)l * DD * DD;
    uint32_t* out = g_wS + (size_t)(matBase + l) * DD * DD;
    int tx = threadIdx.x, ty = threadIdx.y;
#pragma unroll
    for (int i = 0; i < 4; i++)
        ts[ty + i * 8][tx] = in[(size_t)(k0 + ty + i * 8) * DD + n0 + tx];
    __syncthreads();
    int w_n = ty * 4 + (tx >> 3);
    int kp8 = tx & 7;
#pragma unroll
    for (int i = 0; i < 2; i++) {
        int kpl = kp8 * 2 + i;
        int kl = kpl * 2;
        __nv_bfloat16 h0, l0, h1, l1;
        split_bf(ts[kl][w_n], h0, l0);
        split_bf(ts[kl + 1][w_n], h1, l1);
        size_t base = (size_t)(n0 + w_n) * DD + (k0 >> 1) + kpl;
        out[base] = pack_bf(h0, h1);
        out[base + 256] = pack_bf(l0, l1);
    }
}

// ============================================================
// scalar FFMA GEMM bits (k_tab1 only)
// ============================================================
__device__ __forceinline__ void mma_tile(const float (*As)[132], const float (*Bs)[128],
                                         int tx, int ty, float acc[8][8]) {
#pragma unroll
    for (int k = 0; k < 16; k++) {
        float4 a0 = *(const float4*)&As[k][ty * 8];
        float4 a1 = *(const float4*)&As[k][ty * 8 + 4];
        float4 b0 = *(const float4*)&Bs[k][tx * 8];
        float4 b1 = *(const float4*)&Bs[k][tx * 8 + 4];
        float av[8] = {a0.x, a0.y, a0.z, a0.w, a1.x, a1.y, a1.z, a1.w};
        float bv[8] = {b0.x, b0.y, b0.z, b0.w, b1.x, b1.y, b1.z, b1.w};
#pragma unroll
        for (int i = 0; i < 8; i++)
#pragma unroll
            for (int j = 0; j < 8; j++)
                acc[i][j] = fmaf(av[i], bv[j], acc[i][j]);
    }
}
__device__ __forceinline__ void cpB(float (*Bs)[128], const float* __restrict__ W,
                                    int n0, int kc, int tid) {
#pragma unroll
    for (int i = 0; i < 2; i++) {
        int q = i * 256 + tid;
        int r = q >> 5, c4 = q & 31;
        cp16(&Bs[r][c4 * 4], &W[(size_t)(kc * 16 + r) * DD + n0 + c4 * 4]);
    }
}

// ============================================================
// Table pass 1: g_thS[z] = split(silu(rbf(grid) @ W1[z] + b1[z]))
// ============================================================
__global__ void __launch_bounds__(256, 2) k_tab1(const float* __restrict__ Wb,
                                                 const float* __restrict__ bb_) {
    __shared__ float As[16][132];
    __shared__ float Bs[2][16][128];
    int tid = threadIdx.x, tx = tid & 15, ty = tid >> 4;
    int m0 = blockIdx.x * 128, n0 = blockIdx.y * 128, l = blockIdx.z;
    const float* W = Wb + (size_t)l * NRBF * DD;
    const float* b = bb_ + (size_t)l * DD;
    const float step = 6.0f / 127.0f;

    cpB(Bs[0], W, n0, 0, tid);
    cp_commit();

    float acc[8][8] = {};
#pragma unroll 1
    for (int kc = 0; kc < NRBF / 16; kc++) {
        int buf = kc & 1;
#pragma unroll
        for (int i = 0; i < 8; i++) {
            int idx = i * 256 + tid;
            int m = idx & 127, k = idx >> 7;
            float d = (float)(m0 + m) * HSTEP;
            float c = (float)(kc * 16 + k) * step;
            float dd = d - c;
            As[k][m] = __expf(-10.0f * dd * dd);
        }
        if (kc + 1 < NRBF / 16) { cpB(Bs[buf ^ 1], W, n0, kc + 1, tid); cp_commit(); }
        cp_wait0();
        __syncthreads();
        mma_tile(As, Bs[buf], tx, ty, acc);
        __syncthreads();
    }

    float bb[8];
#pragma unroll
    for (int j = 0; j < 8; j++) bb[j] = b[n0 + tx * 8 + j];
    uint32_t* out = g_thS + (size_t)l * NP * DD;
#pragma unroll
    for (int i = 0; i < 8; i++) {
        float o[8];
#pragma unroll
        for (int j = 0; j < 8; j++) o[j] = silu_f(acc[i][j] + bb[j]);
        uint4 H, L;
        split8(o, H, L);
        size_t rb = (size_t)(m0 + ty * 8 + i) * DD + tx * 4 + (n0 >> 1);
        *(uint4*)&out[rb] = H;
        *(uint4*)&out[rb + 256] = L;
    }
}

// ============================================================
// HMMA bf16x3 GEMM, pre-split inputs, cp.async staging, 3 stages.
// Tile 128x256, 8 warps (2m x 4n), warp tile 64x64, BK=32.
// EPI 0: g_tS = split(silu(.)); 1: g_x += . (+ g_xh); 2: g_tabH[z] = half(.)
// ============================================================
#define NSTAGE 3
#define STGSZ  49152
#define SMEM_GEMM (NSTAGE * STGSZ + 1024)

template <int EPI>
__global__ void __launch_bounds__(256) k_gemm(int mat, const float* __restrict__ bb_) {
    extern __shared__ uint32_t smem_u[];
    char* smem_c = (char*)smem_u;
    float* sbias = (float*)(smem_c + NSTAGE * STGSZ);
    const uint32_t sbase = (uint32_t)__cvta_generic_to_shared(smem_u);

    int tid = threadIdx.x, lane = tid & 31, wid = tid >> 5;
    int m0 = blockIdx.x * 128, n0 = blockIdx.y * 256, l = blockIdx.z;
    const uint32_t* Aq = (EPI == 0) ? g_aggS : (EPI == 1) ? g_tS
                                             : (g_thS + (size_t)l * NP * DD);
    const uint32_t* Wq = g_wS + (size_t)(mat + l) * DD * DD;
    const float* b = (EPI == 2) ? bb_ + (size_t)l * DD : bb_;

    sbias[tid] = b[n0 + tid];

    const int srow = tid >> 1, cbase = (tid & 1) * 4;
    const uint32_t* aRow = Aq + (size_t)(m0 + srow) * DD + (cbase ? 256 : 0);
    uint32_t dstA[4];
#pragma unroll
    for (int j = 0; j < 4; j++)
        dstA[j] = srow * 128 + (((cbase + j) ^ (srow & 7)) << 4);
    const int brow = tid;
    const uint32_t* bRow = Wq + (size_t)(n0 + brow) * DD;
    uint32_t dstB[8];
#pragma unroll
    for (int c = 0; c < 8; c++)
        dstB[c] = brow * 128 + ((c ^ (brow & 7)) << 4);

    auto issue = [&](int kc, int buf) {
        char* Ab = smem_c + buf * STGSZ;
        char* Bb = Ab + 16384;
        const uint32_t* as = aRow + kc * 16;
#pragma unroll
        for (int j = 0; j < 4; j++) cp16(Ab + dstA[j], as + j * 4);
#pragma unroll
        for (int c = 0; c < 8; c++)
            cp16(Bb + dstB[c], bRow + (c < 4 ? kc * 16 + c * 4 : 256 + kc * 16 + (c - 4) * 4));
        cp_commit();
    };

    const int g = lane >> 2, tig = lane & 3;
    const int wm = (wid >> 2) * 64, wn = (wid & 3) * 64;
    const int lq = lane >> 3, lr = lane & 7;
    const int rowA = (lq & 1) * 8 + lr, kqA = lq >> 1;
    const int rowB = (lq >> 1) * 8 + lr, kqB = lq & 1;
    const uint32_t aBase = sbase + (wm + rowA) * 128;
    const uint32_t bBase = sbase + 16384 + (wn + rowB) * 128;

    issue(0, 0);
    issue(1, 1);

    float acc[4][8][4] = {};
    const int NCH = DD / 32;
#pragma unroll 1
    for (int kc = 0; kc < NCH; kc++) {
        int buf = kc % NSTAGE;
        if (kc + 2 < NCH) cp_wait1(); else cp_wait0();
        __syncthreads();
#pragma unroll
        for (int ks = 0; ks < 2; ks++) {
            uint32_t aH[4][4], aL[4][4], bH[4][4], bL[4][4];
            uint32_t chA = (uint32_t)(((ks * 2 + kqA) ^ (rowA & 7)) << 4);
            uint32_t chB = (uint32_t)(((ks * 2 + kqB) ^ (rowB & 7)) << 4);
#pragma unroll
            for (int mt = 0; mt < 4; mt++) {
                uint32_t ad = aBase + buf * STGSZ + mt * 2048 + chA;
                ldsm4(aH[mt], ad);
                ldsm4(aL[mt], ad ^ 64);
            }
#pragma unroll
            for (int np = 0; np < 4; np++) {
                uint32_t bd = bBase + buf * STGSZ + np * 2048 + chB;
                ldsm4(bH[np], bd);
                ldsm4(bL[np], bd ^ 64);
            }
#pragma unroll
            for (int mt = 0; mt < 4; mt++)
#pragma unroll
                for (int nt = 0; nt < 8; nt++) {
                    uint32_t bh0 = bH[nt >> 1][(nt & 1) * 2], bh1 = bH[nt >> 1][(nt & 1) * 2 + 1];
                    uint32_t bl0 = bL[nt >> 1][(nt & 1) * 2], bl1 = bL[nt >> 1][(nt & 1) * 2 + 1];
                    mma_bf16(acc[mt][nt], aH[mt], bh0, bh1);
                    mma_bf16(acc[mt][nt], aH[mt], bl0, bl1);
                    mma_bf16(acc[mt][nt], aL[mt], bh0, bh1);
                }
        }
        if (kc + 2 < NCH) issue(kc + 2, (kc + 2) % NSTAGE);
    }

    // ---- epilogue ----
#pragma unroll
    for (int mt = 0; mt < 4; mt++) {
#pragma unroll
        for (int nt = 0; nt < 8; nt++) {
            int row = m0 + wm + mt * 16 + g;
            int cl = wn + nt * 8 + tig * 2;
            float b0 = sbias[cl], b1 = sbias[cl + 1];
            float* c = acc[mt][nt];
#pragma unroll
            for (int half = 0; half < 2; half++) {
                int r = row + half * 8;
                float v0 = c[half * 2 + 0] + b0, v1 = c[half * 2 + 1] + b1;
                size_t off = (size_t)r * DD + n0 + cl;
                if (EPI == 0) {
                    __nv_bfloat16 h0, l0, h1, l1;
                    float s0 = silu_f(v0), s1 = silu_f(v1);
                    split_bf(s0, h0, l0);
                    split_bf(s1, h1, l1);
                    size_t rb = (size_t)r * DD + ((n0 + cl) >> 1);
                    g_tS[rb] = pack_bf(h0, h1);
                    g_tS[rb + 256] = pack_bf(l0, l1);
                } else if (EPI == 1) {
                    float2 x = *(float2*)(g_x + off);
                    x.x += v0; x.y += v1;
                    *(float2*)(g_x + off) = x;
                    *(__half2*)(g_xh + off) = __floats2half2_rn(x.x, x.y);
                } else {
                    *(__half2*)(g_tabH + (size_t)l * NP * DD + off) =
                        __floats2half2_rn(v0, v1);
                }
            }
        }
    }
}

// ============================================================
// Edge pass (fp16 inputs, fp32 accumulate):
// aggS[node] = split( sum_{32} lerp(tabH_l, d_e) * xh[col_e] )
// ============================================================
__global__ void __launch_bounds__(128) k_agg(const int* __restrict__ col, int l) {
    __shared__ int   scol[32];
    __shared__ int   sidx[32];
    __shared__ float sw[32];
    const __half* tab = g_tabH + (size_t)l * NP * DD;
    int node = blockIdx.x, tid = threadIdx.x;
    if (tid < 32) {
        int e = node * 32 + tid;
        scol[tid] = col[e];
        float f = g_dist[e] * INVH;
        int i = (int)f;
        if (i > NP - 2) i = NP - 2;
        sidx[tid] = i;
        sw[tid] = f - (float)i;
    }
    __syncthreads();

    int dim = tid * 4;
    float4 a = make_float4(0.f, 0.f, 0.f, 0.f);
#pragma unroll 8
    for (int e = 0; e < 32; e++) {
        size_t tbase = (size_t)sidx[e] * DD + dim;
        __half2 t0a = *(const __half2*)&tab[tbase];
        __half2 t0b = *(const __half2*)&tab[tbase + 2];
        __half2 t1a = *(const __half2*)&tab[tbase + DD];
        __half2 t1b = *(const __half2*)&tab[tbase + DD + 2];
        size_t xb = (size_t)scol[e] * DD + dim;
        __half2 xa = *(const __half2*)&g_xh[xb];
        __half2 xbh = *(const __half2*)&g_xh[xb + 2];
        float2 f0a = __half22float2(t0a), f0b = __half22float2(t0b);
        float2 f1a = __half22float2(t1a), f1b = __half22float2(t1b);
        float2 fxa = __half22float2(xa), fxb = __half22float2(xbh);
        float w = sw[e];
        a.x = fmaf(fmaf(w, f1a.x - f0a.x, f0a.x), fxa.x, a.x);
        a.y = fmaf(fmaf(w, f1a.y - f0a.y, f0a.y), fxa.y, a.y);
        a.z = fmaf(fmaf(w, f1b.x - f0b.x, f0b.x), fxb.x, a.z);
        a.w = fmaf(fmaf(w, f1b.y - f0b.y, f0b.y), fxb.y, a.w);
    }
    __nv_bfloat16 h0, l0, h1, l1, h2, l2, h3, l3;
    split_bf(a.x, h0, l0);
    split_bf(a.y, h1, l1);
    split_bf(a.z, h2, l2);
    split_bf(a.w, h3, l3);
    size_t rb = (size_t)node * DD + tid * 2;
    *(uint2*)&g_aggS[rb] = make_uint2(pack_bf(h0, h1), pack_bf(h2, h3));
    *(uint2*)&g_aggS[rb + 256] = make_uint2(pack_bf(l0, l1), pack_bf(l2, l3));
}

// ============================================================
__global__ void k_copy_out(float* __restrict__ out) {
    size_t i = (size_t)blockIdx.x * 256 + threadIdx.x;
    ((float4*)out)[i] = ((const float4*)g_x)[i];
}
__global__ void k_mask(float* __restrict__ out, const int* __restrict__ tok, int n) {
    int i = blockIdx.x * 256 + threadIdx.x;
    if (i < n) out[i] = (i < BNODES && tok[i] == 0) ? 1.0f : 0.0f;
}

// ============================================================
extern "C" void kernel_launch(void* const* d_in, const int* in_sizes, int n_in,
                              void* d_out, int out_size) {
    const int*   tok    = (const int*)d_in[0];
    const float* coords = (const float*)d_in[1];
    const int*   ei     = (const int*)d_in[2];
    const float* emb    = (const float*)d_in[3];
    const float* ew1    = (const float*)d_in[4];
    const float* eb1    = (const float*)d_in[5];
    const float* ew2    = (const float*)d_in[6];
    const float* eb2    = (const float*)d_in[7];
    const float* nw1    = (const float*)d_in[8];
    const float* nb1    = (const float*)d_in[9];
    const float* nw2    = (const float*)d_in[10];
    const float* nb2    = (const float*)d_in[11];

    cudaFuncSetAttribute(k_gemm<0>, cudaFuncAttributeMaxDynamicSharedMemorySize, SMEM_GEMM);
    cudaFuncSetAttribute(k_gemm<1>, cudaFuncAttributeMaxDynamicSharedMemorySize, SMEM_GEMM);
    cudaFuncSetAttribute(k_gemm<2>, cudaFuncAttributeMaxDynamicSharedMemorySize, SMEM_GEMM);

    k_gather<<<BNODES, 128>>>(tok, emb);
    k_dist<<<EE / 256, 256>>>(ei, coords);

    k_wsplit<<<dim3(16, 16, NLAYER), dim3(32, 8)>>>(ew2, 0);
    k_wsplit<<<dim3(16, 16, NLAYER), dim3(32, 8)>>>(nw1, 4);
    k_wsplit<<<dim3(16, 16, NLAYER), dim3(32, 8)>>>(nw2, 8);

    k_tab1<<<dim3(NP / 128, 4, NLAYER), 256>>>(ew1, eb1);
    k_gemm<2><<<dim3(NP / 128, DD / 256, NLAYER), 256, SMEM_GEMM>>>(0, eb2);

    const int* col = ei + EE;
    for (int l = 0; l < NLAYER; l++) {
        k_agg<<<BNODES, 128>>>(col, l);
        k_gemm<0><<<dim3(BNODES / 128, DD / 256), 256, SMEM_GEMM>>>(4 + l, nb1 + l * DD);
        k_gemm<1><<<dim3(BNODES / 128, DD / 256), 256, SMEM_GEMM>>>(8 + l, nb2 + l * DD);
    }

    k_copy_out<<<(BNODES * DD) / (256 * 4), 256>>>((float*)d_out);
    int extra = out_size - BNODES * DD;
    if (extra > 0)
        k_mask<<<(extra + 255) / 256, 256>>>((float*)d_out + BNODES * DD, tok, extra);
}

// round 13
// speedup vs baseline: 1.8711x; 1.0491x over previous
#include <cuda_runtime.h>
#include <cuda_bf16.h>
#include <cuda_fp16.h>
#include <cstdint>

// ----- problem constants -----
#define BNODES 8192
#define EE     262144
#define DD     512
#define NRBF   128
#define NLAYER 4

// ----- distance->ef lookup table -----
#define NP    2048
#define DMAXF 10.4f
#define HSTEP (DMAXF / (float)(NP - 1))
#define INVH  ((float)(NP - 1) / DMAXF)

// ----- device scratch -----
// split format: per row, u32[0..255] = bf16 hi pairs, u32[256..511] = lo pairs
__device__ float    g_x[BNODES * DD];             // fp32 node features (output path)
__device__ __half   g_xh[BNODES * DD];            // fp16 shadow of x (k_agg input)
__device__ float    g_dist[EE];
__device__ __half   g_tabH[NLAYER * NP * DD];     // fp16 ef tables (k_agg input)
__device__ uint32_t g_thS[NLAYER * NP * DD];      // split hidden tables
__device__ uint32_t g_aggS[BNODES * DD];          // split agg
__device__ uint32_t g_tS[BNODES * DD];            // split node hidden
__device__ uint32_t g_wS[12 * DD * DD];           // split transposed weights

__device__ __forceinline__ float silu_f(float v) { return v / (1.0f + __expf(-v)); }

__device__ __forceinline__ void cp16(void* dst, const void* src) {
    uint32_t d = (uint32_t)__cvta_generic_to_shared(dst);
    asm volatile("cp.async.cg.shared.global [%0], [%1], 16;" :: "r"(d), "l"(src));
}
__device__ __forceinline__ void cp_commit() { asm volatile("cp.async.commit_group;"); }
__device__ __forceinline__ void cp_wait0() { asm volatile("cp.async.wait_group 0;" ::: "memory"); }
__device__ __forceinline__ void cp_wait1() { asm volatile("cp.async.wait_group 1;" ::: "memory"); }

__device__ __forceinline__ void split_bf(float x, __nv_bfloat16& h, __nv_bfloat16& l) {
    h = __float2bfloat16_rn(x);
    l = __float2bfloat16_rn(x - __bfloat162float(h));
}
__device__ __forceinline__ uint32_t pack_bf(__nv_bfloat16 a, __nv_bfloat16 b) {
    __nv_bfloat162 p;
    p.x = a; p.y = b;
    return *(uint32_t*)&p;
}
__device__ __forceinline__ void split8(const float* f, uint4& H, uint4& L) {
    __nv_bfloat16 h[8], l[8];
#pragma unroll
    for (int j = 0; j < 8; j++) split_bf(f[j], h[j], l[j]);
    H = make_uint4(pack_bf(h[0], h[1]), pack_bf(h[2], h[3]),
                   pack_bf(h[4], h[5]), pack_bf(h[6], h[7]));
    L = make_uint4(pack_bf(l[0], l[1]), pack_bf(l[2], l[3]),
                   pack_bf(l[4], l[5]), pack_bf(l[6], l[7]));
}

__device__ __forceinline__ void mma_bf16(float* c, const uint32_t* a, uint32_t b0, uint32_t b1) {
    asm volatile(
        "mma.sync.aligned.m16n8k16.row.col.f32.bf16.bf16.f32 "
        "{%0,%1,%2,%3}, {%4,%5,%6,%7}, {%8,%9}, {%0,%1,%2,%3};"
        : "+f"(c[0]), "+f"(c[1]), "+f"(c[2]), "+f"(c[3])
        : "r"(a[0]), "r"(a[1]), "r"(a[2]), "r"(a[3]), "r"(b0), "r"(b1));
}
__device__ __forceinline__ void ldsm4(uint32_t* r, uint32_t addr) {
    asm volatile("ldmatrix.sync.aligned.m8n8.x4.shared.b16 {%0,%1,%2,%3}, [%4];"
                 : "=r"(r[0]), "=r"(r[1]), "=r"(r[2]), "=r"(r[3]) : "r"(addr));
}

// ============================================================
__global__ void k_gather(const int* __restrict__ tok, const float* __restrict__ emb) {
    int i = blockIdx.x;
    int t = tok[i];
    float4 v = ((const float4*)(emb + (size_t)t * DD))[threadIdx.x];
    ((float4*)(g_x + (size_t)i * DD))[threadIdx.x] = v;
    __half2 h01 = __floats2half2_rn(v.x, v.y);
    __half2 h23 = __floats2half2_rn(v.z, v.w);
    __half2* xh = (__half2*)(g_xh + (size_t)i * DD);
    xh[threadIdx.x * 2] = h01;
    xh[threadIdx.x * 2 + 1] = h23;
}

__global__ void k_dist(const int* __restrict__ ei, const float* __restrict__ coords) {
    int e = blockIdx.x * 256 + threadIdx.x;
    int r = ei[e], c = ei[EE + e];
    float dx = coords[r * 3 + 0] - coords[c * 3 + 0];
    float dy = coords[r * 3 + 1] - coords[c * 3 + 1];
    float dz = coords[r * 3 + 2] - coords[c * 3 + 2];
    g_dist[e] = sqrtf(dx * dx + dy * dy + dz * dz);
}

// ============================================================
// Weight prep: transpose + split.
// ============================================================
__global__ void k_wsplit(const float* __restrict__ Wb, int matBase) {
    __shared__ float ts[32][33];
    int k0 = blockIdx.x * 32, n0 = blockIdx.y * 32, l = blockIdx.z;
    const float* in = Wb + (size_t)l * DD * DD;
    uint32_t* out = g_wS + (size_t)(matBase + l) * DD * DD;
    int tx = threadIdx.x, ty = threadIdx.y;
#pragma unroll
    for (int i = 0; i < 4; i++)
        ts[ty + i * 8][tx] = in[(size_t)(k0 + ty + i * 8) * DD + n0 + tx];
    __syncthreads();
    int w_n = ty * 4 + (tx >> 3);
    int kp8 = tx & 7;
#pragma unroll
    for (int i = 0; i < 2; i++) {
        int kpl = kp8 * 2 + i;
        int kl = kpl * 2;
        __nv_bfloat16 h0, l0, h1, l1;
        split_bf(ts[kl][w_n], h0, l0);
        split_bf(ts[kl + 1][w_n], h1, l1);
        size_t base = (size_t)(n0 + w_n) * DD + (k0 >> 1) + kpl;
        out[base] = pack_bf(h0, h1);
        out[base + 256] = pack_bf(l0, l1);
    }
}

// ============================================================
// scalar FFMA GEMM bits (k_tab1 only)
// ============================================================
__device__ __forceinline__ void mma_tile(const float (*As)[132], const float (*Bs)[128],
                                         int tx, int ty, float acc[8][8]) {
#pragma unroll
    for (int k = 0; k < 16; k++) {
        float4 a0 = *(const float4*)&As[k][ty * 8];
        float4 a1 = *(const float4*)&As[k][ty * 8 + 4];
        float4 b0 = *(const float4*)&Bs[k][tx * 8];
        float4 b1 = *(const float4*)&Bs[k][tx * 8 + 4];
        float av[8] = {a0.x, a0.y, a0.z, a0.w, a1.x, a1.y, a1.z, a1.w};
        float bv[8] = {b0.x, b0.y, b0.z, b0.w, b1.x, b1.y, b1.z, b1.w};
#pragma unroll
        for (int i = 0; i < 8; i++)
#pragma unroll
            for (int j = 0; j < 8; j++)
                acc[i][j] = fmaf(av[i], bv[j], acc[i][j]);
    }
}
__device__ __forceinline__ void cpB(float (*Bs)[128], const float* __restrict__ W,
                                    int n0, int kc, int tid) {
#pragma unroll
    for (int i = 0; i < 2; i++) {
        int q = i * 256 + tid;
        int r = q >> 5, c4 = q & 31;
        cp16(&Bs[r][c4 * 4], &W[(size_t)(kc * 16 + r) * DD + n0 + c4 * 4]);
    }
}

// ============================================================
// Table pass 1: g_thS[z] = split(silu(rbf(grid) @ W1[z] + b1[z]))
// ============================================================
__global__ void __launch_bounds__(256, 2) k_tab1(const float* __restrict__ Wb,
                                                 const float* __restrict__ bb_) {
    __shared__ float As[16][132];
    __shared__ float Bs[2][16][128];
    int tid = threadIdx.x, tx = tid & 15, ty = tid >> 4;
    int m0 = blockIdx.x * 128, n0 = blockIdx.y * 128, l = blockIdx.z;
    const float* W = Wb + (size_t)l * NRBF * DD;
    const float* b = bb_ + (size_t)l * DD;
    const float step = 6.0f / 127.0f;

    cpB(Bs[0], W, n0, 0, tid);
    cp_commit();

    float acc[8][8] = {};
#pragma unroll 1
    for (int kc = 0; kc < NRBF / 16; kc++) {
        int buf = kc & 1;
#pragma unroll
        for (int i = 0; i < 8; i++) {
            int idx = i * 256 + tid;
            int m = idx & 127, k = idx >> 7;
            float d = (float)(m0 + m) * HSTEP;
            float c = (float)(kc * 16 + k) * step;
            float dd = d - c;
            As[k][m] = __expf(-10.0f * dd * dd);
        }
        if (kc + 1 < NRBF / 16) { cpB(Bs[buf ^ 1], W, n0, kc + 1, tid); cp_commit(); }
        cp_wait0();
        __syncthreads();
        mma_tile(As, Bs[buf], tx, ty, acc);
        __syncthreads();
    }

    float bb[8];
#pragma unroll
    for (int j = 0; j < 8; j++) bb[j] = b[n0 + tx * 8 + j];
    uint32_t* out = g_thS + (size_t)l * NP * DD;
#pragma unroll
    for (int i = 0; i < 8; i++) {
        float o[8];
#pragma unroll
        for (int j = 0; j < 8; j++) o[j] = silu_f(acc[i][j] + bb[j]);
        uint4 H, L;
        split8(o, H, L);
        size_t rb = (size_t)(m0 + ty * 8 + i) * DD + tx * 4 + (n0 >> 1);
        *(uint4*)&out[rb] = H;
        *(uint4*)&out[rb + 256] = L;
    }
}

// ============================================================
// HMMA bf16x3 GEMM, pre-split inputs, cp.async staging, 3 stages.
// Tile 128x256, 8 warps (2m x 4n), warp tile 64x64, BK=32.
// EPI 0: g_tS = split(silu(.)); 1: g_x += . (+ g_xh); 2: g_tabH[z] = half(.)
// ============================================================
#define NSTAGE 3
#define STGSZ  49152
#define SMEM_GEMM (NSTAGE * STGSZ + 1024)

template <int EPI>
__global__ void __launch_bounds__(256) k_gemm(int mat, const float* __restrict__ bb_) {
    extern __shared__ uint32_t smem_u[];
    char* smem_c = (char*)smem_u;
    float* sbias = (float*)(smem_c + NSTAGE * STGSZ);
    const uint32_t sbase = (uint32_t)__cvta_generic_to_shared(smem_u);

    int tid = threadIdx.x, lane = tid & 31, wid = tid >> 5;
    int m0 = blockIdx.x * 128, n0 = blockIdx.y * 256, l = blockIdx.z;
    const uint32_t* Aq = (EPI == 0) ? g_aggS : (EPI == 1) ? g_tS
                                             : (g_thS + (size_t)l * NP * DD);
    const uint32_t* Wq = g_wS + (size_t)(mat + l) * DD * DD;
    const float* b = (EPI == 2) ? bb_ + (size_t)l * DD : bb_;

    sbias[tid] = b[n0 + tid];

    const int srow = tid >> 1, cbase = (tid & 1) * 4;
    const uint32_t* aRow = Aq + (size_t)(m0 + srow) * DD + (cbase ? 256 : 0);
    uint32_t dstA[4];
#pragma unroll
    for (int j = 0; j < 4; j++)
        dstA[j] = srow * 128 + (((cbase + j) ^ (srow & 7)) << 4);
    const int brow = tid;
    const uint32_t* bRow = Wq + (size_t)(n0 + brow) * DD;
    uint32_t dstB[8];
#pragma unroll
    for (int c = 0; c < 8; c++)
        dstB[c] = brow * 128 + ((c ^ (brow & 7)) << 4);

    auto issue = [&](int kc, int buf) {
        char* Ab = smem_c + buf * STGSZ;
        char* Bb = Ab + 16384;
        const uint32_t* as = aRow + kc * 16;
#pragma unroll
        for (int j = 0; j < 4; j++) cp16(Ab + dstA[j], as + j * 4);
#pragma unroll
        for (int c = 0; c < 8; c++)
            cp16(Bb + dstB[c], bRow + (c < 4 ? kc * 16 + c * 4 : 256 + kc * 16 + (c - 4) * 4));
        cp_commit();
    };

    const int g = lane >> 2, tig = lane & 3;
    const int wm = (wid >> 2) * 64, wn = (wid & 3) * 64;
    const int lq = lane >> 3, lr = lane & 7;
    const int rowA = (lq & 1) * 8 + lr, kqA = lq >> 1;
    const int rowB = (lq >> 1) * 8 + lr, kqB = lq & 1;
    const uint32_t aBase = sbase + (wm + rowA) * 128;
    const uint32_t bBase = sbase + 16384 + (wn + rowB) * 128;

    issue(0, 0);
    issue(1, 1);

    float acc[4][8][4] = {};
    const int NCH = DD / 32;
#pragma unroll 1
    for (int kc = 0; kc < NCH; kc++) {
        int buf = kc % NSTAGE;
        if (kc + 2 < NCH) cp_wait1(); else cp_wait0();
        __syncthreads();
#pragma unroll
        for (int ks = 0; ks < 2; ks++) {
            uint32_t aH[4][4], aL[4][4], bH[4][4], bL[4][4];
            uint32_t chA = (uint32_t)(((ks * 2 + kqA) ^ (rowA & 7)) << 4);
            uint32_t chB = (uint32_t)(((ks * 2 + kqB) ^ (rowB & 7)) << 4);
#pragma unroll
            for (int mt = 0; mt < 4; mt++) {
                uint32_t ad = aBase + buf * STGSZ + mt * 2048 + chA;
                ldsm4(aH[mt], ad);
                ldsm4(aL[mt], ad ^ 64);
            }
#pragma unroll
            for (int np = 0; np < 4; np++) {
                uint32_t bd = bBase + buf * STGSZ + np * 2048 + chB;
                ldsm4(bH[np], bd);
                ldsm4(bL[np], bd ^ 64);
            }
#pragma unroll
            for (int mt = 0; mt < 4; mt++)
#pragma unroll
                for (int nt = 0; nt < 8; nt++) {
                    uint32_t bh0 = bH[nt >> 1][(nt & 1) * 2], bh1 = bH[nt >> 1][(nt & 1) * 2 + 1];
                    uint32_t bl0 = bL[nt >> 1][(nt & 1) * 2], bl1 = bL[nt >> 1][(nt & 1) * 2 + 1];
                    mma_bf16(acc[mt][nt], aH[mt], bh0, bh1);
                    mma_bf16(acc[mt][nt], aH[mt], bl0, bl1);
                    mma_bf16(acc[mt][nt], aL[mt], bh0, bh1);
                }
        }
        if (kc + 2 < NCH) issue(kc + 2, (kc + 2) % NSTAGE);
    }

    // ---- epilogue ----
#pragma unroll
    for (int mt = 0; mt < 4; mt++) {
#pragma unroll
        for (int nt = 0; nt < 8; nt++) {
            int row = m0 + wm + mt * 16 + g;
            int cl = wn + nt * 8 + tig * 2;
            float b0 = sbias[cl], b1 = sbias[cl + 1];
            float* c = acc[mt][nt];
#pragma unroll
            for (int half = 0; half < 2; half++) {
                int r = row + half * 8;
                float v0 = c[half * 2 + 0] + b0, v1 = c[half * 2 + 1] + b1;
                size_t off = (size_t)r * DD + n0 + cl;
                if (EPI == 0) {
                    __nv_bfloat16 h0, l0, h1, l1;
                    float s0 = silu_f(v0), s1 = silu_f(v1);
                    split_bf(s0, h0, l0);
                    split_bf(s1, h1, l1);
                    size_t rb = (size_t)r * DD + ((n0 + cl) >> 1);
                    g_tS[rb] = pack_bf(h0, h1);
                    g_tS[rb + 256] = pack_bf(l0, l1);
                } else if (EPI == 1) {
                    float2 x = *(float2*)(g_x + off);
                    x.x += v0; x.y += v1;
                    *(float2*)(g_x + off) = x;
                    *(__half2*)(g_xh + off) = __floats2half2_rn(x.x, x.y);
                } else {
                    *(__half2*)(g_tabH + (size_t)l * NP * DD + off) =
                        __floats2half2_rn(v0, v1);
                }
            }
        }
    }
}

// ============================================================
// Edge pass (fp16 inputs, LDG.128, fp32 accumulate):
// 256-thread blocks process 4 nodes; 64 threads (2 warps) per node;
// each thread covers 8 dims = one uint4 (16B) per row.
// aggS[node] = split( sum_{32} lerp(tabH_l, d_e) * xh[col_e] )
// ============================================================
__global__ void __launch_bounds__(256) k_agg(const int* __restrict__ col, int l) {
    __shared__ int   scol[4][32];
    __shared__ int   sidx[4][32];
    __shared__ float sw[4][32];
    const __half* tab = g_tabH + (size_t)l * NP * DD;
    int tid = threadIdx.x;
    int node0 = blockIdx.x * 4;
    if (tid < 128) {
        int sn = tid >> 5, se = tid & 31;
        int e = (node0 + sn) * 32 + se;
        scol[sn][se] = col[e];
        float f = g_dist[e] * INVH;
        int i = (int)f;
        if (i > NP - 2) i = NP - 2;
        sidx[sn][se] = i;
        sw[sn][se] = f - (float)i;
    }
    __syncthreads();

    int sn = tid >> 6;            // node within block (0..3)
    int t = tid & 63;             // thread within node
    int node = node0 + sn;
    int dim = t * 8;              // 8 fp16 dims per thread

    float a[8] = {};
#pragma unroll 8
    for (int e = 0; e < 32; e++) {
        size_t tbase = (size_t)sidx[sn][e] * DD + dim;
        uint4 T0 = *(const uint4*)&tab[tbase];
        uint4 T1 = *(const uint4*)&tab[tbase + DD];
        uint4 X = *(const uint4*)&g_xh[(size_t)scol[sn][e] * DD + dim];
        float w = sw[sn][e];
        const __half2* t0 = (const __half2*)&T0;
        const __half2* t1 = (const __half2*)&T1;
        const __half2* xv = (const __half2*)&X;
#pragma unroll
        for (int q = 0; q < 4; q++) {
            float2 f0 = __half22float2(t0[q]);
            float2 f1 = __half22float2(t1[q]);
            float2 fx = __half22float2(xv[q]);
            a[q * 2 + 0] = fmaf(fmaf(w, f1.x - f0.x, f0.x), fx.x, a[q * 2 + 0]);
            a[q * 2 + 1] = fmaf(fmaf(w, f1.y - f0.y, f0.y), fx.y, a[q * 2 + 1]);
        }
    }
    uint4 H, L;
    split8(a, H, L);
    size_t rb = (size_t)node * DD + t * 4;
    *(uint4*)&g_aggS[rb] = H;
    *(uint4*)&g_aggS[rb + 256] = L;
}

// ============================================================
__global__ void k_copy_out(float* __restrict__ out) {
    size_t i = (size_t)blockIdx.x * 256 + threadIdx.x;
    ((float4*)out)[i] = ((const float4*)g_x)[i];
}
__global__ void k_mask(float* __restrict__ out, const int* __restrict__ tok, int n) {
    int i = blockIdx.x * 256 + threadIdx.x;
    if (i < n) out[i] = (i < BNODES && tok[i] == 0) ? 1.0f : 0.0f;
}

// ============================================================
extern "C" void kernel_launch(void* const* d_in, const int* in_sizes, int n_in,
                              void* d_out, int out_size) {
    const int*   tok    = (const int*)d_in[0];
    const float* coords = (const float*)d_in[1];
    const int*   ei     = (const int*)d_in[2];
    const float* emb    = (const float*)d_in[3];
    const float* ew1    = (const float*)d_in[4];
    const float* eb1    = (const float*)d_in[5];
    const float* ew2    = (const float*)d_in[6];
    const float* eb2    = (const float*)d_in[7];
    const float* nw1    = (const float*)d_in[8];
    const float* nb1    = (const float*)d_in[9];
    const float* nw2    = (const float*)d_in[10];
    const float* nb2    = (const float*)d_in[11];

    cudaFuncSetAttribute(k_gemm<0>, cudaFuncAttributeMaxDynamicSharedMemorySize, SMEM_GEMM);
    cudaFuncSetAttribute(k_gemm<1>, cudaFuncAttributeMaxDynamicSharedMemorySize, SMEM_GEMM);
    cudaFuncSetAttribute(k_gemm<2>, cudaFuncAttributeMaxDynamicSharedMemorySize, SMEM_GEMM);

    k_gather<<<BNODES, 128>>>(tok, emb);
    k_dist<<<EE / 256, 256>>>(ei, coords);

    k_wsplit<<<dim3(16, 16, NLAYER), dim3(32, 8)>>>(ew2, 0);
    k_wsplit<<<dim3(16, 16, NLAYER), dim3(32, 8)>>>(nw1, 4);
    k_wsplit<<<dim3(16, 16, NLAYER), dim3(32, 8)>>>(nw2, 8);

    k_tab1<<<dim3(NP / 128, 4, NLAYER), 256>>>(ew1, eb1);
    k_gemm<2><<<dim3(NP / 128, DD / 256, NLAYER), 256, SMEM_GEMM>>>(0, eb2);

    const int* col = ei + EE;
    for (int l = 0; l < NLAYER; l++) {
        k_agg<<<BNODES / 4, 256>>>(col, l);
        k_gemm<0><<<dim3(BNODES / 128, DD / 256), 256, SMEM_GEMM>>>(4 + l, nb1 + l * DD);
        k_gemm<1><<<dim3(BNODES / 128, DD / 256), 256, SMEM_GEMM>>>(8 + l, nb2 + l * DD);
    }

    k_copy_out<<<(BNODES * DD) / (256 * 4), 256>>>((float*)d_out);
    int extra = out_size - BNODES * DD;
    if (extra > 0)
        k_mask<<<(extra + 255) / 256, 256>>>((float*)d_out + BNODES * DD, tok, extra);
}

// round 14
// speedup vs baseline: 2.2471x; 1.2010x over previous
#include <cuda_runtime.h>
#include <cuda_fp16.h>
#include <cstdint>

// ----- problem constants -----
#define BNODES 8192
#define EE     262144
#define DD     512
#define NRBF   128
#define NLAYER 4

// ----- distance->ef lookup table -----
#define NP    2048
#define DMAXF 10.4f
#define HSTEP (DMAXF / (float)(NP - 1))
#define INVH  ((float)(NP - 1) / DMAXF)

// ----- device scratch -----
__device__ float    g_x[BNODES * DD];             // fp32 node features (output path)
__device__ __half   g_xh[BNODES * DD];            // fp16 shadow of x (k_agg input)
__device__ float    g_dist[EE];
__device__ __half   g_tabH[NLAYER * NP * DD];     // fp16 ef tables (k_agg input)
__device__ __half   g_thH[NLAYER * NP * DD];      // fp16 hidden tables (gemm A)
__device__ __half   g_aggH[BNODES * DD];          // fp16 agg (gemm A)
__device__ __half   g_tH[BNODES * DD];            // fp16 node hidden (gemm A)
// weights: fp16 hi/lo split, transposed: per row(n): u32[0..255]=hi pairs, [256..511]=lo
__device__ uint32_t g_wS[12 * DD * DD];

__device__ __forceinline__ float silu_f(float v) { return v / (1.0f + __expf(-v)); }

__device__ __forceinline__ void cp16(void* dst, const void* src) {
    uint32_t d = (uint32_t)__cvta_generic_to_shared(dst);
    asm volatile("cp.async.cg.shared.global [%0], [%1], 16;" :: "r"(d), "l"(src));
}
__device__ __forceinline__ void cp_commit() { asm volatile("cp.async.commit_group;"); }
__device__ __forceinline__ void cp_wait0() { asm volatile("cp.async.wait_group 0;" ::: "memory"); }

__device__ __forceinline__ void split_hf(float x, __half& h, __half& l) {
    h = __float2half_rn(x);
    l = __float2half_rn(x - __half2float(h));
}
__device__ __forceinline__ uint32_t pack_hf(__half a, __half b) {
    __half2 p;
    p.x = a; p.y = b;
    return *(uint32_t*)&p;
}

__device__ __forceinline__ void mma_f16(float* c, const uint32_t* a, uint32_t b0, uint32_t b1) {
    asm volatile(
        "mma.sync.aligned.m16n8k16.row.col.f32.f16.f16.f32 "
        "{%0,%1,%2,%3}, {%4,%5,%6,%7}, {%8,%9}, {%0,%1,%2,%3};"
        : "+f"(c[0]), "+f"(c[1]), "+f"(c[2]), "+f"(c[3])
        : "r"(a[0]), "r"(a[1]), "r"(a[2]), "r"(a[3]), "r"(b0), "r"(b1));
}
__device__ __forceinline__ void ldsm4(uint32_t* r, uint32_t addr) {
    asm volatile("ldmatrix.sync.aligned.m8n8.x4.shared.b16 {%0,%1,%2,%3}, [%4];"
                 : "=r"(r[0]), "=r"(r[1]), "=r"(r[2]), "=r"(r[3]) : "r"(addr));
}

// ============================================================
__global__ void k_gather(const int* __restrict__ tok, const float* __restrict__ emb) {
    int i = blockIdx.x;
    int t = tok[i];
    float4 v = ((const float4*)(emb + (size_t)t * DD))[threadIdx.x];
    ((float4*)(g_x + (size_t)i * DD))[threadIdx.x] = v;
    __half2* xh = (__half2*)(g_xh + (size_t)i * DD);
    xh[threadIdx.x * 2] = __floats2half2_rn(v.x, v.y);
    xh[threadIdx.x * 2 + 1] = __floats2half2_rn(v.z, v.w);
}

__global__ void k_dist(const int* __restrict__ ei, const float* __restrict__ coords) {
    int e = blockIdx.x * 256 + threadIdx.x;
    int r = ei[e], c = ei[EE + e];
    float dx = coords[r * 3 + 0] - coords[c * 3 + 0];
    float dy = coords[r * 3 + 1] - coords[c * 3 + 1];
    float dz = coords[r * 3 + 2] - coords[c * 3 + 2];
    g_dist[e] = sqrtf(dx * dx + dy * dy + dz * dz);
}

// ============================================================
// Weight prep: transpose + fp16 hi/lo split.
// ============================================================
__global__ void k_wsplit(const float* __restrict__ Wb, int matBase) {
    __shared__ float ts[32][33];
    int k0 = blockIdx.x * 32, n0 = blockIdx.y * 32, l = blockIdx.z;
    const float* in = Wb + (size_t)l * DD * DD;
    uint32_t* out = g_wS + (size_t)(matBase + l) * DD * DD;
    int tx = threadIdx.x, ty = threadIdx.y;
#pragma unroll
    for (int i = 0; i < 4; i++)
        ts[ty + i * 8][tx] = in[(size_t)(k0 + ty + i * 8) * DD + n0 + tx];
    __syncthreads();
    int w_n = ty * 4 + (tx >> 3);
    int kp8 = tx & 7;
#pragma unroll
    for (int i = 0; i < 2; i++) {
        int kpl = kp8 * 2 + i;
        int kl = kpl * 2;
        __half h0, l0, h1, l1;
        split_hf(ts[kl][w_n], h0, l0);
        split_hf(ts[kl + 1][w_n], h1, l1);
        size_t base = (size_t)(n0 + w_n) * DD + (k0 >> 1) + kpl;
        out[base] = pack_hf(h0, h1);
        out[base + 256] = pack_hf(l0, l1);
    }
}

// ============================================================
// scalar FFMA GEMM bits (k_tab1 only)
// ============================================================
__device__ __forceinline__ void mma_tile(const float (*As)[132], const float (*Bs)[128],
                                         int tx, int ty, float acc[8][8]) {
#pragma unroll
    for (int k = 0; k < 16; k++) {
        float4 a0 = *(const float4*)&As[k][ty * 8];
        float4 a1 = *(const float4*)&As[k][ty * 8 + 4];
        float4 b0 = *(const float4*)&Bs[k][tx * 8];
        float4 b1 = *(const float4*)&Bs[k][tx * 8 + 4];
        float av[8] = {a0.x, a0.y, a0.z, a0.w, a1.x, a1.y, a1.z, a1.w};
        float bv[8] = {b0.x, b0.y, b0.z, b0.w, b1.x, b1.y, b1.z, b1.w};
#pragma unroll
        for (int i = 0; i < 8; i++)
#pragma unroll
            for (int j = 0; j < 8; j++)
                acc[i][j] = fmaf(av[i], bv[j], acc[i][j]);
    }
}
__device__ __forceinline__ void cpB(float (*Bs)[128], const float* __restrict__ W,
                                    int n0, int kc, int tid) {
#pragma unroll
    for (int i = 0; i < 2; i++) {
        int q = i * 256 + tid;
        int r = q >> 5, c4 = q & 31;
        cp16(&Bs[r][c4 * 4], &W[(size_t)(kc * 16 + r) * DD + n0 + c4 * 4]);
    }
}

// ============================================================
// Table pass 1: g_thH[z] = fp16(silu(rbf(grid) @ W1[z] + b1[z]))
// ============================================================
__global__ void __launch_bounds__(256, 2) k_tab1(const float* __restrict__ Wb,
                                                 const float* __restrict__ bb_) {
    __shared__ float As[16][132];
    __shared__ float Bs[2][16][128];
    int tid = threadIdx.x, tx = tid & 15, ty = tid >> 4;
    int m0 = blockIdx.x * 128, n0 = blockIdx.y * 128, l = blockIdx.z;
    const float* W = Wb + (size_t)l * NRBF * DD;
    const float* b = bb_ + (size_t)l * DD;
    const float step = 6.0f / 127.0f;

    cpB(Bs[0], W, n0, 0, tid);
    cp_commit();

    float acc[8][8] = {};
#pragma unroll 1
    for (int kc = 0; kc < NRBF / 16; kc++) {
        int buf = kc & 1;
#pragma unroll
        for (int i = 0; i < 8; i++) {
            int idx = i * 256 + tid;
            int m = idx & 127, k = idx >> 7;
            float d = (float)(m0 + m) * HSTEP;
            float c = (float)(kc * 16 + k) * step;
            float dd = d - c;
            As[k][m] = __expf(-10.0f * dd * dd);
        }
        if (kc + 1 < NRBF / 16) { cpB(Bs[buf ^ 1], W, n0, kc + 1, tid); cp_commit(); }
        cp_wait0();
        __syncthreads();
        mma_tile(As, Bs[buf], tx, ty, acc);
        __syncthreads();
    }

    float bb[8];
#pragma unroll
    for (int j = 0; j < 8; j++) bb[j] = b[n0 + tx * 8 + j];
    __half* out = g_thH + (size_t)l * NP * DD;
#pragma unroll
    for (int i = 0; i < 8; i++) {
        uint32_t p[4];
#pragma unroll
        for (int q = 0; q < 4; q++) {
            float v0 = silu_f(acc[i][q * 2] + bb[q * 2]);
            float v1 = silu_f(acc[i][q * 2 + 1] + bb[q * 2 + 1]);
            __half2 h = __floats2half2_rn(v0, v1);
            p[q] = *(uint32_t*)&h;
        }
        *(uint4*)(out + (size_t)(m0 + ty * 8 + i) * DD + n0 + tx * 8) =
            make_uint4(p[0], p[1], p[2], p[3]);
    }
}

// ============================================================
// HMMA fp16x2 GEMM: C = A(fp16) @ (Wh + Wl) + b.  2 MMAs per tile.
// Tile 128x256, 8 warps (2m x 4n), warp tile 64x64, BK=64, 2 stages.
// Stage buffer: A 16KB + Bhi 32KB + Blo 32KB = 80KB; x2 = 160KB.
// smem rows 128B, 8 chunks, pos = c ^ (row&7).
// EPI 0: g_tH = fp16(silu(.)); 1: g_x += . (+g_xh); 2: g_tabH[z] = fp16(.)
// ============================================================
#define STGSZ 81920
#define SMEM_GEMM (2 * STGSZ + 1024)

template <int EPI>
__global__ void __launch_bounds__(256) k_gemm(int mat, const float* __restrict__ bb_) {
    extern __shared__ uint32_t smem_u[];
    char* smem_c = (char*)smem_u;
    float* sbias = (float*)(smem_c + 2 * STGSZ);
    const uint32_t sbase = (uint32_t)__cvta_generic_to_shared(smem_u);

    int tid = threadIdx.x, lane = tid & 31, wid = tid >> 5;
    int m0 = blockIdx.x * 128, n0 = blockIdx.y * 256, l = blockIdx.z;
    const __half* Aq = (EPI == 0) ? g_aggH : (EPI == 1) ? g_tH
                                           : (g_thH + (size_t)l * NP * DD);
    const uint32_t* Wq = g_wS + (size_t)(mat + l) * DD * DD;
    const float* b = (EPI == 2) ? bb_ + (size_t)l * DD : bb_;

    sbias[tid] = b[n0 + tid];

    // A staging: 2 threads/row, 4 chunks each (BK=64 -> 128B/row)
    const int srow = tid >> 1, cbase = (tid & 1) * 4;
    const __half* aRow = Aq + (size_t)(m0 + srow) * DD;
    uint32_t dstA[4];
#pragma unroll
    for (int j = 0; j < 4; j++)
        dstA[j] = srow * 128 + (((cbase + j) ^ (srow & 7)) << 4);
    // B staging: 1 thread/row, 8 hi chunks + 8 lo chunks
    const int brow = tid;
    const uint32_t* bRow = Wq + (size_t)(n0 + brow) * DD;
    uint32_t dstB[8];
#pragma unroll
    for (int c = 0; c < 8; c++)
        dstB[c] = brow * 128 + ((c ^ (brow & 7)) << 4);

    auto issue = [&](int kc, int buf) {
        char* Ab = smem_c + buf * STGSZ;
        char* Bh = Ab + 16384;
        char* Bl = Bh + 32768;
#pragma unroll
        for (int j = 0; j < 4; j++)
            cp16(Ab + dstA[j], aRow + kc * 64 + (cbase + j) * 8);
#pragma unroll
        for (int c = 0; c < 8; c++)
            cp16(Bh + dstB[c], bRow + kc * 32 + c * 4);
#pragma unroll
        for (int c = 0; c < 8; c++)
            cp16(Bl + dstB[c], bRow + 256 + kc * 32 + c * 4);
        cp_commit();
    };

    // fragment mapping
    const int g = lane >> 2, tig = lane & 3;
    const int wm = (wid >> 2) * 64, wn = (wid & 3) * 64;
    const int lq = lane >> 3, lr = lane & 7;
    const int rowA = (lq & 1) * 8 + lr, kqA = lq >> 1;
    const int rowB = (lq >> 1) * 8 + lr, kqB = lq & 1;
    const uint32_t aBase = sbase + (wm + rowA) * 128;
    const uint32_t bBase = sbase + 16384 + (wn + rowB) * 128;

    issue(0, 0);

    float acc[4][8][4] = {};
    const int NCH = DD / 64;   // 8
#pragma unroll 1
    for (int kc = 0; kc < NCH; kc++) {
        int buf = kc & 1;
        cp_wait0();
        __syncthreads();
        if (kc + 1 < NCH) issue(kc + 1, buf ^ 1);
#pragma unroll
        for (int ks = 0; ks < 4; ks++) {
            uint32_t aH[4][4], bH[4][4], bL[4][4];
            uint32_t chA = (uint32_t)(((ks * 2 + kqA) ^ (rowA & 7)) << 4);
            uint32_t chB = (uint32_t)(((ks * 2 + kqB) ^ (rowB & 7)) << 4);
#pragma unroll
            for (int mt = 0; mt < 4; mt++)
                ldsm4(aH[mt], aBase + buf * STGSZ + mt * 2048 + chA);
#pragma unroll
            for (int np = 0; np < 4; np++) {
                uint32_t bd = bBase + buf * STGSZ + np * 2048 + chB;
                ldsm4(bH[np], bd);
                ldsm4(bL[np], bd + 32768);
            }
#pragma unroll
            for (int mt = 0; mt < 4; mt++)
#pragma unroll
                for (int nt = 0; nt < 8; nt++) {
                    uint32_t bh0 = bH[nt >> 1][(nt & 1) * 2], bh1 = bH[nt >> 1][(nt & 1) * 2 + 1];
                    uint32_t bl0 = bL[nt >> 1][(nt & 1) * 2], bl1 = bL[nt >> 1][(nt & 1) * 2 + 1];
                    mma_f16(acc[mt][nt], aH[mt], bh0, bh1);
                    mma_f16(acc[mt][nt], aH[mt], bl0, bl1);
                }
        }
    }

    // ---- epilogue ----
#pragma unroll
    for (int mt = 0; mt < 4; mt++) {
#pragma unroll
        for (int nt = 0; nt < 8; nt++) {
            int row = m0 + wm + mt * 16 + g;
            int cl = wn + nt * 8 + tig * 2;
            float b0 = sbias[cl], b1 = sbias[cl + 1];
            float* c = acc[mt][nt];
#pragma unroll
            for (int half = 0; half < 2; half++) {
                int r = row + half * 8;
                float v0 = c[half * 2 + 0] + b0, v1 = c[half * 2 + 1] + b1;
                size_t off = (size_t)r * DD + n0 + cl;
                if (EPI == 0) {
                    *(__half2*)(g_tH + off) = __floats2half2_rn(silu_f(v0), silu_f(v1));
                } else if (EPI == 1) {
                    float2 x = *(float2*)(g_x + off);
                    x.x += v0; x.y += v1;
                    *(float2*)(g_x + off) = x;
                    *(__half2*)(g_xh + off) = __floats2half2_rn(x.x, x.y);
                } else {
                    *(__half2*)(g_tabH + (size_t)l * NP * DD + off) =
                        __floats2half2_rn(v0, v1);
                }
            }
        }
    }
}

// ============================================================
// Edge pass (fp16 inputs, LDG.128, fp32 accumulate):
// 256-thread blocks process 4 nodes; 64 threads/node; 8 dims/thread.
// ============================================================
__global__ void __launch_bounds__(256) k_agg(const int* __restrict__ col, int l) {
    __shared__ int   scol[4][32];
    __shared__ int   sidx[4][32];
    __shared__ float sw[4][32];
    const __half* tab = g_tabH + (size_t)l * NP * DD;
    int tid = threadIdx.x;
    int node0 = blockIdx.x * 4;
    if (tid < 128) {
        int sn = tid >> 5, se = tid & 31;
        int e = (node0 + sn) * 32 + se;
        scol[sn][se] = col[e];
        float f = g_dist[e] * INVH;
        int i = (int)f;
        if (i > NP - 2) i = NP - 2;
        sidx[sn][se] = i;
        sw[sn][se] = f - (float)i;
    }
    __syncthreads();

    int sn = tid >> 6;
    int t = tid & 63;
    int node = node0 + sn;
    int dim = t * 8;

    float a[8] = {};
#pragma unroll 8
    for (int e = 0; e < 32; e++) {
        size_t tbase = (size_t)sidx[sn][e] * DD + dim;
        uint4 T0 = *(const uint4*)&tab[tbase];
        uint4 T1 = *(const uint4*)&tab[tbase + DD];
        uint4 X = *(const uint4*)&g_xh[(size_t)scol[sn][e] * DD + dim];
        float w = sw[sn][e];
        const __half2* t0 = (const __half2*)&T0;
        const __half2* t1 = (const __half2*)&T1;
        const __half2* xv = (const __half2*)&X;
#pragma unroll
        for (int q = 0; q < 4; q++) {
            float2 f0 = __half22float2(t0[q]);
            float2 f1 = __half22float2(t1[q]);
            float2 fx = __half22float2(xv[q]);
            a[q * 2 + 0] = fmaf(fmaf(w, f1.x - f0.x, f0.x), fx.x, a[q * 2 + 0]);
            a[q * 2 + 1] = fmaf(fmaf(w, f1.y - f0.y, f0.y), fx.y, a[q * 2 + 1]);
        }
    }
    uint32_t p[4];
#pragma unroll
    for (int q = 0; q < 4; q++) {
        __half2 h = __floats2half2_rn(a[q * 2], a[q * 2 + 1]);
        p[q] = *(uint32_t*)&h;
    }
    *(uint4*)(g_aggH + (size_t)node * DD + dim) = make_uint4(p[0], p[1], p[2], p[3]);
}

// ============================================================
__global__ void k_copy_out(float* __restrict__ out) {
    size_t i = (size_t)blockIdx.x * 256 + threadIdx.x;
    ((float4*)out)[i] = ((const float4*)g_x)[i];
}
__global__ void k_mask(float* __restrict__ out, const int* __restrict__ tok, int n) {
    int i = blockIdx.x * 256 + threadIdx.x;
    if (i < n) out[i] = (i < BNODES && tok[i] == 0) ? 1.0f : 0.0f;
}

// ============================================================
extern "C" void kernel_launch(void* const* d_in, const int* in_sizes, int n_in,
                              void* d_out, int out_size) {
    const int*   tok    = (const int*)d_in[0];
    const float* coords = (const float*)d_in[1];
    const int*   ei     = (const int*)d_in[2];
    const float* emb    = (const float*)d_in[3];
    const float* ew1    = (const float*)d_in[4];
    const float* eb1    = (const float*)d_in[5];
    const float* ew2    = (const float*)d_in[6];
    const float* eb2    = (const float*)d_in[7];
    const float* nw1    = (const float*)d_in[8];
    const float* nb1    = (const float*)d_in[9];
    const float* nw2    = (const float*)d_in[10];
    const float* nb2    = (const float*)d_in[11];

    cudaFuncSetAttribute(k_gemm<0>, cudaFuncAttributeMaxDynamicSharedMemorySize, SMEM_GEMM);
    cudaFuncSetAttribute(k_gemm<1>, cudaFuncAttributeMaxDynamicSharedMemorySize, SMEM_GEMM);
    cudaFuncSetAttribute(k_gemm<2>, cudaFuncAttributeMaxDynamicSharedMemorySize, SMEM_GEMM);

    k_gather<<<BNODES, 128>>>(tok, emb);
    k_dist<<<EE / 256, 256>>>(ei, coords);

    k_wsplit<<<dim3(16, 16, NLAYER), dim3(32, 8)>>>(ew2, 0);
    k_wsplit<<<dim3(16, 16, NLAYER), dim3(32, 8)>>>(nw1, 4);
    k_wsplit<<<dim3(16, 16, NLAYER), dim3(32, 8)>>>(nw2, 8);

    k_tab1<<<dim3(NP / 128, 4, NLAYER), 256>>>(ew1, eb1);
    k_gemm<2><<<dim3(NP / 128, DD / 256, NLAYER), 256, SMEM_GEMM>>>(0, eb2);

    const int* col = ei + EE;
    for (int l = 0; l < NLAYER; l++) {
        k_agg<<<BNODES / 4, 256>>>(col, l);
        k_gemm<0><<<dim3(BNODES / 128, DD / 256), 256, SMEM_GEMM>>>(4 + l, nb1 + l * DD);
        k_gemm<1><<<dim3(BNODES / 128, DD / 256), 256, SMEM_GEMM>>>(8 + l, nb2 + l * DD);
    }

    k_copy_out<<<(BNODES * DD) / (256 * 4), 256>>>((float*)d_out);
    int extra = out_size - BNODES * DD;
    if (extra > 0)
        k_mask<<<(extra + 255) / 256, 256>>>((float*)d_out + BNODES * DD, tok, extra);
}

// round 15
// speedup vs baseline: 2.8712x; 1.2777x over previous
#include <cuda_runtime.h>
#include <cuda_fp16.h>
#include <cstdint>

// ----- problem constants -----
#define BNODES 8192
#define EE     262144
#define DD     512
#define NRBF   128
#define NLAYER 4

// ----- distance->ef lookup table -----
#define NP    2048
#define DMAXF 10.4f
#define HSTEP (DMAXF / (float)(NP - 1))
#define INVH  ((float)(NP - 1) / DMAXF)

// ----- device scratch -----
__device__ float    g_x[BNODES * DD];             // fp32 node features (output path)
__device__ __half   g_xh[BNODES * DD];            // fp16 shadow of x (k_agg input)
__device__ float    g_dist[EE];
__device__ __half   g_tabH[NLAYER * NP * DD];     // fp16 ef tables (k_agg input)
__device__ __half   g_thH[NLAYER * NP * DD];      // fp16 hidden tables (gemm A)
__device__ __half   g_aggH[BNODES * DD];          // fp16 agg (gemm A)
__device__ __half   g_tH[BNODES * DD];            // fp16 node hidden (gemm A)
__device__ __half   g_wH[12 * DD * DD];           // fp16 transposed weights [mat][n][k]

__device__ __forceinline__ float silu_f(float v) { return v / (1.0f + __expf(-v)); }

__device__ __forceinline__ void cp16(void* dst, const void* src) {
    uint32_t d = (uint32_t)__cvta_generic_to_shared(dst);
    asm volatile("cp.async.cg.shared.global [%0], [%1], 16;" :: "r"(d), "l"(src));
}
__device__ __forceinline__ void cp_commit() { asm volatile("cp.async.commit_group;"); }
__device__ __forceinline__ void cp_wait0() { asm volatile("cp.async.wait_group 0;" ::: "memory"); }

__device__ __forceinline__ uint32_t pack_hf(__half a, __half b) {
    __half2 p;
    p.x = a; p.y = b;
    return *(uint32_t*)&p;
}

__device__ __forceinline__ void mma_f16(float* c, const uint32_t* a, uint32_t b0, uint32_t b1) {
    asm volatile(
        "mma.sync.aligned.m16n8k16.row.col.f32.f16.f16.f32 "
        "{%0,%1,%2,%3}, {%4,%5,%6,%7}, {%8,%9}, {%0,%1,%2,%3};"
        : "+f"(c[0]), "+f"(c[1]), "+f"(c[2]), "+f"(c[3])
        : "r"(a[0]), "r"(a[1]), "r"(a[2]), "r"(a[3]), "r"(b0), "r"(b1));
}
__device__ __forceinline__ void ldsm4(uint32_t* r, uint32_t addr) {
    asm volatile("ldmatrix.sync.aligned.m8n8.x4.shared.b16 {%0,%1,%2,%3}, [%4];"
                 : "=r"(r[0]), "=r"(r[1]), "=r"(r[2]), "=r"(r[3]) : "r"(addr));
}

// ============================================================
__global__ void k_gather(const int* __restrict__ tok, const float* __restrict__ emb) {
    int i = blockIdx.x;
    int t = tok[i];
    float4 v = ((const float4*)(emb + (size_t)t * DD))[threadIdx.x];
    ((float4*)(g_x + (size_t)i * DD))[threadIdx.x] = v;
    __half2* xh = (__half2*)(g_xh + (size_t)i * DD);
    xh[threadIdx.x * 2] = __floats2half2_rn(v.x, v.y);
    xh[threadIdx.x * 2 + 1] = __floats2half2_rn(v.z, v.w);
}

__global__ void k_dist(const int* __restrict__ ei, const float* __restrict__ coords) {
    int e = blockIdx.x * 256 + threadIdx.x;
    int r = ei[e], c = ei[EE + e];
    float dx = coords[r * 3 + 0] - coords[c * 3 + 0];
    float dy = coords[r * 3 + 1] - coords[c * 3 + 1];
    float dz = coords[r * 3 + 2] - coords[c * 3 + 2];
    g_dist[e] = sqrtf(dx * dx + dy * dy + dz * dz);
}

// ============================================================
// Weight prep: transpose + fp16 convert. Out: g_wH[mat][n][k].
// ============================================================
__global__ void k_wprep(const float* __restrict__ Wb, int matBase) {
    __shared__ float ts[32][33];
    int k0 = blockIdx.x * 32, n0 = blockIdx.y * 32, l = blockIdx.z;
    const float* in = Wb + (size_t)l * DD * DD;
    __half* out = g_wH + (size_t)(matBase + l) * DD * DD;
    int tx = threadIdx.x, ty = threadIdx.y;   // 32 x 8
#pragma unroll
    for (int i = 0; i < 4; i++)
        ts[ty + i * 8][tx] = in[(size_t)(k0 + ty + i * 8) * DD + n0 + tx];
    __syncthreads();
    int w_n = ty * 4 + (tx >> 3);
    int kq = (tx & 7) * 4;
    uint32_t* orow = (uint32_t*)(out + (size_t)(n0 + w_n) * DD + k0 + kq);
#pragma unroll
    for (int i = 0; i < 2; i++) {
        __half h0 = __float2half_rn(ts[kq + 2 * i][w_n]);
        __half h1 = __float2half_rn(ts[kq + 2 * i + 1][w_n]);
        orow[i] = pack_hf(h0, h1);
    }
}

// ============================================================
// scalar FFMA GEMM bits (k_tab1 only)
// ============================================================
__device__ __forceinline__ void mma_tile(const float (*As)[132], const float (*Bs)[128],
                                         int tx, int ty, float acc[8][8]) {
#pragma unroll
    for (int k = 0; k < 16; k++) {
        float4 a0 = *(const float4*)&As[k][ty * 8];
        float4 a1 = *(const float4*)&As[k][ty * 8 + 4];
        float4 b0 = *(const float4*)&Bs[k][tx * 8];
        float4 b1 = *(const float4*)&Bs[k][tx * 8 + 4];
        float av[8] = {a0.x, a0.y, a0.z, a0.w, a1.x, a1.y, a1.z, a1.w};
        float bv[8] = {b0.x, b0.y, b0.z, b0.w, b1.x, b1.y, b1.z, b1.w};
#pragma unroll
        for (int i = 0; i < 8; i++)
#pragma unroll
            for (int j = 0; j < 8; j++)
                acc[i][j] = fmaf(av[i], bv[j], acc[i][j]);
    }
}
__device__ __forceinline__ void cpB(float (*Bs)[128], const float* __restrict__ W,
                                    int n0, int kc, int tid) {
#pragma unroll
    for (int i = 0; i < 2; i++) {
        int q = i * 256 + tid;
        int r = q >> 5, c4 = q & 31;
        cp16(&Bs[r][c4 * 4], &W[(size_t)(kc * 16 + r) * DD + n0 + c4 * 4]);
    }
}

// ============================================================
// Table pass 1: g_thH[z] = fp16(silu(rbf(grid) @ W1[z] + b1[z]))
// ============================================================
__global__ void __launch_bounds__(256, 2) k_tab1(const float* __restrict__ Wb,
                                                 const float* __restrict__ bb_) {
    __shared__ float As[16][132];
    __shared__ float Bs[2][16][128];
    int tid = threadIdx.x, tx = tid & 15, ty = tid >> 4;
    int m0 = blockIdx.x * 128, n0 = blockIdx.y * 128, l = blockIdx.z;
    const float* W = Wb + (size_t)l * NRBF * DD;
    const float* b = bb_ + (size_t)l * DD;
    const float step = 6.0f / 127.0f;

    cpB(Bs[0], W, n0, 0, tid);
    cp_commit();

    float acc[8][8] = {};
#pragma unroll 1
    for (int kc = 0; kc < NRBF / 16; kc++) {
        int buf = kc & 1;
#pragma unroll
        for (int i = 0; i < 8; i++) {
            int idx = i * 256 + tid;
            int m = idx & 127, k = idx >> 7;
            float d = (float)(m0 + m) * HSTEP;
            float c = (float)(kc * 16 + k) * step;
            float dd = d - c;
            As[k][m] = __expf(-10.0f * dd * dd);
        }
        if (kc + 1 < NRBF / 16) { cpB(Bs[buf ^ 1], W, n0, kc + 1, tid); cp_commit(); }
        cp_wait0();
        __syncthreads();
        mma_tile(As, Bs[buf], tx, ty, acc);
        __syncthreads();
    }

    float bb[8];
#pragma unroll
    for (int j = 0; j < 8; j++) bb[j] = b[n0 + tx * 8 + j];
    __half* out = g_thH + (size_t)l * NP * DD;
#pragma unroll
    for (int i = 0; i < 8; i++) {
        uint32_t p[4];
#pragma unroll
        for (int q = 0; q < 4; q++) {
            float v0 = silu_f(acc[i][q * 2] + bb[q * 2]);
            float v1 = silu_f(acc[i][q * 2 + 1] + bb[q * 2 + 1]);
            __half2 h = __floats2half2_rn(v0, v1);
            p[q] = *(uint32_t*)&h;
        }
        *(uint4*)(out + (size_t)(m0 + ty * 8 + i) * DD + n0 + tx * 8) =
            make_uint4(p[0], p[1], p[2], p[3]);
    }
}

// ============================================================
// HMMA fp16 GEMM: C = A(fp16) @ W(fp16) + b.  1 MMA per tile.
// Tile 128x256, 8 warps (2m x 4n), warp tile 64x64, BK=64, 2 stages.
// Stage buffer: A 16KB + B 32KB = 48KB; x2 = 96KB.
// smem rows 128B (64 fp16 k-values), 8 chunks, pos = c ^ (row&7).
// EPI 0: g_tH = fp16(silu(.)); 1: g_x += . (+g_xh); 2: g_tabH[z] = fp16(.)
// ============================================================
#define STGSZ 49152
#define SMEM_GEMM (2 * STGSZ + 1024)

template <int EPI>
__global__ void __launch_bounds__(256) k_gemm(int mat, const float* __restrict__ bb_) {
    extern __shared__ uint32_t smem_u[];
    char* smem_c = (char*)smem_u;
    float* sbias = (float*)(smem_c + 2 * STGSZ);
    const uint32_t sbase = (uint32_t)__cvta_generic_to_shared(smem_u);

    int tid = threadIdx.x, lane = tid & 31, wid = tid >> 5;
    int m0 = blockIdx.x * 128, n0 = blockIdx.y * 256, l = blockIdx.z;
    const __half* Aq = (EPI == 0) ? g_aggH : (EPI == 1) ? g_tH
                                           : (g_thH + (size_t)l * NP * DD);
    const __half* Wq = g_wH + (size_t)(mat + l) * DD * DD;
    const float* b = (EPI == 2) ? bb_ + (size_t)l * DD : bb_;

    sbias[tid] = b[n0 + tid];

    // A staging: 2 threads/row, 4 chunks each (BK=64 -> 128B/row)
    const int srow = tid >> 1, cbase = (tid & 1) * 4;
    const __half* aRow = Aq + (size_t)(m0 + srow) * DD;
    uint32_t dstA[4];
#pragma unroll
    for (int j = 0; j < 4; j++)
        dstA[j] = srow * 128 + (((cbase + j) ^ (srow & 7)) << 4);
    // B staging: 1 thread/row (256 rows), 8 chunks of 16B = 64 fp16 k
    const int brow = tid;
    const __half* bRow = Wq + (size_t)(n0 + brow) * DD;
    uint32_t dstB[8];
#pragma unroll
    for (int c = 0; c < 8; c++)
        dstB[c] = brow * 128 + ((c ^ (brow & 7)) << 4);

    auto issue = [&](int kc, int buf) {
        char* Ab = smem_c + buf * STGSZ;
        char* Bb = Ab + 16384;
#pragma unroll
        for (int j = 0; j < 4; j++)
            cp16(Ab + dstA[j], aRow + kc * 64 + (cbase + j) * 8);
#pragma unroll
        for (int c = 0; c < 8; c++)
            cp16(Bb + dstB[c], bRow + kc * 64 + c * 8);
        cp_commit();
    };

    // fragment mapping
    const int g = lane >> 2, tig = lane & 3;
    const int wm = (wid >> 2) * 64, wn = (wid & 3) * 64;
    const int lq = lane >> 3, lr = lane & 7;
    const int rowA = (lq & 1) * 8 + lr, kqA = lq >> 1;
    const int rowB = (lq >> 1) * 8 + lr, kqB = lq & 1;
    const uint32_t aBase = sbase + (wm + rowA) * 128;
    const uint32_t bBase = sbase + 16384 + (wn + rowB) * 128;

    issue(0, 0);

    float acc[4][8][4] = {};
    const int NCH = DD / 64;   // 8
#pragma unroll 1
    for (int kc = 0; kc < NCH; kc++) {
        int buf = kc & 1;
        cp_wait0();
        __syncthreads();
        if (kc + 1 < NCH) issue(kc + 1, buf ^ 1);
#pragma unroll
        for (int ks = 0; ks < 4; ks++) {
            uint32_t aH[4][4], bH[4][4];
            uint32_t chA = (uint32_t)(((ks * 2 + kqA) ^ (rowA & 7)) << 4);
            uint32_t chB = (uint32_t)(((ks * 2 + kqB) ^ (rowB & 7)) << 4);
#pragma unroll
            for (int mt = 0; mt < 4; mt++)
                ldsm4(aH[mt], aBase + buf * STGSZ + mt * 2048 + chA);
#pragma unroll
            for (int np = 0; np < 4; np++)
                ldsm4(bH[np], bBase + buf * STGSZ + np * 2048 + chB);
#pragma unroll
            for (int mt = 0; mt < 4; mt++)
#pragma unroll
                for (int nt = 0; nt < 8; nt++) {
                    uint32_t bh0 = bH[nt >> 1][(nt & 1) * 2];
                    uint32_t bh1 = bH[nt >> 1][(nt & 1) * 2 + 1];
                    mma_f16(acc[mt][nt], aH[mt], bh0, bh1);
                }
        }
    }

    // ---- epilogue ----
#pragma unroll
    for (int mt = 0; mt < 4; mt++) {
#pragma unroll
        for (int nt = 0; nt < 8; nt++) {
            int row = m0 + wm + mt * 16 + g;
            int cl = wn + nt * 8 + tig * 2;
            float b0 = sbias[cl], b1 = sbias[cl + 1];
            float* c = acc[mt][nt];
#pragma unroll
            for (int half = 0; half < 2; half++) {
                int r = row + half * 8;
                float v0 = c[half * 2 + 0] + b0, v1 = c[half * 2 + 1] + b1;
                size_t off = (size_t)r * DD + n0 + cl;
                if (EPI == 0) {
                    *(__half2*)(g_tH + off) = __floats2half2_rn(silu_f(v0), silu_f(v1));
                } else if (EPI == 1) {
                    float2 x = *(float2*)(g_x + off);
                    x.x += v0; x.y += v1;
                    *(float2*)(g_x + off) = x;
                    *(__half2*)(g_xh + off) = __floats2half2_rn(x.x, x.y);
                } else {
                    *(__half2*)(g_tabH + (size_t)l * NP * DD + off) =
                        __floats2half2_rn(v0, v1);
                }
            }
        }
    }
}

// ============================================================
// Edge pass (fp16 inputs, LDG.128, fp32 accumulate):
// 256-thread blocks process 4 nodes; 64 threads/node; 8 dims/thread.
// ============================================================
__global__ void __launch_bounds__(256) k_agg(const int* __restrict__ col, int l) {
    __shared__ int   scol[4][32];
    __shared__ int   sidx[4][32];
    __shared__ float sw[4][32];
    const __half* tab = g_tabH + (size_t)l * NP * DD;
    int tid = threadIdx.x;
    int node0 = blockIdx.x * 4;
    if (tid < 128) {
        int sn = tid >> 5, se = tid & 31;
        int e = (node0 + sn) * 32 + se;
        scol[sn][se] = col[e];
        float f = g_dist[e] * INVH;
        int i = (int)f;
        if (i > NP - 2) i = NP - 2;
        sidx[sn][se] = i;
        sw[sn][se] = f - (float)i;
    }
    __syncthreads();

    int sn = tid >> 6;
    int t = tid & 63;
    int node = node0 + sn;
    int dim = t * 8;

    float a[8] = {};
#pragma unroll 8
    for (int e = 0; e < 32; e++) {
        size_t tbase = (size_t)sidx[sn][e] * DD + dim;
        uint4 T0 = *(const uint4*)&tab[tbase];
        uint4 T1 = *(const uint4*)&tab[tbase + DD];
        uint4 X = *(const uint4*)&g_xh[(size_t)scol[sn][e] * DD + dim];
        float w = sw[sn][e];
        const __half2* t0 = (const __half2*)&T0;
        const __half2* t1 = (const __half2*)&T1;
        const __half2* xv = (const __half2*)&X;
#pragma unroll
        for (int q = 0; q < 4; q++) {
            float2 f0 = __half22float2(t0[q]);
            float2 f1 = __half22float2(t1[q]);
            float2 fx = __half22float2(xv[q]);
            a[q * 2 + 0] = fmaf(fmaf(w, f1.x - f0.x, f0.x), fx.x, a[q * 2 + 0]);
            a[q * 2 + 1] = fmaf(fmaf(w, f1.y - f0.y, f0.y), fx.y, a[q * 2 + 1]);
        }
    }
    uint32_t p[4];
#pragma unroll
    for (int q = 0; q < 4; q++) {
        __half2 h = __floats2half2_rn(a[q * 2], a[q * 2 + 1]);
        p[q] = *(uint32_t*)&h;
    }
    *(uint4*)(g_aggH + (size_t)node * DD + dim) = make_uint4(p[0], p[1], p[2], p[3]);
}

// ============================================================
__global__ void k_copy_out(float* __restrict__ out) {
    size_t i = (size_t)blockIdx.x * 256 + threadIdx.x;
    ((float4*)out)[i] = ((const float4*)g_x)[i];
}
__global__ void k_mask(float* __restrict__ out, const int* __restrict__ tok, int n) {
    int i = blockIdx.x * 256 + threadIdx.x;
    if (i < n) out[i] = (i < BNODES && tok[i] == 0) ? 1.0f : 0.0f;
}

// ============================================================
extern "C" void kernel_launch(void* const* d_in, const int* in_sizes, int n_in,
                              void* d_out, int out_size) {
    const int*   tok    = (const int*)d_in[0];
    const float* coords = (const float*)d_in[1];
    const int*   ei     = (const int*)d_in[2];
    const float* emb    = (const float*)d_in[3];
    const float* ew1    = (const float*)d_in[4];
    const float* eb1    = (const float*)d_in[5];
    const float* ew2    = (const float*)d_in[6];
    const float* eb2    = (const float*)d_in[7];
    const float* nw1    = (const float*)d_in[8];
    const float* nb1    = (const float*)d_in[9];
    const float* nw2    = (const float*)d_in[10];
    const float* nb2    = (const float*)d_in[11];

    cudaFuncSetAttribute(k_gemm<0>, cudaFuncAttributeMaxDynamicSharedMemorySize, SMEM_GEMM);
    cudaFuncSetAttribute(k_gemm<1>, cudaFuncAttributeMaxDynamicSharedMemorySize, SMEM_GEMM);
    cudaFuncSetAttribute(k_gemm<2>, cudaFuncAttributeMaxDynamicSharedMemorySize, SMEM_GEMM);

    k_gather<<<BNODES, 128>>>(tok, emb);
    k_dist<<<EE / 256, 256>>>(ei, coords);

    k_wprep<<<dim3(16, 16, NLAYER), dim3(32, 8)>>>(ew2, 0);
    k_wprep<<<dim3(16, 16, NLAYER), dim3(32, 8)>>>(nw1, 4);
    k_wprep<<<dim3(16, 16, NLAYER), dim3(32, 8)>>>(nw2, 8);

    k_tab1<<<dim3(NP / 128, 4, NLAYER), 256>>>(ew1, eb1);
    k_gemm<2><<<dim3(NP / 128, DD / 256, NLAYER), 256, SMEM_GEMM>>>(0, eb2);

    const int* col = ei + EE;
    for (int l = 0; l < NLAYER; l++) {
        k_agg<<<BNODES / 4, 256>>>(col, l);
        k_gemm<0><<<dim3(BNODES / 128, DD / 256), 256, SMEM_GEMM>>>(4 + l, nb1 + l * DD);
        k_gemm<1><<<dim3(BNODES / 128, DD / 256), 256, SMEM_GEMM>>>(8 + l, nb2 + l * DD);
    }

    k_copy_out<<<(BNODES * DD) / (256 * 4), 256>>>((float*)d_out);
    int extra = out_size - BNODES * DD;
    if (extra > 0)
        k_mask<<<(extra + 255) / 256, 256>>>((float*)d_out + BNODES * DD, tok, extra);
}

// round 16
// speedup vs baseline: 2.9182x; 1.0164x over previous
#include <cuda_runtime.h>
#include <cuda_fp16.h>
#include <cstdint>

// ----- problem constants -----
#define BNODES 8192
#define EE     262144
#define DD     512
#define NRBF   128
#define NLAYER 4

// ----- distance->ef lookup table -----
#define NP    2048
#define DMAXF 10.4f
#define HSTEP (DMAXF / (float)(NP - 1))
#define INVH  ((float)(NP - 1) / DMAXF)

// ----- device scratch -----
__device__ float    g_x[BNODES * DD];             // fp32 node features (output path)
__device__ __half   g_xh[BNODES * DD];            // fp16 shadow of x (k_agg input)
__device__ float    g_dist[EE];
__device__ __half   g_tabH[NLAYER * NP * DD];     // fp16 ef tables (k_agg input)
__device__ __half   g_thH[NLAYER * NP * DD];      // fp16 hidden tables (gemm A)
__device__ __half   g_aggH[BNODES * DD];          // fp16 agg (gemm A)
__device__ __half   g_tH[BNODES * DD];            // fp16 node hidden (gemm A)
__device__ __half   g_wH[12 * DD * DD];           // fp16 transposed weights [mat][n][k]

__device__ __forceinline__ float silu_f(float v) { return v / (1.0f + __expf(-v)); }

__device__ __forceinline__ void cp16(void* dst, const void* src) {
    uint32_t d = (uint32_t)__cvta_generic_to_shared(dst);
    asm volatile("cp.async.cg.shared.global [%0], [%1], 16;" :: "r"(d), "l"(src));
}
__device__ __forceinline__ void cp_commit() { asm volatile("cp.async.commit_group;"); }
__device__ __forceinline__ void cp_wait0() { asm volatile("cp.async.wait_group 0;" ::: "memory"); }
__device__ __forceinline__ void cp_wait1() { asm volatile("cp.async.wait_group 1;" ::: "memory"); }

__device__ __forceinline__ uint32_t pack_hf(__half a, __half b) {
    __half2 p;
    p.x = a; p.y = b;
    return *(uint32_t*)&p;
}

__device__ __forceinline__ void mma_f16(float* c, const uint32_t* a, uint32_t b0, uint32_t b1) {
    asm volatile(
        "mma.sync.aligned.m16n8k16.row.col.f32.f16.f16.f32 "
        "{%0,%1,%2,%3}, {%4,%5,%6,%7}, {%8,%9}, {%0,%1,%2,%3};"
        : "+f"(c[0]), "+f"(c[1]), "+f"(c[2]), "+f"(c[3])
        : "r"(a[0]), "r"(a[1]), "r"(a[2]), "r"(a[3]), "r"(b0), "r"(b1));
}
__device__ __forceinline__ void ldsm4(uint32_t* r, uint32_t addr) {
    asm volatile("ldmatrix.sync.aligned.m8n8.x4.shared.b16 {%0,%1,%2,%3}, [%4];"
                 : "=r"(r[0]), "=r"(r[1]), "=r"(r[2]), "=r"(r[3]) : "r"(addr));
}

// ============================================================
__global__ void k_gather(const int* __restrict__ tok, const float* __restrict__ emb) {
    int i = blockIdx.x;
    int t = tok[i];
    float4 v = ((const float4*)(emb + (size_t)t * DD))[threadIdx.x];
    ((float4*)(g_x + (size_t)i * DD))[threadIdx.x] = v;
    __half2* xh = (__half2*)(g_xh + (size_t)i * DD);
    xh[threadIdx.x * 2] = __floats2half2_rn(v.x, v.y);
    xh[threadIdx.x * 2 + 1] = __floats2half2_rn(v.z, v.w);
}

__global__ void k_dist(const int* __restrict__ ei, const float* __restrict__ coords) {
    int e = blockIdx.x * 256 + threadIdx.x;
    int r = ei[e], c = ei[EE + e];
    float dx = coords[r * 3 + 0] - coords[c * 3 + 0];
    float dy = coords[r * 3 + 1] - coords[c * 3 + 1];
    float dz = coords[r * 3 + 2] - coords[c * 3 + 2];
    g_dist[e] = sqrtf(dx * dx + dy * dy + dz * dz);
}

// ============================================================
// Weight prep (single launch, z = 0..11): transpose + fp16 convert.
// mats 0-3: ew2, 4-7: nw1, 8-11: nw2.
// ============================================================
__global__ void k_wprep(const float* __restrict__ W0, const float* __restrict__ W1,
                        const float* __restrict__ W2) {
    __shared__ float ts[32][33];
    int k0 = blockIdx.x * 32, n0 = blockIdx.y * 32, mat = blockIdx.z;
    int l = mat & 3;
    const float* Wb = (mat < 4) ? W0 : (mat < 8) ? W1 : W2;
    const float* in = Wb + (size_t)l * DD * DD;
    __half* out = g_wH + (size_t)mat * DD * DD;
    int tx = threadIdx.x, ty = threadIdx.y;   // 32 x 8
#pragma unroll
    for (int i = 0; i < 4; i++)
        ts[ty + i * 8][tx] = in[(size_t)(k0 + ty + i * 8) * DD + n0 + tx];
    __syncthreads();
    int w_n = ty * 4 + (tx >> 3);
    int kq = (tx & 7) * 4;
    uint32_t* orow = (uint32_t*)(out + (size_t)(n0 + w_n) * DD + k0 + kq);
#pragma unroll
    for (int i = 0; i < 2; i++) {
        __half h0 = __float2half_rn(ts[kq + 2 * i][w_n]);
        __half h1 = __float2half_rn(ts[kq + 2 * i + 1][w_n]);
        orow[i] = pack_hf(h0, h1);
    }
}

// ============================================================
// scalar FFMA GEMM bits (k_tab1 only)
// ============================================================
__device__ __forceinline__ void mma_tile(const float (*As)[132], const float (*Bs)[128],
                                         int tx, int ty, float acc[8][8]) {
#pragma unroll
    for (int k = 0; k < 16; k++) {
        float4 a0 = *(const float4*)&As[k][ty * 8];
        float4 a1 = *(const float4*)&As[k][ty * 8 + 4];
        float4 b0 = *(const float4*)&Bs[k][tx * 8];
        float4 b1 = *(const float4*)&Bs[k][tx * 8 + 4];
        float av[8] = {a0.x, a0.y, a0.z, a0.w, a1.x, a1.y, a1.z, a1.w};
        float bv[8] = {b0.x, b0.y, b0.z, b0.w, b1.x, b1.y, b1.z, b1.w};
#pragma unroll
        for (int i = 0; i < 8; i++)
#pragma unroll
            for (int j = 0; j < 8; j++)
                acc[i][j] = fmaf(av[i], bv[j], acc[i][j]);
    }
}
__device__ __forceinline__ void cpB(float (*Bs)[128], const float* __restrict__ W,
                                    int n0, int kc, int tid) {
#pragma unroll
    for (int i = 0; i < 2; i++) {
        int q = i * 256 + tid;
        int r = q >> 5, c4 = q & 31;
        cp16(&Bs[r][c4 * 4], &W[(size_t)(kc * 16 + r) * DD + n0 + c4 * 4]);
    }
}

// ============================================================
// Table pass 1: g_thH[z] = fp16(silu(rbf(grid) @ W1[z] + b1[z]))
// ============================================================
__global__ void __launch_bounds__(256, 2) k_tab1(const float* __restrict__ Wb,
                                                 const float* __restrict__ bb_) {
    __shared__ float As[16][132];
    __shared__ float Bs[2][16][128];
    int tid = threadIdx.x, tx = tid & 15, ty = tid >> 4;
    int m0 = blockIdx.x * 128, n0 = blockIdx.y * 128, l = blockIdx.z;
    const float* W = Wb + (size_t)l * NRBF * DD;
    const float* b = bb_ + (size_t)l * DD;
    const float step = 6.0f / 127.0f;

    cpB(Bs[0], W, n0, 0, tid);
    cp_commit();

    float acc[8][8] = {};
#pragma unroll 1
    for (int kc = 0; kc < NRBF / 16; kc++) {
        int buf = kc & 1;
#pragma unroll
        for (int i = 0; i < 8; i++) {
            int idx = i * 256 + tid;
            int m = idx & 127, k = idx >> 7;
            float d = (float)(m0 + m) * HSTEP;
            float c = (float)(kc * 16 + k) * step;
            float dd = d - c;
            As[k][m] = __expf(-10.0f * dd * dd);
        }
        if (kc + 1 < NRBF / 16) { cpB(Bs[buf ^ 1], W, n0, kc + 1, tid); cp_commit(); }
        cp_wait0();
        __syncthreads();
        mma_tile(As, Bs[buf], tx, ty, acc);
        __syncthreads();
    }

    float bb[8];
#pragma unroll
    for (int j = 0; j < 8; j++) bb[j] = b[n0 + tx * 8 + j];
    __half* out = g_thH + (size_t)l * NP * DD;
#pragma unroll
    for (int i = 0; i < 8; i++) {
        uint32_t p[4];
#pragma unroll
        for (int q = 0; q < 4; q++) {
            float v0 = silu_f(acc[i][q * 2] + bb[q * 2]);
            float v1 = silu_f(acc[i][q * 2 + 1] + bb[q * 2 + 1]);
            __half2 h = __floats2half2_rn(v0, v1);
            p[q] = *(uint32_t*)&h;
        }
        *(uint4*)(out + (size_t)(m0 + ty * 8 + i) * DD + n0 + tx * 8) =
            make_uint4(p[0], p[1], p[2], p[3]);
    }
}

// ============================================================
// HMMA fp16 GEMM: C = A(fp16) @ W(fp16) + b.  1 MMA per tile.
// Tile 128x256, 8 warps (2m x 4n), warp tile 64x64, BK=64, 3 STAGES.
// Stage buffer: A 16KB + B 32KB = 48KB; x3 = 144KB.
// smem rows 128B (64 fp16 k-values), 8 chunks, pos = c ^ (row&7).
// EPI 0: g_tH = fp16(silu(.)); 1: g_x += . (+g_xh); 2: g_tabH[z] = fp16(.)
// ============================================================
#define NSTAGE 3
#define STGSZ 49152
#define SMEM_GEMM (NSTAGE * STGSZ + 1024)

template <int EPI>
__global__ void __launch_bounds__(256) k_gemm(int mat, const float* __restrict__ bb_) {
    extern __shared__ uint32_t smem_u[];
    char* smem_c = (char*)smem_u;
    float* sbias = (float*)(smem_c + NSTAGE * STGSZ);
    const uint32_t sbase = (uint32_t)__cvta_generic_to_shared(smem_u);

    int tid = threadIdx.x, lane = tid & 31, wid = tid >> 5;
    int m0 = blockIdx.x * 128, n0 = blockIdx.y * 256, l = blockIdx.z;
    const __half* Aq = (EPI == 0) ? g_aggH : (EPI == 1) ? g_tH
                                           : (g_thH + (size_t)l * NP * DD);
    const __half* Wq = g_wH + (size_t)(mat + l) * DD * DD;
    const float* b = (EPI == 2) ? bb_ + (size_t)l * DD : bb_;

    sbias[tid] = b[n0 + tid];

    // A staging: 2 threads/row, 4 chunks each (BK=64 -> 128B/row)
    const int srow = tid >> 1, cbase = (tid & 1) * 4;
    const __half* aRow = Aq + (size_t)(m0 + srow) * DD;
    uint32_t dstA[4];
#pragma unroll
    for (int j = 0; j < 4; j++)
        dstA[j] = srow * 128 + (((cbase + j) ^ (srow & 7)) << 4);
    // B staging: 1 thread/row (256 rows), 8 chunks of 16B = 64 fp16 k
    const int brow = tid;
    const __half* bRow = Wq + (size_t)(n0 + brow) * DD;
    uint32_t dstB[8];
#pragma unroll
    for (int c = 0; c < 8; c++)
        dstB[c] = brow * 128 + ((c ^ (brow & 7)) << 4);

    auto issue = [&](int kc, int buf) {
        char* Ab = smem_c + buf * STGSZ;
        char* Bb = Ab + 16384;
#pragma unroll
        for (int j = 0; j < 4; j++)
            cp16(Ab + dstA[j], aRow + kc * 64 + (cbase + j) * 8);
#pragma unroll
        for (int c = 0; c < 8; c++)
            cp16(Bb + dstB[c], bRow + kc * 64 + c * 8);
        cp_commit();
    };

    // fragment mapping
    const int g = lane >> 2, tig = lane & 3;
    const int wm = (wid >> 2) * 64, wn = (wid & 3) * 64;
    const int lq = lane >> 3, lr = lane & 7;
    const int rowA = (lq & 1) * 8 + lr, kqA = lq >> 1;
    const int rowB = (lq >> 1) * 8 + lr, kqB = lq & 1;
    const uint32_t aBase = sbase + (wm + rowA) * 128;
    const uint32_t bBase = sbase + 16384 + (wn + rowB) * 128;

    issue(0, 0);
    issue(1, 1);

    float acc[4][8][4] = {};
    const int NCH = DD / 64;   // 8
#pragma unroll 1
    for (int kc = 0; kc < NCH; kc++) {
        int buf = kc % NSTAGE;
        if (kc + 1 < NCH) cp_wait1(); else cp_wait0();
        __syncthreads();
        if (kc + 2 < NCH) issue(kc + 2, (kc + 2) % NSTAGE);
#pragma unroll
        for (int ks = 0; ks < 4; ks++) {
            uint32_t aH[4][4], bH[4][4];
            uint32_t chA = (uint32_t)(((ks * 2 + kqA) ^ (rowA & 7)) << 4);
            uint32_t chB = (uint32_t)(((ks * 2 + kqB) ^ (rowB & 7)) << 4);
#pragma unroll
            for (int mt = 0; mt < 4; mt++)
                ldsm4(aH[mt], aBase + buf * STGSZ + mt * 2048 + chA);
#pragma unroll
            for (int np = 0; np < 4; np++)
                ldsm4(bH[np], bBase + buf * STGSZ + np * 2048 + chB);
#pragma unroll
            for (int mt = 0; mt < 4; mt++)
#pragma unroll
                for (int nt = 0; nt < 8; nt++) {
                    uint32_t bh0 = bH[nt >> 1][(nt & 1) * 2];
                    uint32_t bh1 = bH[nt >> 1][(nt & 1) * 2 + 1];
                    mma_f16(acc[mt][nt], aH[mt], bh0, bh1);
                }
        }
    }

    // ---- epilogue ----
#pragma unroll
    for (int mt = 0; mt < 4; mt++) {
#pragma unroll
        for (int nt = 0; nt < 8; nt++) {
            int row = m0 + wm + mt * 16 + g;
            int cl = wn + nt * 8 + tig * 2;
            float b0 = sbias[cl], b1 = sbias[cl + 1];
            float* c = acc[mt][nt];
#pragma unroll
            for (int half = 0; half < 2; half++) {
                int r = row + half * 8;
                float v0 = c[half * 2 + 0] + b0, v1 = c[half * 2 + 1] + b1;
                size_t off = (size_t)r * DD + n0 + cl;
                if (EPI == 0) {
                    *(__half2*)(g_tH + off) = __floats2half2_rn(silu_f(v0), silu_f(v1));
                } else if (EPI == 1) {
                    float2 x = *(float2*)(g_x + off);
                    x.x += v0; x.y += v1;
                    *(float2*)(g_x + off) = x;
                    *(__half2*)(g_xh + off) = __floats2half2_rn(x.x, x.y);
                } else {
                    *(__half2*)(g_tabH + (size_t)l * NP * DD + off) =
                        __floats2half2_rn(v0, v1);
                }
            }
        }
    }
}

// ============================================================
// Edge pass (fp16 inputs, LDG.128, fp32 accumulate):
// 256-thread blocks process 4 nodes; 64 threads/node; 8 dims/thread.
// ============================================================
__global__ void __launch_bounds__(256) k_agg(const int* __restrict__ col, int l) {
    __shared__ int   scol[4][32];
    __shared__ int   sidx[4][32];
    __shared__ float sw[4][32];
    const __half* tab = g_tabH + (size_t)l * NP * DD;
    int tid = threadIdx.x;
    int node0 = blockIdx.x * 4;
    if (tid < 128) {
        int sn = tid >> 5, se = tid & 31;
        int e = (node0 + sn) * 32 + se;
        scol[sn][se] = col[e];
        float f = g_dist[e] * INVH;
        int i = (int)f;
        if (i > NP - 2) i = NP - 2;
        sidx[sn][se] = i;
        sw[sn][se] = f - (float)i;
    }
    __syncthreads();

    int sn = tid >> 6;
    int t = tid & 63;
    int node = node0 + sn;
    int dim = t * 8;

    float a[8] = {};
#pragma unroll 8
    for (int e = 0; e < 32; e++) {
        size_t tbase = (size_t)sidx[sn][e] * DD + dim;
        uint4 T0 = *(const uint4*)&tab[tbase];
        uint4 T1 = *(const uint4*)&tab[tbase + DD];
        uint4 X = *(const uint4*)&g_xh[(size_t)scol[sn][e] * DD + dim];
        float w = sw[sn][e];
        const __half2* t0 = (const __half2*)&T0;
        const __half2* t1 = (const __half2*)&T1;
        const __half2* xv = (const __half2*)&X;
#pragma unroll
        for (int q = 0; q < 4; q++) {
            float2 f0 = __half22float2(t0[q]);
            float2 f1 = __half22float2(t1[q]);
            float2 fx = __half22float2(xv[q]);
            a[q * 2 + 0] = fmaf(fmaf(w, f1.x - f0.x, f0.x), fx.x, a[q * 2 + 0]);
            a[q * 2 + 1] = fmaf(fmaf(w, f1.y - f0.y, f0.y), fx.y, a[q * 2 + 1]);
        }
    }
    uint32_t p[4];
#pragma unroll
    for (int q = 0; q < 4; q++) {
        __half2 h = __floats2half2_rn(a[q * 2], a[q * 2 + 1]);
        p[q] = *(uint32_t*)&h;
    }
    *(uint4*)(g_aggH + (size_t)node * DD + dim) = make_uint4(p[0], p[1], p[2], p[3]);
}

// ============================================================
// output: encoder_rep copy + optional padding-mask tail, one kernel
// ============================================================
__global__ void k_out(float* __restrict__ out, const int* __restrict__ tok, int extra) {
    size_t i = (size_t)blockIdx.x * 256 + threadIdx.x;   // float4 index
    if (i < (BNODES * DD) / 4) {
        ((float4*)out)[i] = ((const float4*)g_x)[i];
    } else {
        size_t j = i - (BNODES * DD) / 4;                // 4 mask elems per thread
        float* mp = out + BNODES * DD;
#pragma unroll
        for (int q = 0; q < 4; q++) {
            size_t m = j * 4 + q;
            if ((int)m < extra)
                mp[m] = (m < BNODES && tok[m] == 0) ? 1.0f : 0.0f;
        }
    }
}

// ============================================================
extern "C" void kernel_launch(void* const* d_in, const int* in_sizes, int n_in,
                              void* d_out, int out_size) {
    const int*   tok    = (const int*)d_in[0];
    const float* coords = (const float*)d_in[1];
    const int*   ei     = (const int*)d_in[2];
    const float* emb    = (const float*)d_in[3];
    const float* ew1    = (const float*)d_in[4];
    const float* eb1    = (const float*)d_in[5];
    const float* ew2    = (const float*)d_in[6];
    const float* eb2    = (const float*)d_in[7];
    const float* nw1    = (const float*)d_in[8];
    const float* nb1    = (const float*)d_in[9];
    const float* nw2    = (const float*)d_in[10];
    const float* nb2    = (const float*)d_in[11];

    cudaFuncSetAttribute(k_gemm<0>, cudaFuncAttributeMaxDynamicSharedMemorySize, SMEM_GEMM);
    cudaFuncSetAttribute(k_gemm<1>, cudaFuncAttributeMaxDynamicSharedMemorySize, SMEM_GEMM);
    cudaFuncSetAttribute(k_gemm<2>, cudaFuncAttributeMaxDynamicSharedMemorySize, SMEM_GEMM);

    k_gather<<<BNODES, 128>>>(tok, emb);
    k_dist<<<EE / 256, 256>>>(ei, coords);

    k_wprep<<<dim3(16, 16, 12), dim3(32, 8)>>>(ew2, nw1, nw2);

    k_tab1<<<dim3(NP / 128, 4, NLAYER), 256>>>(ew1, eb1);
    k_gemm<2><<<dim3(NP / 128, DD / 256, NLAYER), 256, SMEM_GEMM>>>(0, eb2);

    const int* col = ei + EE;
    for (int l = 0; l < NLAYER; l++) {
        k_agg<<<BNODES / 4, 256>>>(col, l);
        k_gemm<0><<<dim3(BNODES / 128, DD / 256), 256, SMEM_GEMM>>>(4 + l, nb1 + l * DD);
        k_gemm<1><<<dim3(BNODES / 128, DD / 256), 256, SMEM_GEMM>>>(8 + l, nb2 + l * DD);
    }

    int extra = out_size - BNODES * DD;
    int total4 = (BNODES * DD) / 4 + (extra > 0 ? (extra + 3) / 4 : 0);
    k_out<<<(total4 + 255) / 256, 256>>>((float*)d_out, tok, extra > 0 ? extra : 0);
}

// round 17
// speedup vs baseline: 3.0441x; 1.0432x over previous
#include <cuda_runtime.h>
#include <cuda_fp16.h>
#include <cstdint>

// ----- problem constants -----
#define BNODES 8192
#define EE     262144
#define DD     512
#define NRBF   128
#define NLAYER 4

// ----- distance->ef lookup table -----
#define NP    2048
#define DMAXF 10.4f
#define HSTEP (DMAXF / (float)(NP - 1))
#define INVH  ((float)(NP - 1) / DMAXF)

// ----- device scratch -----
__device__ float    g_x[BNODES * DD];             // fp32 node features (output path)
__device__ __half   g_xh[BNODES * DD];            // fp16 shadow of x (k_agg input)
__device__ float    g_dist[EE];
__device__ __half   g_rbfH[NP * NRBF];            // fp16 rbf grid (layer-invariant)
__device__ __half   g_tabH[NLAYER * NP * DD];     // fp16 ef tables (k_agg input)
__device__ __half   g_thH[NLAYER * NP * DD];      // fp16 hidden tables (gemm A)
__device__ __half   g_aggH[BNODES * DD];          // fp16 agg (gemm A)
__device__ __half   g_tH[BNODES * DD];            // fp16 node hidden (gemm A)
// weights fp16 transposed: mats 0-11 are DD x DD ([n][k=512]);
// mats 12-15 (ew1) are DD x NRBF ([n][k=128]) at offset 12*DD*DD.
__device__ __half   g_wH[12 * DD * DD + NLAYER * DD * NRBF];
#define EW1_OFF (12 * DD * DD)

__device__ __forceinline__ float silu_f(float v) { return v / (1.0f + __expf(-v)); }

__device__ __forceinline__ void cp16(void* dst, const void* src) {
    uint32_t d = (uint32_t)__cvta_generic_to_shared(dst);
    asm volatile("cp.async.cg.shared.global [%0], [%1], 16;" :: "r"(d), "l"(src));
}
__device__ __forceinline__ void cp_commit() { asm volatile("cp.async.commit_group;"); }
__device__ __forceinline__ void cp_wait0() { asm volatile("cp.async.wait_group 0;" ::: "memory"); }
__device__ __forceinline__ void cp_wait1() { asm volatile("cp.async.wait_group 1;" ::: "memory"); }

__device__ __forceinline__ uint32_t pack_hf(__half a, __half b) {
    __half2 p;
    p.x = a; p.y = b;
    return *(uint32_t*)&p;
}

__device__ __forceinline__ void mma_f16(float* c, const uint32_t* a, uint32_t b0, uint32_t b1) {
    asm volatile(
        "mma.sync.aligned.m16n8k16.row.col.f32.f16.f16.f32 "
        "{%0,%1,%2,%3}, {%4,%5,%6,%7}, {%8,%9}, {%0,%1,%2,%3};"
        : "+f"(c[0]), "+f"(c[1]), "+f"(c[2]), "+f"(c[3])
        : "r"(a[0]), "r"(a[1]), "r"(a[2]), "r"(a[3]), "r"(b0), "r"(b1));
}
__device__ __forceinline__ void ldsm4(uint32_t* r, uint32_t addr) {
    asm volatile("ldmatrix.sync.aligned.m8n8.x4.shared.b16 {%0,%1,%2,%3}, [%4];"
                 : "=r"(r[0]), "=r"(r[1]), "=r"(r[2]), "=r"(r[3]) : "r"(addr));
}

// ============================================================
__global__ void k_gather(const int* __restrict__ tok, const float* __restrict__ emb) {
    int i = blockIdx.x;
    int t = tok[i];
    float4 v = ((const float4*)(emb + (size_t)t * DD))[threadIdx.x];
    ((float4*)(g_x + (size_t)i * DD))[threadIdx.x] = v;
    __half2* xh = (__half2*)(g_xh + (size_t)i * DD);
    xh[threadIdx.x * 2] = __floats2half2_rn(v.x, v.y);
    xh[threadIdx.x * 2 + 1] = __floats2half2_rn(v.z, v.w);
}

__global__ void k_dist(const int* __restrict__ ei, const float* __restrict__ coords) {
    int e = blockIdx.x * 256 + threadIdx.x;
    int r = ei[e], c = ei[EE + e];
    float dx = coords[r * 3 + 0] - coords[c * 3 + 0];
    float dy = coords[r * 3 + 1] - coords[c * 3 + 1];
    float dz = coords[r * 3 + 2] - coords[c * 3 + 2];
    g_dist[e] = sqrtf(dx * dx + dy * dy + dz * dz);
}

// rbf grid (fp16, layer-invariant): g_rbfH[m][j] = exp(-10*(m*H - j*step)^2)
__global__ void k_rbf() {
    int q = blockIdx.x * 256 + threadIdx.x;   // one elem per thread
    int m = q >> 7, j = q & 127;
    const float step = 6.0f / 127.0f;
    float dd = (float)m * HSTEP - (float)j * step;
    g_rbfH[q] = __float2half_rn(__expf(-10.0f * dd * dd));
}

// ============================================================
// Weight prep (single launch): transpose + fp16 convert.
// z 0-11: DDxDD mats (ew2, nw1, nw2); z 12-15: ew1 (NRBF x DD -> [n][128]).
// For DDxDD: grid covers (k0 16, n0 16); ew1 only needs k0 < 4.
// ============================================================
__global__ void k_wprep(const float* __restrict__ W0, const float* __restrict__ W1,
                        const float* __restrict__ W2, const float* __restrict__ W3) {
    __shared__ float ts[32][33];
    int k0 = blockIdx.x * 32, n0 = blockIdx.y * 32, mat = blockIdx.z;
    int l = mat & 3;
    int K = (mat < 12) ? DD : NRBF;
    if (k0 >= K) return;
    const float* Wb = (mat < 4) ? W0 : (mat < 8) ? W1 : (mat < 12) ? W2 : W3;
    const float* in = Wb + (size_t)l * K * DD;
    __half* out = (mat < 12) ? (g_wH + (size_t)mat * DD * DD)
                             : (g_wH + EW1_OFF + (size_t)l * DD * NRBF);
    int tx = threadIdx.x, ty = threadIdx.y;   // 32 x 8
#pragma unroll
    for (int i = 0; i < 4; i++)
        ts[ty + i * 8][tx] = in[(size_t)(k0 + ty + i * 8) * DD + n0 + tx];
    __syncthreads();
    int w_n = ty * 4 + (tx >> 3);
    int kq = (tx & 7) * 4;
    uint32_t* orow = (uint32_t*)(out + (size_t)(n0 + w_n) * K + k0 + kq);
#pragma unroll
    for (int i = 0; i < 2; i++) {
        __half h0 = __float2half_rn(ts[kq + 2 * i][w_n]);
        __half h1 = __float2half_rn(ts[kq + 2 * i + 1][w_n]);
        orow[i] = pack_hf(h0, h1);
    }
}

// ============================================================
// HMMA fp16 GEMM: C = A(fp16) @ W(fp16) + b.
// Tile 128x256, 8 warps (2m x 4n), warp tile 64x64, BK=64, 3 stages.
// EPI 0: g_tH = fp16(silu(.)), A=g_aggH, K=512
// EPI 1: g_x += . (+g_xh),     A=g_tH,   K=512
// EPI 2: g_tabH[z] = fp16(.),  A=g_thH,  K=512
// EPI 3: g_thH[z] = fp16(silu(.)), A=g_rbfH, K=128 (table pass 1)
// ============================================================
#define NSTAGE 3
#define STGSZ 49152
#define SMEM_GEMM (NSTAGE * STGSZ + 1024)

template <int EPI>
__global__ void __launch_bounds__(256) k_gemm(int mat, const float* __restrict__ bb_) {
    constexpr int KTOT = (EPI == 3) ? NRBF : DD;
    extern __shared__ uint32_t smem_u[];
    char* smem_c = (char*)smem_u;
    float* sbias = (float*)(smem_c + NSTAGE * STGSZ);
    const uint32_t sbase = (uint32_t)__cvta_generic_to_shared(smem_u);

    int tid = threadIdx.x, lane = tid & 31, wid = tid >> 5;
    int m0 = blockIdx.x * 128, n0 = blockIdx.y * 256, l = blockIdx.z;
    const __half* Aq = (EPI == 0) ? g_aggH : (EPI == 1) ? g_tH
                     : (EPI == 2) ? (g_thH + (size_t)l * NP * DD) : g_rbfH;
    const __half* Wq = (EPI == 3) ? (g_wH + EW1_OFF + (size_t)l * DD * NRBF)
                                  : (g_wH + (size_t)(mat + l) * DD * DD);
    const float* b = (EPI >= 2) ? bb_ + (size_t)l * DD : bb_;

    sbias[tid] = b[n0 + tid];

    // A staging: 2 threads/row, 4 chunks each (BK=64 -> 128B/row)
    const int srow = tid >> 1, cbase = (tid & 1) * 4;
    const __half* aRow = Aq + (size_t)(m0 + srow) * KTOT;
    uint32_t dstA[4];
#pragma unroll
    for (int j = 0; j < 4; j++)
        dstA[j] = srow * 128 + (((cbase + j) ^ (srow & 7)) << 4);
    // B staging: 1 thread/row (256 rows), 8 chunks of 16B = 64 fp16 k
    const int brow = tid;
    const __half* bRow = Wq + (size_t)(n0 + brow) * KTOT;
    uint32_t dstB[8];
#pragma unroll
    for (int c = 0; c < 8; c++)
        dstB[c] = brow * 128 + ((c ^ (brow & 7)) << 4);

    auto issue = [&](int kc, int buf) {
        char* Ab = smem_c + buf * STGSZ;
        char* Bb = Ab + 16384;
#pragma unroll
        for (int j = 0; j < 4; j++)
            cp16(Ab + dstA[j], aRow + kc * 64 + (cbase + j) * 8);
#pragma unroll
        for (int c = 0; c < 8; c++)
            cp16(Bb + dstB[c], bRow + kc * 64 + c * 8);
        cp_commit();
    };

    // fragment mapping
    const int g = lane >> 2, tig = lane & 3;
    const int wm = (wid >> 2) * 64, wn = (wid & 3) * 64;
    const int lq = lane >> 3, lr = lane & 7;
    const int rowA = (lq & 1) * 8 + lr, kqA = lq >> 1;
    const int rowB = (lq >> 1) * 8 + lr, kqB = lq & 1;
    const uint32_t aBase = sbase + (wm + rowA) * 128;
    const uint32_t bBase = sbase + 16384 + (wn + rowB) * 128;

    const int NCH = KTOT / 64;
    issue(0, 0);
    if (NCH > 1) issue(1, 1);

    float acc[4][8][4] = {};
#pragma unroll 1
    for (int kc = 0; kc < NCH; kc++) {
        int buf = kc % NSTAGE;
        if (kc + 1 < NCH) cp_wait1(); else cp_wait0();
        __syncthreads();
        if (kc + 2 < NCH) issue(kc + 2, (kc + 2) % NSTAGE);
#pragma unroll
        for (int ks = 0; ks < 4; ks++) {
            uint32_t aH[4][4], bH[4][4];
            uint32_t chA = (uint32_t)(((ks * 2 + kqA) ^ (rowA & 7)) << 4);
            uint32_t chB = (uint32_t)(((ks * 2 + kqB) ^ (rowB & 7)) << 4);
#pragma unroll
            for (int mt = 0; mt < 4; mt++)
                ldsm4(aH[mt], aBase + buf * STGSZ + mt * 2048 + chA);
#pragma unroll
            for (int np = 0; np < 4; np++)
                ldsm4(bH[np], bBase + buf * STGSZ + np * 2048 + chB);
#pragma unroll
            for (int mt = 0; mt < 4; mt++)
#pragma unroll
                for (int nt = 0; nt < 8; nt++) {
                    uint32_t bh0 = bH[nt >> 1][(nt & 1) * 2];
                    uint32_t bh1 = bH[nt >> 1][(nt & 1) * 2 + 1];
                    mma_f16(acc[mt][nt], aH[mt], bh0, bh1);
                }
        }
    }

    // ---- epilogue ----
#pragma unroll
    for (int mt = 0; mt < 4; mt++) {
#pragma unroll
        for (int nt = 0; nt < 8; nt++) {
            int row = m0 + wm + mt * 16 + g;
            int cl = wn + nt * 8 + tig * 2;
            float b0 = sbias[cl], b1 = sbias[cl + 1];
            float* c = acc[mt][nt];
#pragma unroll
            for (int half = 0; half < 2; half++) {
                int r = row + half * 8;
                float v0 = c[half * 2 + 0] + b0, v1 = c[half * 2 + 1] + b1;
                size_t off = (size_t)r * DD + n0 + cl;
                if (EPI == 0) {
                    *(__half2*)(g_tH + off) = __floats2half2_rn(silu_f(v0), silu_f(v1));
                } else if (EPI == 1) {
                    float2 x = *(float2*)(g_x + off);
                    x.x += v0; x.y += v1;
                    *(float2*)(g_x + off) = x;
                    *(__half2*)(g_xh + off) = __floats2half2_rn(x.x, x.y);
                } else if (EPI == 2) {
                    *(__half2*)(g_tabH + (size_t)l * NP * DD + off) =
                        __floats2half2_rn(v0, v1);
                } else {
                    *(__half2*)(g_thH + (size_t)l * NP * DD + off) =
                        __floats2half2_rn(silu_f(v0), silu_f(v1));
                }
            }
        }
    }
}

// ============================================================
// Edge pass (fp16 inputs, LDG.128, fp32 accumulate):
// 256-thread blocks process 4 nodes; 64 threads/node; 8 dims/thread.
// ============================================================
__global__ void __launch_bounds__(256) k_agg(const int* __restrict__ col, int l) {
    __shared__ int   scol[4][32];
    __shared__ int   sidx[4][32];
    __shared__ float sw[4][32];
    const __half* tab = g_tabH + (size_t)l * NP * DD;
    int tid = threadIdx.x;
    int node0 = blockIdx.x * 4;
    if (tid < 128) {
        int sn = tid >> 5, se = tid & 31;
        int e = (node0 + sn) * 32 + se;
        scol[sn][se] = col[e];
        float f = g_dist[e] * INVH;
        int i = (int)f;
        if (i > NP - 2) i = NP - 2;
        sidx[sn][se] = i;
        sw[sn][se] = f - (float)i;
    }
    __syncthreads();

    int sn = tid >> 6;
    int t = tid & 63;
    int node = node0 + sn;
    int dim = t * 8;

    float a[8] = {};
#pragma unroll 8
    for (int e = 0; e < 32; e++) {
        size_t tbase = (size_t)sidx[sn][e] * DD + dim;
        uint4 T0 = *(const uint4*)&tab[tbase];
        uint4 T1 = *(const uint4*)&tab[tbase + DD];
        uint4 X = *(const uint4*)&g_xh[(size_t)scol[sn][e] * DD + dim];
        float w = sw[sn][e];
        const __half2* t0 = (const __half2*)&T0;
        const __half2* t1 = (const __half2*)&T1;
        const __half2* xv = (const __half2*)&X;
#pragma unroll
        for (int q = 0; q < 4; q++) {
            float2 f0 = __half22float2(t0[q]);
            float2 f1 = __half22float2(t1[q]);
            float2 fx = __half22float2(xv[q]);
            a[q * 2 + 0] = fmaf(fmaf(w, f1.x - f0.x, f0.x), fx.x, a[q * 2 + 0]);
            a[q * 2 + 1] = fmaf(fmaf(w, f1.y - f0.y, f0.y), fx.y, a[q * 2 + 1]);
        }
    }
    uint32_t p[4];
#pragma unroll
    for (int q = 0; q < 4; q++) {
        __half2 h = __floats2half2_rn(a[q * 2], a[q * 2 + 1]);
        p[q] = *(uint32_t*)&h;
    }
    *(uint4*)(g_aggH + (size_t)node * DD + dim) = make_uint4(p[0], p[1], p[2], p[3]);
}

// ============================================================
// output: encoder_rep copy + optional padding-mask tail, one kernel
// ============================================================
__global__ void k_out(float* __restrict__ out, const int* __restrict__ tok, int extra) {
    size_t i = (size_t)blockIdx.x * 256 + threadIdx.x;   // float4 index
    if (i < (BNODES * DD) / 4) {
        ((float4*)out)[i] = ((const float4*)g_x)[i];
    } else {
        size_t j = i - (BNODES * DD) / 4;
        float* mp = out + BNODES * DD;
#pragma unroll
        for (int q = 0; q < 4; q++) {
            size_t m = j * 4 + q;
            if ((int)m < extra)
                mp[m] = (m < BNODES && tok[m] == 0) ? 1.0f : 0.0f;
        }
    }
}

// ============================================================
extern "C" void kernel_launch(void* const* d_in, const int* in_sizes, int n_in,
                              void* d_out, int out_size) {
    const int*   tok    = (const int*)d_in[0];
    const float* coords = (const float*)d_in[1];
    const int*   ei     = (const int*)d_in[2];
    const float* emb    = (const float*)d_in[3];
    const float* ew1    = (const float*)d_in[4];
    const float* eb1    = (const float*)d_in[5];
    const float* ew2    = (const float*)d_in[6];
    const float* eb2    = (const float*)d_in[7];
    const float* nw1    = (const float*)d_in[8];
    const float* nb1    = (const float*)d_in[9];
    const float* nw2    = (const float*)d_in[10];
    const float* nb2    = (const float*)d_in[11];

    cudaFuncSetAttribute(k_gemm<0>, cudaFuncAttributeMaxDynamicSharedMemorySize, SMEM_GEMM);
    cudaFuncSetAttribute(k_gemm<1>, cudaFuncAttributeMaxDynamicSharedMemorySize, SMEM_GEMM);
    cudaFuncSetAttribute(k_gemm<2>, cudaFuncAttributeMaxDynamicSharedMemorySize, SMEM_GEMM);
    cudaFuncSetAttribute(k_gemm<3>, cudaFuncAttributeMaxDynamicSharedMemorySize, SMEM_GEMM);

    k_gather<<<BNODES, 128>>>(tok, emb);
    k_dist<<<EE / 256, 256>>>(ei, coords);
    k_rbf<<<(NP * NRBF) / 256, 256>>>();

    k_wprep<<<dim3(16, 16, 16), dim3(32, 8)>>>(ew2, nw1, nw2, ew1);

    // table pass 1 (HMMA, K=128) then pass 2 (K=512), all layers batched
    k_gemm<3><<<dim3(NP / 128, DD / 256, NLAYER), 256, SMEM_GEMM>>>(0, eb1);
    k_gemm<2><<<dim3(NP / 128, DD / 256, NLAYER), 256, SMEM_GEMM>>>(0, eb2);

    const int* col = ei + EE;
    for (int l = 0; l < NLAYER; l++) {
        k_agg<<<BNODES / 4, 256>>>(col, l);
        k_gemm<0><<<dim3(BNODES / 128, DD / 256), 256, SMEM_GEMM>>>(4 + l, nb1 + l * DD);
        k_gemm<1><<<dim3(BNODES / 128, DD / 256), 256, SMEM_GEMM>>>(8 + l, nb2 + l * DD);
    }

    int extra = out_size - BNODES * DD;
    int total4 = (BNODES * DD) / 4 + (extra > 0 ? (extra + 3) / 4 : 0);
    k_out<<<(total4 + 255) / 256, 256>>>((float*)d_out, tok, extra > 0 ? extra : 0);
}